// round 2
// baseline (speedup 1.0000x reference)
#include <cuda_runtime.h>
#include <math.h>

#define BB   64
#define LL   2048
#define VV   30
#define EE   128
#define GG   8
#define GEGE 1024
#define CC   64
#define FF   128
#define OO   30
#define NDND 9

#define TS   128          // timesteps per layer tile
#define PSTR 130          // pair stride for duplicated activation rows (floats = 2*PSTR)

typedef unsigned long long u64;

// ---------------- packed fp32 helpers --------------------------------------
__device__ __forceinline__ u64 ffma2(u64 a, u64 b, u64 c) {
    asm("fma.rn.f32x2 %0, %1, %2, %0;" : "+l"(c) : "l"(a), "l"(b));
    return c;
}
__device__ __forceinline__ u64 pack2(float lo, float hi) {
    u64 r; asm("mov.b64 %0, {%1, %2};" : "=l"(r) : "f"(lo), "f"(hi)); return r;
}
__device__ __forceinline__ void unpack2(u64 v, float& lo, float& hi) {
    asm("mov.b64 {%0, %1}, %2;" : "=f"(lo), "=f"(hi) : "l"(v));
}
__device__ __forceinline__ float fast_tanh(float x) {
    float e; asm("ex2.approx.f32 %0, %1;" : "=f"(e) : "f"(x * 2.8853900817779268f)); // e^{2x}
    float r; asm("rcp.approx.f32 %0, %1;" : "=f"(r) : "f"(e + 1.0f));
    return 1.0f - 2.0f * r;
}
__device__ __forceinline__ float fast_sigmoid(float x) {
    float e; asm("ex2.approx.f32 %0, %1;" : "=f"(e) : "f"(-x * 1.4426950408889634f)); // e^{-x}
    float r; asm("rcp.approx.f32 %0, %1;" : "=f"(r) : "f"(e + 1.0f));
    return r;
}

// ---------------- scratch (device globals) ----------------------------------
__device__ float g_res0[(size_t)BB * LL * CC];   // initial residual (preserved)
__device__ float g_resA[(size_t)BB * LL * CC];   // ping
__device__ float g_resB[(size_t)BB * LL * CC];   // pong
__device__ float g_embg[BB * GEGE];
__device__ float g_HF[NDND * BB * CC];
__device__ float g_HG[NDND * BB * CC];
__device__ float g_M0[VV * CC];
__device__ float g_M1[VV * CC];

__device__ __forceinline__ const float* buf_c(int sel) {
    return sel == 0 ? g_res0 : (sel == 1 ? g_resA : g_resB);
}
__device__ __forceinline__ float* buf_m(int sel) {
    return sel == 1 ? g_resA : g_resB;
}

// ---------------- K0: fold embedding + initial conv into lookup -------------
__global__ void __launch_bounds__(64) k_precompute_M(
    const float* __restrict__ emb, const float* __restrict__ wc)
{
    int v = blockIdx.x, c = threadIdx.x;
    float a0 = 0.f, a1 = 0.f;
    if (v != 0) {
        for (int e = 0; e < EE; e++) {
            float x = emb[v * EE + e];
            a0 = fmaf(x, wc[(c * EE + e) * 2 + 0], a0);
            a1 = fmaf(x, wc[(c * EE + e) * 2 + 1], a1);
        }
    }
    g_M0[v * CC + c] = a0;
    g_M1[v * CC + c] = a1;
}

// ---------------- K1: global embedding --------------------------------------
__global__ void __launch_bounds__(256) k_embg(
    const int* __restrict__ gin, const float* __restrict__ emb)
{
    int b = blockIdx.x;
    for (int j = threadIdx.x; j < GEGE; j += 256) {
        int g = j >> 7, e = j & 127;
        int tok = gin[b * GG + g];
        g_embg[b * GEGE + j] = (tok == 0) ? 0.f : emb[tok * EE + e];
    }
}

// ---------------- K2: conditioning vectors ----------------------------------
__global__ void __launch_bounds__(128) k_H(
    const float* __restrict__ wlf, const float* __restrict__ blf,
    const float* __restrict__ wlg, const float* __restrict__ blg)
{
    __shared__ float se[GEGE];
    int i = blockIdx.x, b = blockIdx.y, tid = threadIdx.x;
    for (int j = tid; j < GEGE; j += 128) se[j] = g_embg[b * GEGE + j];
    __syncthreads();
    int c = tid & 63;
    bool isf = tid < 64;
    const float* w = (isf ? wlf : wlg) + ((size_t)i * CC + c) * GEGE;
    float acc = (isf ? blf : blg)[i * CC + c];
    for (int j = 0; j < GEGE; j += 4) {
        float4 wv = *(const float4*)(w + j);
        acc = fmaf(se[j], wv.x, acc);
        acc = fmaf(se[j + 1], wv.y, acc);
        acc = fmaf(se[j + 2], wv.z, acc);
        acc = fmaf(se[j + 3], wv.w, acc);
    }
    (isf ? g_HF : g_HG)[((size_t)i * BB + b) * CC + c] = acc;
}

// ---------------- K3: initial residual via lookup ----------------------------
__global__ void __launch_bounds__(256) k_init(
    const int* __restrict__ tok, const float* __restrict__ b_causal)
{
    __shared__ float sM0[VV * CC], sM1[VV * CC], sb[CC];
    int tid = threadIdx.x;
    for (int i = tid; i < VV * CC; i += 256) { sM0[i] = g_M0[i]; sM1[i] = g_M1[i]; }
    if (tid < CC) sb[tid] = b_causal[tid];
    __syncthreads();
    int b = blockIdx.y, tt0 = blockIdx.x * 64;
    const int* tb = tok + b * LL;
    float* ro = g_res0 + (size_t)b * LL * CC;
    for (int idx = tid; idx < 64 * 64; idx += 256) {
        int t = tt0 + (idx >> 6);
        int c = idx & 63;
        float r = sM1[tb[t] * CC + c] + sb[c];
        if (t > 0) r += sM0[tb[t - 1] * CC + c];
        ro[(size_t)t * CC + c] = r;
    }
}

// ---------------- K4: dilated residual layer, FFMA2 path --------------------
// Block: 128 threads, tile = 128 timesteps x 64 channels of one batch.
// Thread tile: 8 channels (4 c-pairs) x 8 timesteps, f & g accumulated packed.
__global__ void __launch_bounds__(128, 1) k_layer(
    const float* __restrict__ w_f, const float* __restrict__ b_f,
    const float* __restrict__ w_g, const float* __restrict__ b_g,
    const float* __restrict__ w_res, const float* __restrict__ b_res,
    int layer, int d, int in_sel, int out_sel)
{
    extern __shared__ float sm[];
    float* sWf0 = sm;                       // [k][c] 64x64, weights transposed
    float* sWf1 = sWf0 + 4096;
    float* sWg0 = sWf1 + 4096;
    float* sWg1 = sWg0 + 4096;
    float* sWr  = sWg1 + 4096;
    float* sCur = sWr + 4096;               // dup pairs: [c][2*PSTR floats]
    float* sPrev = sCur + 64 * 2 * PSTR;    // dup pairs; reused as sZ in phase 2

    int tid = threadIdx.x;
    int b = blockIdx.y;
    int tt0 = blockIdx.x * TS;

    // ---- weights (transposed to [k][c]) ----
    const float* wf = w_f + (size_t)layer * CC * CC * 2;
    const float* wg = w_g + (size_t)layer * CC * CC * 2;
    const float* wr = w_res + (size_t)layer * CC * CC;
    for (int idx = tid; idx < CC * CC; idx += 128) {
        int co = idx >> 6, ci = idx & 63;
        int tr = ci * 64 + co;
        sWf0[tr] = wf[idx * 2];
        sWf1[tr] = wf[idx * 2 + 1];
        sWg0[tr] = wg[idx * 2];
        sWg1[tr] = wg[idx * 2 + 1];
        sWr[tr]  = wr[idx];
    }

    // ---- activations, duplicated (v,v) pairs for FFMA2 broadcast ----
    const float* rin = buf_c(in_sel) + (size_t)b * LL * CC;
    for (int f = tid; f < TS * 16; f += 128) {
        int t = f >> 4;
        int c4 = (f & 15) * 4;
        float4 v = *(const float4*)(rin + (size_t)(tt0 + t) * CC + c4);
        *(float2*)(sCur + (c4 + 0) * 2 * PSTR + 2 * t) = make_float2(v.x, v.x);
        *(float2*)(sCur + (c4 + 1) * 2 * PSTR + 2 * t) = make_float2(v.y, v.y);
        *(float2*)(sCur + (c4 + 2) * 2 * PSTR + 2 * t) = make_float2(v.z, v.z);
        *(float2*)(sCur + (c4 + 3) * 2 * PSTR + 2 * t) = make_float2(v.w, v.w);
        int tp = tt0 + t - d;
        float4 p = make_float4(0.f, 0.f, 0.f, 0.f);
        if (tp >= 0) p = *(const float4*)(rin + (size_t)tp * CC + c4);
        *(float2*)(sPrev + (c4 + 0) * 2 * PSTR + 2 * t) = make_float2(p.x, p.x);
        *(float2*)(sPrev + (c4 + 1) * 2 * PSTR + 2 * t) = make_float2(p.y, p.y);
        *(float2*)(sPrev + (c4 + 2) * 2 * PSTR + 2 * t) = make_float2(p.z, p.z);
        *(float2*)(sPrev + (c4 + 3) * 2 * PSTR + 2 * t) = make_float2(p.w, p.w);
    }
    __syncthreads();

    int c0 = (tid >> 4) * 8;     // 8 channels = 4 pairs
    int t0 = (tid & 15) * 8;     // 8 timesteps

    // ---- phase 1: x_f / x_g GEMMs, packed accumulators ----
    u64 af[4][8], ag[4][8];
    {
        const float* bfp = b_f + layer * CC;
        const float* bgp = b_g + layer * CC;
        const float* hfp = g_HF + ((size_t)layer * BB + b) * CC;
        const float* hgp = g_HG + ((size_t)layer * BB + b) * CC;
        #pragma unroll
        for (int cp = 0; cp < 4; cp++) {
            int c = c0 + 2 * cp;
            u64 hf = pack2(bfp[c] + hfp[c], bfp[c + 1] + hfp[c + 1]);
            u64 hg = pack2(bgp[c] + hgp[c], bgp[c + 1] + hgp[c + 1]);
            #pragma unroll
            for (int tj = 0; tj < 8; tj++) { af[cp][tj] = hf; ag[cp][tj] = hg; }
        }
    }

    #pragma unroll 1
    for (int k = 0; k < 64; k++) {
        int wo = k * 64 + c0;
        ulonglong2 F0 = *(const ulonglong2*)(sWf0 + wo);
        ulonglong2 F1 = *(const ulonglong2*)(sWf0 + wo + 4);
        ulonglong2 H0 = *(const ulonglong2*)(sWf1 + wo);
        ulonglong2 H1 = *(const ulonglong2*)(sWf1 + wo + 4);
        ulonglong2 G0 = *(const ulonglong2*)(sWg0 + wo);
        ulonglong2 G1 = *(const ulonglong2*)(sWg0 + wo + 4);
        ulonglong2 J0 = *(const ulonglong2*)(sWg1 + wo);
        ulonglong2 J1 = *(const ulonglong2*)(sWg1 + wo + 4);
        int ao = k * 2 * PSTR + 2 * t0;
        ulonglong2 P0 = *(const ulonglong2*)(sPrev + ao);
        ulonglong2 P1 = *(const ulonglong2*)(sPrev + ao + 4);
        ulonglong2 P2 = *(const ulonglong2*)(sPrev + ao + 8);
        ulonglong2 P3 = *(const ulonglong2*)(sPrev + ao + 12);
        ulonglong2 Q0 = *(const ulonglong2*)(sCur + ao);
        ulonglong2 Q1 = *(const ulonglong2*)(sCur + ao + 4);
        ulonglong2 Q2 = *(const ulonglong2*)(sCur + ao + 8);
        ulonglong2 Q3 = *(const ulonglong2*)(sCur + ao + 12);
        u64 wf0v[4] = {F0.x, F0.y, F1.x, F1.y};
        u64 wf1v[4] = {H0.x, H0.y, H1.x, H1.y};
        u64 wg0v[4] = {G0.x, G0.y, G1.x, G1.y};
        u64 wg1v[4] = {J0.x, J0.y, J1.x, J1.y};
        u64 pv[8] = {P0.x, P0.y, P1.x, P1.y, P2.x, P2.y, P3.x, P3.y};
        u64 cv[8] = {Q0.x, Q0.y, Q1.x, Q1.y, Q2.x, Q2.y, Q3.x, Q3.y};
        #pragma unroll
        for (int cp = 0; cp < 4; cp++)
            #pragma unroll
            for (int tj = 0; tj < 8; tj++) {
                af[cp][tj] = ffma2(wf0v[cp], pv[tj], af[cp][tj]);
                af[cp][tj] = ffma2(wf1v[cp], cv[tj], af[cp][tj]);
                ag[cp][tj] = ffma2(wg0v[cp], pv[tj], ag[cp][tj]);
                ag[cp][tj] = ffma2(wg1v[cp], cv[tj], ag[cp][tj]);
            }
    }

    // ---- gated activation; z stored duplicated into sPrev's space ----
    __syncthreads();           // everyone done reading sPrev
    float* sZ = sPrev;
    #pragma unroll
    for (int cp = 0; cp < 4; cp++) {
        int c = c0 + 2 * cp;
        #pragma unroll
        for (int tj = 0; tj < 8; tj++) {
            float x0, x1, y0, y1;
            unpack2(af[cp][tj], x0, x1);
            unpack2(ag[cp][tj], y0, y1);
            float z0 = fast_tanh(x0) * fast_sigmoid(y0);
            float z1 = fast_tanh(x1) * fast_sigmoid(y1);
            *(float2*)(sZ + c * 2 * PSTR + 2 * (t0 + tj)) = make_float2(z0, z0);
            *(float2*)(sZ + (c + 1) * 2 * PSTR + 2 * (t0 + tj)) = make_float2(z1, z1);
        }
    }
    __syncthreads();

    // ---- phase 2: skip = W_res * z ----
    u64 as[4][8];
    {
        const float* brp = b_res + layer * CC;
        #pragma unroll
        for (int cp = 0; cp < 4; cp++) {
            u64 bp = pack2(brp[c0 + 2 * cp], brp[c0 + 2 * cp + 1]);
            #pragma unroll
            for (int tj = 0; tj < 8; tj++) as[cp][tj] = bp;
        }
    }
    #pragma unroll 2
    for (int k = 0; k < 64; k++) {
        int wo = k * 64 + c0;
        ulonglong2 W0 = *(const ulonglong2*)(sWr + wo);
        ulonglong2 W1 = *(const ulonglong2*)(sWr + wo + 4);
        int ao = k * 2 * PSTR + 2 * t0;
        ulonglong2 Z0 = *(const ulonglong2*)(sZ + ao);
        ulonglong2 Z1 = *(const ulonglong2*)(sZ + ao + 4);
        ulonglong2 Z2 = *(const ulonglong2*)(sZ + ao + 8);
        ulonglong2 Z3 = *(const ulonglong2*)(sZ + ao + 12);
        u64 wv[4] = {W0.x, W0.y, W1.x, W1.y};
        u64 zv[8] = {Z0.x, Z0.y, Z1.x, Z1.y, Z2.x, Z2.y, Z3.x, Z3.y};
        #pragma unroll
        for (int cp = 0; cp < 4; cp++)
            #pragma unroll
            for (int tj = 0; tj < 8; tj++)
                as[cp][tj] = ffma2(wv[cp], zv[tj], as[cp][tj]);
    }

    // ---- epilogue: res_out = res_in + skip (skips tracked implicitly) ----
    float* rout = buf_m(out_sel) + (size_t)b * LL * CC;
    #pragma unroll
    for (int tj = 0; tj < 8; tj++) {
        int t = tt0 + t0 + tj;
        float o[8];
        #pragma unroll
        for (int cp = 0; cp < 4; cp++) {
            float s0, s1;
            unpack2(as[cp][tj], s0, s1);
            int c = c0 + 2 * cp;
            float v0 = sCur[c * 2 * PSTR + 2 * (t0 + tj)];
            float v1 = sCur[(c + 1) * 2 * PSTR + 2 * (t0 + tj)];
            o[2 * cp] = v0 + s0;
            o[2 * cp + 1] = v1 + s1;
        }
        *(float4*)(rout + (size_t)t * CC + c0) = make_float4(o[0], o[1], o[2], o[3]);
        *(float4*)(rout + (size_t)t * CC + c0 + 4) = make_float4(o[4], o[5], o[6], o[7]);
    }
}

// ---------------- K5: head: relu(resA - res0) -> 64x128 -> relu -> 128x30 ---
__global__ void __launch_bounds__(256) k_final(
    const float* __restrict__ w1, const float* __restrict__ b1,
    const float* __restrict__ w2, const float* __restrict__ b2,
    float* __restrict__ out)
{
    extern __shared__ float sm[];
    float* sS  = sm;                  // [c][t] 64x68
    float* sW1 = sS + 64 * 68;        // [c][f] 64x128
    float* sH  = sW1 + 64 * 128;      // [f][t] 128x68
    float* sW2 = sH + 128 * 68;       // [f][o] 128x32

    int tid = threadIdx.x;
    int b = blockIdx.y;
    int tt0 = blockIdx.x * 64;

    for (int idx = tid; idx < FF * CC; idx += 256) {
        int f = idx >> 6, c = idx & 63;
        sW1[c * 128 + f] = w1[idx];
    }
    for (int idx = tid; idx < 128 * 32; idx += 256) {
        int f = idx >> 5, o = idx & 31;
        sW2[idx] = (o < OO) ? w2[o * 128 + f] : 0.f;
    }
    const float* rA = g_resA + (size_t)b * LL * CC;
    const float* r0 = g_res0 + (size_t)b * LL * CC;
    for (int f4 = tid; f4 < 1024; f4 += 256) {
        int t = f4 >> 4, c4 = (f4 & 15) * 4;
        size_t off = (size_t)(tt0 + t) * CC + c4;
        float4 a = *(const float4*)(rA + off);
        float4 z = *(const float4*)(r0 + off);
        sS[(c4 + 0) * 68 + t] = fmaxf(a.x - z.x, 0.f);
        sS[(c4 + 1) * 68 + t] = fmaxf(a.y - z.y, 0.f);
        sS[(c4 + 2) * 68 + t] = fmaxf(a.z - z.z, 0.f);
        sS[(c4 + 3) * 68 + t] = fmaxf(a.w - z.w, 0.f);
    }
    __syncthreads();

    // Phase A: H = relu(W1 * S + b1)
    {
        int f0 = (tid & 31) * 4;
        int t0 = (tid >> 5) * 8;
        float acc[4][8];
        #pragma unroll
        for (int fi = 0; fi < 4; fi++) {
            float bb = b1[f0 + fi];
            #pragma unroll
            for (int tj = 0; tj < 8; tj++) acc[fi][tj] = bb;
        }
        #pragma unroll 4
        for (int k = 0; k < 64; k++) {
            float4 w = *(const float4*)(sW1 + k * 128 + f0);
            float4 s0 = *(const float4*)(sS + k * 68 + t0);
            float4 s1 = *(const float4*)(sS + k * 68 + t0 + 4);
            float wa[4] = {w.x, w.y, w.z, w.w};
            float sa[8] = {s0.x, s0.y, s0.z, s0.w, s1.x, s1.y, s1.z, s1.w};
            #pragma unroll
            for (int fi = 0; fi < 4; fi++)
                #pragma unroll
                for (int tj = 0; tj < 8; tj++)
                    acc[fi][tj] = fmaf(wa[fi], sa[tj], acc[fi][tj]);
        }
        #pragma unroll
        for (int fi = 0; fi < 4; fi++) {
            float4 h0 = make_float4(fmaxf(acc[fi][0], 0.f), fmaxf(acc[fi][1], 0.f),
                                    fmaxf(acc[fi][2], 0.f), fmaxf(acc[fi][3], 0.f));
            float4 h1 = make_float4(fmaxf(acc[fi][4], 0.f), fmaxf(acc[fi][5], 0.f),
                                    fmaxf(acc[fi][6], 0.f), fmaxf(acc[fi][7], 0.f));
            *(float4*)(sH + (f0 + fi) * 68 + t0) = h0;
            *(float4*)(sH + (f0 + fi) * 68 + t0 + 4) = h1;
        }
    }
    __syncthreads();

    // Phase B: out = W2 * H + b2
    {
        int t0 = (tid & 15) * 4;
        int o = (tid >> 4) * 2;
        float bb0 = (o < OO) ? b2[o] : 0.f;
        float bb1 = (o + 1 < OO) ? b2[o + 1] : 0.f;
        float a0[4] = {bb0, bb0, bb0, bb0};
        float a1[4] = {bb1, bb1, bb1, bb1};
        #pragma unroll 8
        for (int k = 0; k < 128; k++) {
            float4 h = *(const float4*)(sH + k * 68 + t0);
            float ha[4] = {h.x, h.y, h.z, h.w};
            float wo0 = sW2[k * 32 + o];
            float wo1 = sW2[k * 32 + o + 1];
            #pragma unroll
            for (int tj = 0; tj < 4; tj++) {
                a0[tj] = fmaf(wo0, ha[tj], a0[tj]);
                a1[tj] = fmaf(wo1, ha[tj], a1[tj]);
            }
        }
        if (o < OO)
            *(float4*)(out + ((size_t)b * OO + o) * LL + tt0 + t0) =
                make_float4(a0[0], a0[1], a0[2], a0[3]);
        if (o + 1 < OO)
            *(float4*)(out + ((size_t)b * OO + o + 1) * LL + tt0 + t0) =
                make_float4(a1[0], a1[1], a1[2], a1[3]);
    }
}

// ---------------- launch -----------------------------------------------------
extern "C" void kernel_launch(void* const* d_in, const int* in_sizes, int n_in,
                              void* d_out, int out_size)
{
    const int*   in_tok = (const int*)d_in[0];
    const int*   g_tok  = (const int*)d_in[1];
    const float* emb    = (const float*)d_in[2];
    const float* wc     = (const float*)d_in[3];
    const float* bc     = (const float*)d_in[4];
    const float* wf     = (const float*)d_in[5];
    const float* bf     = (const float*)d_in[6];
    const float* wg     = (const float*)d_in[7];
    const float* bg     = (const float*)d_in[8];
    const float* wlf    = (const float*)d_in[9];
    const float* blf    = (const float*)d_in[10];
    const float* wlg    = (const float*)d_in[11];
    const float* blg    = (const float*)d_in[12];
    const float* wres   = (const float*)d_in[13];
    const float* bres   = (const float*)d_in[14];
    const float* w1     = (const float*)d_in[15];
    const float* b1     = (const float*)d_in[16];
    const float* w2     = (const float*)d_in[17];
    const float* b2     = (const float*)d_in[18];
    float* out = (float*)d_out;

    const int LAYER_SMEM = (5 * 4096 + 2 * 64 * 2 * PSTR) * 4;             // 215040 B
    const int FINAL_SMEM = (64 * 68 + 64 * 128 + 128 * 68 + 128 * 32) * 4; // 101376 B
    cudaFuncSetAttribute(k_layer, cudaFuncAttributeMaxDynamicSharedMemorySize, LAYER_SMEM);
    cudaFuncSetAttribute(k_final, cudaFuncAttributeMaxDynamicSharedMemorySize, FINAL_SMEM);

    k_precompute_M<<<VV, 64>>>(emb, wc);
    k_embg<<<BB, 256>>>(g_tok, emb);
    k_H<<<dim3(NDND, BB), 128>>>(wlf, blf, wlg, blg);
    k_init<<<dim3(LL / 64, BB), 256>>>(in_tok, bc);
    for (int i = 0; i < NDND; i++) {
        int d = 2 << i;                               // 2^(i+1)
        int out_sel = (i % 2 == 0) ? 1 : 2;           // A, B, A, ...  (layer 8 -> A)
        int in_sel  = (i == 0) ? 0 : ((i % 2 == 0) ? 2 : 1);
        k_layer<<<dim3(LL / TS, BB), 128, LAYER_SMEM>>>(
            wf, bf, wg, bg, wres, bres, i, d, in_sel, out_sel);
    }
    k_final<<<dim3(LL / 64, BB), 256, FINAL_SMEM>>>(w1, b1, w2, b2, out);
}

// round 3
// speedup vs baseline: 1.3357x; 1.3357x over previous
#include <cuda_runtime.h>
#include <math.h>

#define BB   64
#define LL   2048
#define VV   30
#define EE   128
#define GG   8
#define GEGE 1024
#define CC   64
#define FF   128
#define OO   30
#define NDND 9

#define ASTR 68          // activation row stride (floats), 16B-aligned rows

typedef unsigned long long u64;

// ---------------- packed fp32 helpers --------------------------------------
__device__ __forceinline__ u64 ffma2(u64 a, u64 b, u64 c) {
    asm("fma.rn.f32x2 %0, %1, %2, %0;" : "+l"(c) : "l"(a), "l"(b));
    return c;
}
__device__ __forceinline__ u64 pack2(float lo, float hi) {
    u64 r; asm("mov.b64 %0, {%1, %2};" : "=l"(r) : "f"(lo), "f"(hi)); return r;
}
__device__ __forceinline__ u64 dup2(float v) {
    u64 r; asm("mov.b64 %0, {%1, %1};" : "=l"(r) : "f"(v)); return r;
}
__device__ __forceinline__ void unpack2(u64 v, float& lo, float& hi) {
    asm("mov.b64 {%0, %1}, %2;" : "=f"(lo), "=f"(hi) : "l"(v));
}
__device__ __forceinline__ float fast_tanh(float x) {
    float e; asm("ex2.approx.f32 %0, %1;" : "=f"(e) : "f"(x * 2.8853900817779268f)); // e^{2x}
    float r; asm("rcp.approx.f32 %0, %1;" : "=f"(r) : "f"(e + 1.0f));
    return 1.0f - 2.0f * r;
}
__device__ __forceinline__ float fast_sigmoid(float x) {
    float e; asm("ex2.approx.f32 %0, %1;" : "=f"(e) : "f"(-x * 1.4426950408889634f)); // e^{-x}
    float r; asm("rcp.approx.f32 %0, %1;" : "=f"(r) : "f"(e + 1.0f));
    return r;
}

// ---------------- scratch (device globals) ----------------------------------
__device__ float g_res0[(size_t)BB * LL * CC];   // initial residual (preserved)
__device__ float g_resA[(size_t)BB * LL * CC];   // ping
__device__ float g_resB[(size_t)BB * LL * CC];   // pong
__device__ float g_embg[BB * GEGE];
__device__ float g_HF[NDND * BB * CC];
__device__ float g_HG[NDND * BB * CC];
__device__ float g_M0[VV * CC];
__device__ float g_M1[VV * CC];

__device__ __forceinline__ const float* buf_c(int sel) {
    return sel == 0 ? g_res0 : (sel == 1 ? g_resA : g_resB);
}
__device__ __forceinline__ float* buf_m(int sel) {
    return sel == 1 ? g_resA : g_resB;
}

// ---------------- K0: fold embedding + initial conv into lookup -------------
__global__ void __launch_bounds__(64) k_precompute_M(
    const float* __restrict__ emb, const float* __restrict__ wc)
{
    int v = blockIdx.x, c = threadIdx.x;
    float a0 = 0.f, a1 = 0.f;
    if (v != 0) {
        for (int e = 0; e < EE; e++) {
            float x = emb[v * EE + e];
            a0 = fmaf(x, wc[(c * EE + e) * 2 + 0], a0);
            a1 = fmaf(x, wc[(c * EE + e) * 2 + 1], a1);
        }
    }
    g_M0[v * CC + c] = a0;
    g_M1[v * CC + c] = a1;
}

// ---------------- K1: global embedding --------------------------------------
__global__ void __launch_bounds__(256) k_embg(
    const int* __restrict__ gin, const float* __restrict__ emb)
{
    int b = blockIdx.x;
    for (int j = threadIdx.x; j < GEGE; j += 256) {
        int g = j >> 7, e = j & 127;
        int tok = gin[b * GG + g];
        g_embg[b * GEGE + j] = (tok == 0) ? 0.f : emb[tok * EE + e];
    }
}

// ---------------- K2: conditioning vectors ----------------------------------
__global__ void __launch_bounds__(128) k_H(
    const float* __restrict__ wlf, const float* __restrict__ blf,
    const float* __restrict__ wlg, const float* __restrict__ blg)
{
    __shared__ float se[GEGE];
    int i = blockIdx.x, b = blockIdx.y, tid = threadIdx.x;
    for (int j = tid; j < GEGE; j += 128) se[j] = g_embg[b * GEGE + j];
    __syncthreads();
    int c = tid & 63;
    bool isf = tid < 64;
    const float* w = (isf ? wlf : wlg) + ((size_t)i * CC + c) * GEGE;
    float acc = (isf ? blf : blg)[i * CC + c];
    for (int j = 0; j < GEGE; j += 4) {
        float4 wv = *(const float4*)(w + j);
        acc = fmaf(se[j], wv.x, acc);
        acc = fmaf(se[j + 1], wv.y, acc);
        acc = fmaf(se[j + 2], wv.z, acc);
        acc = fmaf(se[j + 3], wv.w, acc);
    }
    (isf ? g_HF : g_HG)[((size_t)i * BB + b) * CC + c] = acc;
}

// ---------------- K3: initial residual via lookup ----------------------------
__global__ void __launch_bounds__(256) k_init(
    const int* __restrict__ tok, const float* __restrict__ b_causal)
{
    __shared__ float sM0[VV * CC], sM1[VV * CC], sb[CC];
    int tid = threadIdx.x;
    for (int i = tid; i < VV * CC; i += 256) { sM0[i] = g_M0[i]; sM1[i] = g_M1[i]; }
    if (tid < CC) sb[tid] = b_causal[tid];
    __syncthreads();
    int b = blockIdx.y, tt0 = blockIdx.x * 64;
    const int* tb = tok + b * LL;
    float* ro = g_res0 + (size_t)b * LL * CC;
    for (int idx = tid; idx < 64 * 64; idx += 256) {
        int t = tt0 + (idx >> 6);
        int c = idx & 63;
        float r = sM1[tb[t] * CC + c] + sb[c];
        if (t > 0) r += sM0[tb[t - 1] * CC + c];
        ro[(size_t)t * CC + c] = r;
    }
}

// ---------------- K4: dilated residual layer (FFMA2, 16 warps/SM) ------------
// Block: 256 threads, tile = 64 timesteps x 64 channels of one batch.
// Thread tile: 4 channels (2 pairs) x 4 timesteps. Activation broadcast pairs
// packed in registers (no SMEM duplication). W_res & Z overlay phase-1 SMEM.
__global__ void __launch_bounds__(256, 2) k_layer(
    const float* __restrict__ w_f, const float* __restrict__ b_f,
    const float* __restrict__ w_g, const float* __restrict__ b_g,
    const float* __restrict__ w_res, const float* __restrict__ b_res,
    int layer, int d, int in_sel, int out_sel)
{
    extern __shared__ float sm[];
    float* sWf0 = sm;                 // [k][c] 64x64 (overlaid by W_res in phase 2)
    float* sWf1 = sWf0 + 4096;
    float* sWg0 = sWf1 + 4096;
    float* sWg1 = sWg0 + 4096;
    float* sCur = sWg1 + 4096;        // [c][t] 64 x ASTR
    float* sPrev = sCur + 64 * ASTR;  // [c][t]; overlaid by Z in phase 2

    int tid = threadIdx.x;
    int b = blockIdx.y;
    int tt0 = blockIdx.x * 64;

    // ---- phase-1 weights, transposed to [k][c] ----
    const float* wf = w_f + (size_t)layer * CC * CC * 2;
    const float* wg = w_g + (size_t)layer * CC * CC * 2;
    for (int idx = tid; idx < CC * CC; idx += 256) {
        int co = idx >> 6, ci = idx & 63;
        int tr = ci * 64 + co;
        float2 f2 = *(const float2*)(wf + idx * 2);
        float2 g2 = *(const float2*)(wg + idx * 2);
        sWf0[tr] = f2.x;
        sWf1[tr] = f2.y;
        sWg0[tr] = g2.x;
        sWg1[tr] = g2.y;
    }

    // ---- activations [c][t] ----
    const float* rin = buf_c(in_sel) + (size_t)b * LL * CC;
    for (int f = tid; f < 64 * 16; f += 256) {
        int t = f >> 4;
        int c4 = (f & 15) * 4;
        float4 v = *(const float4*)(rin + (size_t)(tt0 + t) * CC + c4);
        sCur[(c4 + 0) * ASTR + t] = v.x;
        sCur[(c4 + 1) * ASTR + t] = v.y;
        sCur[(c4 + 2) * ASTR + t] = v.z;
        sCur[(c4 + 3) * ASTR + t] = v.w;
        int tp = tt0 + t - d;
        float4 p = make_float4(0.f, 0.f, 0.f, 0.f);
        if (tp >= 0) p = *(const float4*)(rin + (size_t)tp * CC + c4);
        sPrev[(c4 + 0) * ASTR + t] = p.x;
        sPrev[(c4 + 1) * ASTR + t] = p.y;
        sPrev[(c4 + 2) * ASTR + t] = p.z;
        sPrev[(c4 + 3) * ASTR + t] = p.w;
    }
    __syncthreads();

    int c0 = (tid & 15) * 4;     // 4 channels = 2 pairs (coalesced epilogue)
    int t0 = (tid >> 4) * 4;     // 4 timesteps

    // ---- phase 1: packed accumulators for x_f / x_g ----
    u64 af[2][4], ag[2][4];
    {
        const float* bfp = b_f + layer * CC;
        const float* bgp = b_g + layer * CC;
        const float* hfp = g_HF + ((size_t)layer * BB + b) * CC;
        const float* hgp = g_HG + ((size_t)layer * BB + b) * CC;
        #pragma unroll
        for (int cp = 0; cp < 2; cp++) {
            int c = c0 + 2 * cp;
            u64 hf = pack2(bfp[c] + hfp[c], bfp[c + 1] + hfp[c + 1]);
            u64 hg = pack2(bgp[c] + hgp[c], bgp[c + 1] + hgp[c + 1]);
            #pragma unroll
            for (int tj = 0; tj < 4; tj++) { af[cp][tj] = hf; ag[cp][tj] = hg; }
        }
    }

    #pragma unroll 2
    for (int k = 0; k < 64; k++) {
        int wo = k * 64 + c0;
        ulonglong2 F = *(const ulonglong2*)(sWf0 + wo);   // (c0,c0+1),(c0+2,c0+3)
        ulonglong2 H = *(const ulonglong2*)(sWf1 + wo);
        ulonglong2 G = *(const ulonglong2*)(sWg0 + wo);
        ulonglong2 J = *(const ulonglong2*)(sWg1 + wo);
        int ao = k * ASTR + t0;
        float4 pv4 = *(const float4*)(sPrev + ao);
        float4 cv4 = *(const float4*)(sCur + ao);
        u64 pp[4] = {dup2(pv4.x), dup2(pv4.y), dup2(pv4.z), dup2(pv4.w)};
        u64 cc[4] = {dup2(cv4.x), dup2(cv4.y), dup2(cv4.z), dup2(cv4.w)};
        u64 Fv[2] = {F.x, F.y}, Hv[2] = {H.x, H.y};
        u64 Gv[2] = {G.x, G.y}, Jv[2] = {J.x, J.y};
        #pragma unroll
        for (int cp = 0; cp < 2; cp++)
            #pragma unroll
            for (int tj = 0; tj < 4; tj++) {
                af[cp][tj] = ffma2(Fv[cp], pp[tj], af[cp][tj]);
                af[cp][tj] = ffma2(Hv[cp], cc[tj], af[cp][tj]);
                ag[cp][tj] = ffma2(Gv[cp], pp[tj], ag[cp][tj]);
                ag[cp][tj] = ffma2(Jv[cp], cc[tj], ag[cp][tj]);
            }
    }
    __syncthreads();   // done reading sPrev / sWf0

    // ---- gated activation -> Z (overlays sPrev); W_res -> overlays sWf0 ----
    float* sZ = sPrev;
    float* sWr = sWf0;
    #pragma unroll
    for (int cp = 0; cp < 2; cp++) {
        float z0[4], z1[4];
        #pragma unroll
        for (int tj = 0; tj < 4; tj++) {
            float x0, x1, y0, y1;
            unpack2(af[cp][tj], x0, x1);
            unpack2(ag[cp][tj], y0, y1);
            z0[tj] = fast_tanh(x0) * fast_sigmoid(y0);
            z1[tj] = fast_tanh(x1) * fast_sigmoid(y1);
        }
        int c = c0 + 2 * cp;
        *(float4*)(sZ + c * ASTR + t0) = make_float4(z0[0], z0[1], z0[2], z0[3]);
        *(float4*)(sZ + (c + 1) * ASTR + t0) = make_float4(z1[0], z1[1], z1[2], z1[3]);
    }
    {
        const float* wr = w_res + (size_t)layer * CC * CC;
        for (int idx = tid; idx < CC * CC; idx += 256) {
            int co = idx >> 6, ci = idx & 63;
            sWr[ci * 64 + co] = wr[idx];
        }
    }
    __syncthreads();

    // ---- phase 2: skip = W_res * z ----
    u64 as[2][4];
    {
        const float* brp = b_res + layer * CC;
        #pragma unroll
        for (int cp = 0; cp < 2; cp++) {
            u64 bp = pack2(brp[c0 + 2 * cp], brp[c0 + 2 * cp + 1]);
            #pragma unroll
            for (int tj = 0; tj < 4; tj++) as[cp][tj] = bp;
        }
    }
    #pragma unroll 4
    for (int k = 0; k < 64; k++) {
        ulonglong2 W = *(const ulonglong2*)(sWr + k * 64 + c0);
        float4 zz = *(const float4*)(sZ + k * ASTR + t0);
        u64 zp[4] = {dup2(zz.x), dup2(zz.y), dup2(zz.z), dup2(zz.w)};
        u64 Wv[2] = {W.x, W.y};
        #pragma unroll
        for (int cp = 0; cp < 2; cp++)
            #pragma unroll
            for (int tj = 0; tj < 4; tj++)
                as[cp][tj] = ffma2(Wv[cp], zp[tj], as[cp][tj]);
    }

    // ---- epilogue: res_out = res_in + skip ----
    float cr[4][4];   // [ci][tj]
    #pragma unroll
    for (int ci = 0; ci < 4; ci++) {
        float4 v = *(const float4*)(sCur + (c0 + ci) * ASTR + t0);
        cr[ci][0] = v.x; cr[ci][1] = v.y; cr[ci][2] = v.z; cr[ci][3] = v.w;
    }
    float* rout = buf_m(out_sel) + (size_t)b * LL * CC;
    #pragma unroll
    for (int tj = 0; tj < 4; tj++) {
        float s0, s1, s2, s3;
        unpack2(as[0][tj], s0, s1);
        unpack2(as[1][tj], s2, s3);
        *(float4*)(rout + (size_t)(tt0 + t0 + tj) * CC + c0) =
            make_float4(cr[0][tj] + s0, cr[1][tj] + s1, cr[2][tj] + s2, cr[3][tj] + s3);
    }
}

// ---------------- K5: head: relu(resA - res0) -> 64x128 -> relu -> 128x30 ---
__global__ void __launch_bounds__(256) k_final(
    const float* __restrict__ w1, const float* __restrict__ b1,
    const float* __restrict__ w2, const float* __restrict__ b2,
    float* __restrict__ out)
{
    extern __shared__ float sm[];
    float* sS  = sm;                  // [c][t] 64x68
    float* sW1 = sS + 64 * 68;        // [c][f] 64x128
    float* sH  = sW1 + 64 * 128;      // [f][t] 128x68
    float* sW2 = sH + 128 * 68;       // [f][o] 128x32

    int tid = threadIdx.x;
    int b = blockIdx.y;
    int tt0 = blockIdx.x * 64;

    for (int idx = tid; idx < FF * CC; idx += 256) {
        int f = idx >> 6, c = idx & 63;
        sW1[c * 128 + f] = w1[idx];
    }
    for (int idx = tid; idx < 128 * 32; idx += 256) {
        int f = idx >> 5, o = idx & 31;
        sW2[idx] = (o < OO) ? w2[o * 128 + f] : 0.f;
    }
    const float* rA = g_resA + (size_t)b * LL * CC;
    const float* r0 = g_res0 + (size_t)b * LL * CC;
    for (int f4 = tid; f4 < 1024; f4 += 256) {
        int t = f4 >> 4, c4 = (f4 & 15) * 4;
        size_t off = (size_t)(tt0 + t) * CC + c4;
        float4 a = *(const float4*)(rA + off);
        float4 z = *(const float4*)(r0 + off);
        sS[(c4 + 0) * 68 + t] = fmaxf(a.x - z.x, 0.f);
        sS[(c4 + 1) * 68 + t] = fmaxf(a.y - z.y, 0.f);
        sS[(c4 + 2) * 68 + t] = fmaxf(a.z - z.z, 0.f);
        sS[(c4 + 3) * 68 + t] = fmaxf(a.w - z.w, 0.f);
    }
    __syncthreads();

    // Phase A: H = relu(W1 * S + b1)
    {
        int f0 = (tid & 31) * 4;
        int t0 = (tid >> 5) * 8;
        float acc[4][8];
        #pragma unroll
        for (int fi = 0; fi < 4; fi++) {
            float bb = b1[f0 + fi];
            #pragma unroll
            for (int tj = 0; tj < 8; tj++) acc[fi][tj] = bb;
        }
        #pragma unroll 4
        for (int k = 0; k < 64; k++) {
            float4 w = *(const float4*)(sW1 + k * 128 + f0);
            float4 s0 = *(const float4*)(sS + k * 68 + t0);
            float4 s1 = *(const float4*)(sS + k * 68 + t0 + 4);
            float wa[4] = {w.x, w.y, w.z, w.w};
            float sa[8] = {s0.x, s0.y, s0.z, s0.w, s1.x, s1.y, s1.z, s1.w};
            #pragma unroll
            for (int fi = 0; fi < 4; fi++)
                #pragma unroll
                for (int tj = 0; tj < 8; tj++)
                    acc[fi][tj] = fmaf(wa[fi], sa[tj], acc[fi][tj]);
        }
        #pragma unroll
        for (int fi = 0; fi < 4; fi++) {
            float4 h0 = make_float4(fmaxf(acc[fi][0], 0.f), fmaxf(acc[fi][1], 0.f),
                                    fmaxf(acc[fi][2], 0.f), fmaxf(acc[fi][3], 0.f));
            float4 h1 = make_float4(fmaxf(acc[fi][4], 0.f), fmaxf(acc[fi][5], 0.f),
                                    fmaxf(acc[fi][6], 0.f), fmaxf(acc[fi][7], 0.f));
            *(float4*)(sH + (f0 + fi) * 68 + t0) = h0;
            *(float4*)(sH + (f0 + fi) * 68 + t0 + 4) = h1;
        }
    }
    __syncthreads();

    // Phase B: out = W2 * H + b2
    {
        int t0 = (tid & 15) * 4;
        int o = (tid >> 4) * 2;
        float bb0 = (o < OO) ? b2[o] : 0.f;
        float bb1 = (o + 1 < OO) ? b2[o + 1] : 0.f;
        float a0[4] = {bb0, bb0, bb0, bb0};
        float a1[4] = {bb1, bb1, bb1, bb1};
        #pragma unroll 8
        for (int k = 0; k < 128; k++) {
            float4 h = *(const float4*)(sH + k * 68 + t0);
            float ha[4] = {h.x, h.y, h.z, h.w};
            float wo0 = sW2[k * 32 + o];
            float wo1 = sW2[k * 32 + o + 1];
            #pragma unroll
            for (int tj = 0; tj < 4; tj++) {
                a0[tj] = fmaf(wo0, ha[tj], a0[tj]);
                a1[tj] = fmaf(wo1, ha[tj], a1[tj]);
            }
        }
        if (o < OO)
            *(float4*)(out + ((size_t)b * OO + o) * LL + tt0 + t0) =
                make_float4(a0[0], a0[1], a0[2], a0[3]);
        if (o + 1 < OO)
            *(float4*)(out + ((size_t)b * OO + o + 1) * LL + tt0 + t0) =
                make_float4(a1[0], a1[1], a1[2], a1[3]);
    }
}

// ---------------- launch -----------------------------------------------------
extern "C" void kernel_launch(void* const* d_in, const int* in_sizes, int n_in,
                              void* d_out, int out_size)
{
    const int*   in_tok = (const int*)d_in[0];
    const int*   g_tok  = (const int*)d_in[1];
    const float* emb    = (const float*)d_in[2];
    const float* wc     = (const float*)d_in[3];
    const float* bc     = (const float*)d_in[4];
    const float* wf     = (const float*)d_in[5];
    const float* bf     = (const float*)d_in[6];
    const float* wg     = (const float*)d_in[7];
    const float* bg     = (const float*)d_in[8];
    const float* wlf    = (const float*)d_in[9];
    const float* blf    = (const float*)d_in[10];
    const float* wlg    = (const float*)d_in[11];
    const float* blg    = (const float*)d_in[12];
    const float* wres   = (const float*)d_in[13];
    const float* bres   = (const float*)d_in[14];
    const float* w1     = (const float*)d_in[15];
    const float* b1     = (const float*)d_in[16];
    const float* w2     = (const float*)d_in[17];
    const float* b2     = (const float*)d_in[18];
    float* out = (float*)d_out;

    const int LAYER_SMEM = (4 * 4096 + 2 * 64 * ASTR) * 4;                 // 100352 B
    const int FINAL_SMEM = (64 * 68 + 64 * 128 + 128 * 68 + 128 * 32) * 4; // 101376 B
    cudaFuncSetAttribute(k_layer, cudaFuncAttributeMaxDynamicSharedMemorySize, LAYER_SMEM);
    cudaFuncSetAttribute(k_final, cudaFuncAttributeMaxDynamicSharedMemorySize, FINAL_SMEM);

    k_precompute_M<<<VV, 64>>>(emb, wc);
    k_embg<<<BB, 256>>>(g_tok, emb);
    k_H<<<dim3(NDND, BB), 128>>>(wlf, blf, wlg, blg);
    k_init<<<dim3(LL / 64, BB), 256>>>(in_tok, bc);
    for (int i = 0; i < NDND; i++) {
        int d = 2 << i;                               // 2^(i+1)
        int out_sel = (i % 2 == 0) ? 1 : 2;           // A, B, A, ...  (layer 8 -> A)
        int in_sel  = (i == 0) ? 0 : ((i % 2 == 0) ? 2 : 1);
        k_layer<<<dim3(LL / 64, BB), 256, LAYER_SMEM>>>(
            wf, bf, wg, bg, wres, bres, i, d, in_sel, out_sel);
    }
    k_final<<<dim3(LL / 64, BB), 256, FINAL_SMEM>>>(w1, b1, w2, b2, out);
}

// round 4
// speedup vs baseline: 3.7746x; 2.8260x over previous
#include <cuda_runtime.h>
#include <cuda_bf16.h>
#include <math.h>

#define BB   64
#define LL   2048
#define VV   30
#define EE   128
#define GG   8
#define GEGE 1024
#define CC   64
#define FF   128
#define OO   30
#define NDND 9

typedef unsigned int u32;

// ---------------- helpers ----------------------------------------------------
__device__ __forceinline__ void mma16816(float* d, u32 a0, u32 a1, u32 a2, u32 a3,
                                         u32 b0, u32 b1) {
    asm volatile(
        "mma.sync.aligned.m16n8k16.row.col.f32.bf16.bf16.f32 "
        "{%0,%1,%2,%3}, {%4,%5,%6,%7}, {%8,%9}, {%0,%1,%2,%3};"
        : "+f"(d[0]), "+f"(d[1]), "+f"(d[2]), "+f"(d[3])
        : "r"(a0), "r"(a1), "r"(a2), "r"(a3), "r"(b0), "r"(b1));
}
// split two floats into packed-bf16 (hi, lo) pairs; first arg in low 16 bits
__device__ __forceinline__ void split2(float x0, float x1, u32& hi, u32& lo) {
    __nv_bfloat16 h0 = __float2bfloat16_rn(x0);
    __nv_bfloat16 h1 = __float2bfloat16_rn(x1);
    float r0 = x0 - __bfloat162float(h0);
    float r1 = x1 - __bfloat162float(h1);
    __nv_bfloat162 hv; hv.x = h0; hv.y = h1;
    __nv_bfloat162 lv; lv.x = __float2bfloat16_rn(r0); lv.y = __float2bfloat16_rn(r1);
    hi = *(u32*)&hv; lo = *(u32*)&lv;
}
__device__ __forceinline__ float fast_tanh(float x) {
    float e; asm("ex2.approx.f32 %0, %1;" : "=f"(e) : "f"(x * 2.8853900817779268f));
    float r; asm("rcp.approx.f32 %0, %1;" : "=f"(r) : "f"(e + 1.0f));
    return 1.0f - 2.0f * r;
}
__device__ __forceinline__ float fast_sigmoid(float x) {
    float e; asm("ex2.approx.f32 %0, %1;" : "=f"(e) : "f"(-x * 1.4426950408889634f));
    float r; asm("rcp.approx.f32 %0, %1;" : "=f"(r) : "f"(e + 1.0f));
    return r;
}

// ---------------- scratch ----------------------------------------------------
__device__ float g_res0[(size_t)BB * LL * CC];
__device__ float g_resA[(size_t)BB * LL * CC];
__device__ float g_resB[(size_t)BB * LL * CC];
__device__ float g_embg[BB * GEGE];
__device__ float g_HF[NDND * BB * CC];
__device__ float g_HG[NDND * BB * CC];
__device__ float g_M0[VV * CC];
__device__ float g_M1[VV * CC];
// weights in mma-fragment layout, bf16 hi/lo split
__device__ u32 g_WF[NDND * 16384];   // [layer][warp8][kstep8][half2][lane32][reg4]
__device__ u32 g_WR[NDND * 4096];    // [layer][mtile4][kstep4][half2][lane32][reg4]

__device__ __forceinline__ const float* buf_c(int sel) {
    return sel == 0 ? g_res0 : (sel == 1 ? g_resA : g_resB);
}
__device__ __forceinline__ float* buf_m(int sel) {
    return sel == 1 ? g_resA : g_resB;
}

// ---------------- K0a: fold embedding + initial conv -------------------------
__global__ void __launch_bounds__(64) k_precompute_M(
    const float* __restrict__ emb, const float* __restrict__ wc)
{
    int v = blockIdx.x, c = threadIdx.x;
    float a0 = 0.f, a1 = 0.f;
    if (v != 0) {
        for (int e = 0; e < EE; e++) {
            float x = emb[v * EE + e];
            a0 = fmaf(x, wc[(c * EE + e) * 2 + 0], a0);
            a1 = fmaf(x, wc[(c * EE + e) * 2 + 1], a1);
        }
    }
    g_M0[v * CC + c] = a0;
    g_M1[v * CC + c] = a1;
}

// ---------------- K0b: weights -> fragment layout, bf16 split ----------------
__global__ void __launch_bounds__(256) k_prep_w(
    const float* __restrict__ wf, const float* __restrict__ wg,
    const float* __restrict__ wres)
{
    int layer = blockIdx.x;
    // GEMM1 A: [m=128 (f||g)][k=128 (prev||cur)]
    for (int idx = threadIdx.x; idx < 16384; idx += 256) {
        int w = idx >> 11, s = (idx >> 8) & 7, h = (idx >> 7) & 1;
        int lane = (idx >> 2) & 31, r = idx & 3;
        int m = w * 16 + (r & 1) * 8 + (lane >> 2);
        int k0 = s * 16 + ((r >> 1) & 1) * 8 + (lane & 3) * 2;
        const float* src = (m < 64) ? wf : wg;
        int cout = m & 63;
        int cin0 = k0 & 63, tap0 = k0 >> 6;
        int k1 = k0 + 1;
        int cin1 = k1 & 63, tap1 = k1 >> 6;
        float x0 = src[(((size_t)layer * 64 + cout) * 64 + cin0) * 2 + tap0];
        float x1 = src[(((size_t)layer * 64 + cout) * 64 + cin1) * 2 + tap1];
        u32 hi, lo; split2(x0, x1, hi, lo);
        g_WF[(size_t)layer * 16384 + idx] = h ? lo : hi;
    }
    // GEMM2 A: W_res [m=64][k=64]
    for (int idx = threadIdx.x; idx < 4096; idx += 256) {
        int mt = idx >> 10, s = (idx >> 8) & 3, h = (idx >> 7) & 1;
        int lane = (idx >> 2) & 31, r = idx & 3;
        int m = mt * 16 + (r & 1) * 8 + (lane >> 2);
        int k0 = s * 16 + ((r >> 1) & 1) * 8 + (lane & 3) * 2;
        float x0 = wres[((size_t)layer * 64 + m) * 64 + k0];
        float x1 = wres[((size_t)layer * 64 + m) * 64 + k0 + 1];
        u32 hi, lo; split2(x0, x1, hi, lo);
        g_WR[(size_t)layer * 4096 + idx] = h ? lo : hi;
    }
}

// ---------------- K1: global embedding ---------------------------------------
__global__ void __launch_bounds__(256) k_embg(
    const int* __restrict__ gin, const float* __restrict__ emb)
{
    int b = blockIdx.x;
    for (int j = threadIdx.x; j < GEGE; j += 256) {
        int g = j >> 7, e = j & 127;
        int tok = gin[b * GG + g];
        g_embg[b * GEGE + j] = (tok == 0) ? 0.f : emb[tok * EE + e];
    }
}

// ---------------- K2: conditioning vectors -----------------------------------
__global__ void __launch_bounds__(128) k_H(
    const float* __restrict__ wlf, const float* __restrict__ blf,
    const float* __restrict__ wlg, const float* __restrict__ blg)
{
    __shared__ float se[GEGE];
    int i = blockIdx.x, b = blockIdx.y, tid = threadIdx.x;
    for (int j = tid; j < GEGE; j += 128) se[j] = g_embg[b * GEGE + j];
    __syncthreads();
    int c = tid & 63;
    bool isf = tid < 64;
    const float* w = (isf ? wlf : wlg) + ((size_t)i * CC + c) * GEGE;
    float acc = (isf ? blf : blg)[i * CC + c];
    for (int j = 0; j < GEGE; j += 4) {
        float4 wv = *(const float4*)(w + j);
        acc = fmaf(se[j], wv.x, acc);
        acc = fmaf(se[j + 1], wv.y, acc);
        acc = fmaf(se[j + 2], wv.z, acc);
        acc = fmaf(se[j + 3], wv.w, acc);
    }
    (isf ? g_HF : g_HG)[((size_t)i * BB + b) * CC + c] = acc;
}

// ---------------- K3: initial residual via lookup ----------------------------
__global__ void __launch_bounds__(256) k_init(
    const int* __restrict__ tok, const float* __restrict__ b_causal)
{
    __shared__ float sM0[VV * CC], sM1[VV * CC], sb[CC];
    int tid = threadIdx.x;
    for (int i = tid; i < VV * CC; i += 256) { sM0[i] = g_M0[i]; sM1[i] = g_M1[i]; }
    if (tid < CC) sb[tid] = b_causal[tid];
    __syncthreads();
    int b = blockIdx.y, tt0 = blockIdx.x * 64;
    const int* tb = tok + b * LL;
    float* ro = g_res0 + (size_t)b * LL * CC;
    for (int idx = tid; idx < 64 * 64; idx += 256) {
        int t = tt0 + (idx >> 6);
        int c = idx & 63;
        float r = sM1[tb[t] * CC + c] + sb[c];
        if (t > 0) r += sM0[tb[t - 1] * CC + c];
        ro[(size_t)t * CC + c] = r;
    }
}

// ---------------- K4: dilated residual layer on tensor cores -----------------
// Tile: 64 timesteps x 64 channels of one batch. 256 threads = 8 warps.
// GEMM1: D[128(f||g),64t] = W[128,128] * X[128,64t], bf16 2-term split (3 MMAs).
// Activation -> Z (split). GEMM2: skip[64,64t] = W_res * Z. res_out = res + skip.
__global__ void __launch_bounds__(256, 2) k_layer_tc(
    const float* __restrict__ b_f, const float* __restrict__ b_g,
    const float* __restrict__ b_res,
    int layer, int d, int in_sel, int out_sel)
{
    extern __shared__ u32 smem_u[];
    u32* XH = smem_u;                 // 64 x 68 u32  (X hi, [t][kpair])
    u32* XL = smem_u + 4352;          // 64 x 68 u32  (X lo)
    u32* ZH = smem_u + 8704;          // 64 x 36 u32  (Z hi, [t][cpair])
    u32* ZL = smem_u + 11008;         // 64 x 36 u32
    float* sBF = (float*)(smem_u + 13312);  // 64
    float* sBG = sBF + 64;                  // 64
    float* Dsm = (float*)smem_u;      // overlays XH/XL: 128 x 68 f32
    float* SK  = (float*)ZH;          // overlays ZH/ZL: 64 x 68 f32

    int tid = threadIdx.x;
    int lane = tid & 31;
    int w = tid >> 5;
    int b = blockIdx.y;
    int tt0 = blockIdx.x * 64;

    // ---- biases + conditioning ----
    if (tid < 64)
        sBF[tid] = b_f[layer * CC + tid] + g_HF[((size_t)layer * BB + b) * CC + tid];
    else if (tid < 128) {
        int c = tid - 64;
        sBG[c] = b_g[layer * CC + c] + g_HG[((size_t)layer * BB + b) * CC + c];
    }

    // ---- build X = [prev(t-d) ; cur(t)] split hi/lo, layout [t][k] pitch 68 u32 ----
    const float* rin = buf_c(in_sel) + (size_t)b * LL * CC;
    #pragma unroll
    for (int it = 0; it < 8; it++) {
        int id = it * 256 + tid;          // 2048 = 64t * 32 k-quads
        int t = id >> 5;
        int kq = (id & 31) * 4;
        float4 v = make_float4(0.f, 0.f, 0.f, 0.f);
        if (kq < 64) {
            int gt = tt0 + t - d;
            if (gt >= 0) v = *(const float4*)(rin + (size_t)gt * CC + kq);
        } else {
            v = *(const float4*)(rin + (size_t)(tt0 + t) * CC + (kq - 64));
        }
        u32 h0, l0, h1, l1;
        split2(v.x, v.y, h0, l0);
        split2(v.z, v.w, h1, l1);
        int o = t * 68 + (kq >> 1);
        *(uint2*)&XH[o] = make_uint2(h0, h1);
        *(uint2*)&XL[o] = make_uint2(l0, l1);
    }
    __syncthreads();

    // ---- GEMM1: each warp owns m-rows [w*16, w*16+16) ----
    float acc[8][4];
    #pragma unroll
    for (int j = 0; j < 8; j++)
        #pragma unroll
        for (int r = 0; r < 4; r++) acc[j][r] = 0.f;

    const uint4* WFp = (const uint4*)(g_WF + ((size_t)layer * 8 + w) * 2048);
    int tb = lane >> 2;
    #pragma unroll
    for (int s = 0; s < 8; s++) {
        uint4 Ah = WFp[s * 64 + lane];
        uint4 Al = WFp[s * 64 + 32 + lane];
        int kb = s * 8 + (lane & 3);
        #pragma unroll
        for (int j = 0; j < 8; j++) {
            int base = (j * 8 + tb) * 68 + kb;
            u32 bh0 = XH[base], bh1 = XH[base + 4];
            u32 bl0 = XL[base], bl1 = XL[base + 4];
            mma16816(acc[j], Ah.x, Ah.y, Ah.z, Ah.w, bh0, bh1);
            mma16816(acc[j], Ah.x, Ah.y, Ah.z, Ah.w, bl0, bl1);
            mma16816(acc[j], Al.x, Al.y, Al.z, Al.w, bh0, bh1);
        }
    }
    __syncthreads();   // all warps done reading X; region A becomes D

    // ---- store D fragments: Dsm[m][t], pitch 68 ----
    {
        int g = lane >> 2, tq = 2 * (lane & 3);
        int m = w * 16 + g;
        #pragma unroll
        for (int j = 0; j < 8; j++) {
            int t = j * 8 + tq;
            *(float2*)&Dsm[m * 68 + t] = make_float2(acc[j][0], acc[j][1]);
            *(float2*)&Dsm[(m + 8) * 68 + t] = make_float2(acc[j][2], acc[j][3]);
        }
    }
    __syncthreads();

    // ---- gated activation -> Z split, layout [t][cpair] pitch 36 u32 ----
    #pragma unroll
    for (int it = 0; it < 8; it++) {
        int id = it * 256 + tid;          // 2048 = 64t * 32 c-pairs
        int cp = id & 31, t = id >> 5;
        float f0 = Dsm[(2 * cp) * 68 + t] + sBF[2 * cp];
        float f1 = Dsm[(2 * cp + 1) * 68 + t] + sBF[2 * cp + 1];
        float g0 = Dsm[(2 * cp + 64) * 68 + t] + sBG[2 * cp];
        float g1 = Dsm[(2 * cp + 65) * 68 + t] + sBG[2 * cp + 1];
        float z0 = fast_tanh(f0) * fast_sigmoid(g0);
        float z1 = fast_tanh(f1) * fast_sigmoid(g1);
        u32 zh, zl; split2(z0, z1, zh, zl);
        ZH[t * 36 + cp] = zh;
        ZL[t * 36 + cp] = zl;
    }
    __syncthreads();

    // ---- GEMM2: skip[64,64] = W_res * Z ----
    int mt = w >> 1, nb = (w & 1) * 4;
    float acc2[4][4];
    #pragma unroll
    for (int j = 0; j < 4; j++)
        #pragma unroll
        for (int r = 0; r < 4; r++) acc2[j][r] = 0.f;

    const uint4* WRp = (const uint4*)(g_WR + ((size_t)layer * 4 + mt) * 1024);
    #pragma unroll
    for (int s = 0; s < 4; s++) {
        uint4 Ah = WRp[s * 64 + lane];
        uint4 Al = WRp[s * 64 + 32 + lane];
        int kb = s * 8 + (lane & 3);
        #pragma unroll
        for (int j = 0; j < 4; j++) {
            int base = ((nb + j) * 8 + tb) * 36 + kb;
            u32 bh0 = ZH[base], bh1 = ZH[base + 4];
            u32 bl0 = ZL[base], bl1 = ZL[base + 4];
            mma16816(acc2[j], Ah.x, Ah.y, Ah.z, Ah.w, bh0, bh1);
            mma16816(acc2[j], Ah.x, Ah.y, Ah.z, Ah.w, bl0, bl1);
            mma16816(acc2[j], Al.x, Al.y, Al.z, Al.w, bh0, bh1);
        }
    }
    __syncthreads();   // all warps done reading Z; region B becomes SK

    // ---- store skip fragments: SK[t][c], pitch 68 ----
    {
        int m2 = mt * 16 + (lane >> 2);
        #pragma unroll
        for (int j = 0; j < 4; j++) {
            int t = (nb + j) * 8 + 2 * (lane & 3);
            SK[t * 68 + m2] = acc2[j][0];
            SK[(t + 1) * 68 + m2] = acc2[j][1];
            SK[t * 68 + m2 + 8] = acc2[j][2];
            SK[(t + 1) * 68 + m2 + 8] = acc2[j][3];
        }
    }
    __syncthreads();

    // ---- epilogue: res_out = res_in + skip + b_res ----
    const float* brp = b_res + layer * CC;
    float* rout = buf_m(out_sel) + (size_t)b * LL * CC;
    #pragma unroll
    for (int it = 0; it < 4; it++) {
        int id = it * 256 + tid;          // 1024 = 64t * 16 c-quads
        int t = id >> 4, cq = (id & 15) * 4;
        float4 rv = *(const float4*)(rin + (size_t)(tt0 + t) * CC + cq);
        float4 bz = *(const float4*)(brp + cq);
        float4 s4 = *(const float4*)&SK[t * 68 + cq];
        float4 o = make_float4(rv.x + s4.x + bz.x, rv.y + s4.y + bz.y,
                               rv.z + s4.z + bz.z, rv.w + s4.w + bz.w);
        *(float4*)(rout + (size_t)(tt0 + t) * CC + cq) = o;
    }
}

// ---------------- K5: head: relu(resA - res0) -> 64x128 -> relu -> 128x30 ----
__global__ void __launch_bounds__(256) k_final(
    const float* __restrict__ w1, const float* __restrict__ b1,
    const float* __restrict__ w2, const float* __restrict__ b2,
    float* __restrict__ out)
{
    extern __shared__ float sm[];
    float* sS  = sm;                  // [c][t] 64x68
    float* sW1 = sS + 64 * 68;        // [c][f] 64x128
    float* sH  = sW1 + 64 * 128;      // [f][t] 128x68
    float* sW2 = sH + 128 * 68;       // [f][o] 128x32

    int tid = threadIdx.x;
    int b = blockIdx.y;
    int tt0 = blockIdx.x * 64;

    for (int idx = tid; idx < FF * CC; idx += 256) {
        int f = idx >> 6, c = idx & 63;
        sW1[c * 128 + f] = w1[idx];
    }
    for (int idx = tid; idx < 128 * 32; idx += 256) {
        int f = idx >> 5, o = idx & 31;
        sW2[idx] = (o < OO) ? w2[o * 128 + f] : 0.f;
    }
    const float* rA = g_resA + (size_t)b * LL * CC;
    const float* r0 = g_res0 + (size_t)b * LL * CC;
    for (int f4 = tid; f4 < 1024; f4 += 256) {
        int t = f4 >> 4, c4 = (f4 & 15) * 4;
        size_t off = (size_t)(tt0 + t) * CC + c4;
        float4 a = *(const float4*)(rA + off);
        float4 z = *(const float4*)(r0 + off);
        sS[(c4 + 0) * 68 + t] = fmaxf(a.x - z.x, 0.f);
        sS[(c4 + 1) * 68 + t] = fmaxf(a.y - z.y, 0.f);
        sS[(c4 + 2) * 68 + t] = fmaxf(a.z - z.z, 0.f);
        sS[(c4 + 3) * 68 + t] = fmaxf(a.w - z.w, 0.f);
    }
    __syncthreads();

    {
        int f0 = (tid & 31) * 4;
        int t0 = (tid >> 5) * 8;
        float acc[4][8];
        #pragma unroll
        for (int fi = 0; fi < 4; fi++) {
            float bb = b1[f0 + fi];
            #pragma unroll
            for (int tj = 0; tj < 8; tj++) acc[fi][tj] = bb;
        }
        #pragma unroll 4
        for (int k = 0; k < 64; k++) {
            float4 w = *(const float4*)(sW1 + k * 128 + f0);
            float4 s0 = *(const float4*)(sS + k * 68 + t0);
            float4 s1 = *(const float4*)(sS + k * 68 + t0 + 4);
            float wa[4] = {w.x, w.y, w.z, w.w};
            float sa[8] = {s0.x, s0.y, s0.z, s0.w, s1.x, s1.y, s1.z, s1.w};
            #pragma unroll
            for (int fi = 0; fi < 4; fi++)
                #pragma unroll
                for (int tj = 0; tj < 8; tj++)
                    acc[fi][tj] = fmaf(wa[fi], sa[tj], acc[fi][tj]);
        }
        #pragma unroll
        for (int fi = 0; fi < 4; fi++) {
            float4 h0 = make_float4(fmaxf(acc[fi][0], 0.f), fmaxf(acc[fi][1], 0.f),
                                    fmaxf(acc[fi][2], 0.f), fmaxf(acc[fi][3], 0.f));
            float4 h1 = make_float4(fmaxf(acc[fi][4], 0.f), fmaxf(acc[fi][5], 0.f),
                                    fmaxf(acc[fi][6], 0.f), fmaxf(acc[fi][7], 0.f));
            *(float4*)(sH + (f0 + fi) * 68 + t0) = h0;
            *(float4*)(sH + (f0 + fi) * 68 + t0 + 4) = h1;
        }
    }
    __syncthreads();

    {
        int t0 = (tid & 15) * 4;
        int o = (tid >> 4) * 2;
        float bb0 = (o < OO) ? b2[o] : 0.f;
        float bb1 = (o + 1 < OO) ? b2[o + 1] : 0.f;
        float a0[4] = {bb0, bb0, bb0, bb0};
        float a1[4] = {bb1, bb1, bb1, bb1};
        #pragma unroll 8
        for (int k = 0; k < 128; k++) {
            float4 h = *(const float4*)(sH + k * 68 + t0);
            float ha[4] = {h.x, h.y, h.z, h.w};
            float wo0 = sW2[k * 32 + o];
            float wo1 = sW2[k * 32 + o + 1];
            #pragma unroll
            for (int tj = 0; tj < 4; tj++) {
                a0[tj] = fmaf(wo0, ha[tj], a0[tj]);
                a1[tj] = fmaf(wo1, ha[tj], a1[tj]);
            }
        }
        if (o < OO)
            *(float4*)(out + ((size_t)b * OO + o) * LL + tt0 + t0) =
                make_float4(a0[0], a0[1], a0[2], a0[3]);
        if (o + 1 < OO)
            *(float4*)(out + ((size_t)b * OO + o + 1) * LL + tt0 + t0) =
                make_float4(a1[0], a1[1], a1[2], a1[3]);
    }
}

// ---------------- launch -----------------------------------------------------
extern "C" void kernel_launch(void* const* d_in, const int* in_sizes, int n_in,
                              void* d_out, int out_size)
{
    const int*   in_tok = (const int*)d_in[0];
    const int*   g_tok  = (const int*)d_in[1];
    const float* emb    = (const float*)d_in[2];
    const float* wc     = (const float*)d_in[3];
    const float* bc     = (const float*)d_in[4];
    const float* wf     = (const float*)d_in[5];
    const float* bf     = (const float*)d_in[6];
    const float* wg     = (const float*)d_in[7];
    const float* bg     = (const float*)d_in[8];
    const float* wlf    = (const float*)d_in[9];
    const float* blf    = (const float*)d_in[10];
    const float* wlg    = (const float*)d_in[11];
    const float* blg    = (const float*)d_in[12];
    const float* wres   = (const float*)d_in[13];
    const float* bres   = (const float*)d_in[14];
    const float* w1     = (const float*)d_in[15];
    const float* b1     = (const float*)d_in[16];
    const float* w2     = (const float*)d_in[17];
    const float* b2     = (const float*)d_in[18];
    float* out = (float*)d_out;

    const int LAYER_SMEM = 13440 * 4;                                      // 53760 B
    const int FINAL_SMEM = (64 * 68 + 64 * 128 + 128 * 68 + 128 * 32) * 4; // 101376 B
    cudaFuncSetAttribute(k_layer_tc, cudaFuncAttributeMaxDynamicSharedMemorySize, LAYER_SMEM);
    cudaFuncSetAttribute(k_final, cudaFuncAttributeMaxDynamicSharedMemorySize, FINAL_SMEM);

    k_precompute_M<<<VV, 64>>>(emb, wc);
    k_prep_w<<<NDND, 256>>>(wf, wg, wres);
    k_embg<<<BB, 256>>>(g_tok, emb);
    k_H<<<dim3(NDND, BB), 128>>>(wlf, blf, wlg, blg);
    k_init<<<dim3(LL / 64, BB), 256>>>(in_tok, bc);
    for (int i = 0; i < NDND; i++) {
        int d = 2 << i;                               // 2^(i+1)
        int out_sel = (i % 2 == 0) ? 1 : 2;           // layer 8 -> resA
        int in_sel  = (i == 0) ? 0 : ((i % 2 == 0) ? 2 : 1);
        k_layer_tc<<<dim3(LL / 64, BB), 256, LAYER_SMEM>>>(
            bf, bg, bres, i, d, in_sel, out_sel);
    }
    k_final<<<dim3(LL / 64, BB), 256, FINAL_SMEM>>>(w1, b1, w2, b2, out);
}

// round 5
// speedup vs baseline: 4.5141x; 1.1959x over previous
#include <cuda_runtime.h>
#include <cuda_bf16.h>
#include <math.h>

#define BB   64
#define LL   2048
#define VV   30
#define EE   128
#define GG   8
#define GEGE 1024
#define CC   64
#define FF   128
#define OO   30
#define NDND 9

typedef unsigned int u32;

// ---------------- helpers ----------------------------------------------------
__device__ __forceinline__ void mma16816(float* d, u32 a0, u32 a1, u32 a2, u32 a3,
                                         u32 b0, u32 b1) {
    asm volatile(
        "mma.sync.aligned.m16n8k16.row.col.f32.bf16.bf16.f32 "
        "{%0,%1,%2,%3}, {%4,%5,%6,%7}, {%8,%9}, {%0,%1,%2,%3};"
        : "+f"(d[0]), "+f"(d[1]), "+f"(d[2]), "+f"(d[3])
        : "r"(a0), "r"(a1), "r"(a2), "r"(a3), "r"(b0), "r"(b1));
}
__device__ __forceinline__ void split2(float x0, float x1, u32& hi, u32& lo) {
    __nv_bfloat16 h0 = __float2bfloat16_rn(x0);
    __nv_bfloat16 h1 = __float2bfloat16_rn(x1);
    float r0 = x0 - __bfloat162float(h0);
    float r1 = x1 - __bfloat162float(h1);
    __nv_bfloat162 hv; hv.x = h0; hv.y = h1;
    __nv_bfloat162 lv; lv.x = __float2bfloat16_rn(r0); lv.y = __float2bfloat16_rn(r1);
    hi = *(u32*)&hv; lo = *(u32*)&lv;
}
__device__ __forceinline__ float fast_tanh(float x) {
    float e; asm("ex2.approx.f32 %0, %1;" : "=f"(e) : "f"(x * 2.8853900817779268f));
    float r; asm("rcp.approx.f32 %0, %1;" : "=f"(r) : "f"(e + 1.0f));
    return 1.0f - 2.0f * r;
}
__device__ __forceinline__ float fast_sigmoid(float x) {
    float e; asm("ex2.approx.f32 %0, %1;" : "=f"(e) : "f"(-x * 1.4426950408889634f));
    float r; asm("rcp.approx.f32 %0, %1;" : "=f"(r) : "f"(e + 1.0f));
    return r;
}

// ---------------- scratch ----------------------------------------------------
__device__ float g_res0[(size_t)BB * LL * CC];
__device__ float g_resA[(size_t)BB * LL * CC];
__device__ float g_resB[(size_t)BB * LL * CC];
__device__ float g_embg[BB * GEGE];
__device__ float g_HF[NDND * BB * CC];
__device__ float g_HG[NDND * BB * CC];
__device__ float g_M0[VV * CC];
__device__ float g_M1[VV * CC];
__device__ u32 g_WF[NDND * 16384];   // layer GEMM1 A frags (hi/lo split)
__device__ u32 g_WR[NDND * 4096];    // layer GEMM2 A frags
__device__ u32 g_W1[8192];           // head GEMM1 A frags: [warp8][kstep4][half2][lane32][reg4]
__device__ u32 g_W2[4096];           // head GEMM2 A frags: [mtile2][kstep8][half2][lane32][reg4]

__device__ __forceinline__ const float* buf_c(int sel) {
    return sel == 0 ? g_res0 : (sel == 1 ? g_resA : g_resB);
}
__device__ __forceinline__ float* buf_m(int sel) {
    return sel == 1 ? g_resA : g_resB;
}

// ---------------- K0a: fold embedding + initial conv -------------------------
__global__ void __launch_bounds__(64) k_precompute_M(
    const float* __restrict__ emb, const float* __restrict__ wc)
{
    int v = blockIdx.x, c = threadIdx.x;
    float a0 = 0.f, a1 = 0.f;
    if (v != 0) {
        for (int e = 0; e < EE; e++) {
            float x = emb[v * EE + e];
            a0 = fmaf(x, wc[(c * EE + e) * 2 + 0], a0);
            a1 = fmaf(x, wc[(c * EE + e) * 2 + 1], a1);
        }
    }
    g_M0[v * CC + c] = a0;
    g_M1[v * CC + c] = a1;
}

// ---------------- K0b: layer weights -> fragment layout -----------------------
__global__ void __launch_bounds__(256) k_prep_w(
    const float* __restrict__ wf, const float* __restrict__ wg,
    const float* __restrict__ wres)
{
    int layer = blockIdx.x;
    for (int idx = threadIdx.x; idx < 16384; idx += 256) {
        int w = idx >> 11, s = (idx >> 8) & 7, h = (idx >> 7) & 1;
        int lane = (idx >> 2) & 31, r = idx & 3;
        int m = w * 16 + (r & 1) * 8 + (lane >> 2);
        int k0 = s * 16 + ((r >> 1) & 1) * 8 + (lane & 3) * 2;
        const float* src = (m < 64) ? wf : wg;
        int cout = m & 63;
        int cin0 = k0 & 63, tap0 = k0 >> 6;
        int k1 = k0 + 1;
        int cin1 = k1 & 63, tap1 = k1 >> 6;
        float x0 = src[(((size_t)layer * 64 + cout) * 64 + cin0) * 2 + tap0];
        float x1 = src[(((size_t)layer * 64 + cout) * 64 + cin1) * 2 + tap1];
        u32 hi, lo; split2(x0, x1, hi, lo);
        g_WF[(size_t)layer * 16384 + idx] = h ? lo : hi;
    }
    for (int idx = threadIdx.x; idx < 4096; idx += 256) {
        int mt = idx >> 10, s = (idx >> 8) & 3, h = (idx >> 7) & 1;
        int lane = (idx >> 2) & 31, r = idx & 3;
        int m = mt * 16 + (r & 1) * 8 + (lane >> 2);
        int k0 = s * 16 + ((r >> 1) & 1) * 8 + (lane & 3) * 2;
        float x0 = wres[((size_t)layer * 64 + m) * 64 + k0];
        float x1 = wres[((size_t)layer * 64 + m) * 64 + k0 + 1];
        u32 hi, lo; split2(x0, x1, hi, lo);
        g_WR[(size_t)layer * 4096 + idx] = h ? lo : hi;
    }
}

// ---------------- K0c: head weights -> fragment layout ------------------------
__global__ void __launch_bounds__(256) k_prep_head(
    const float* __restrict__ w1, const float* __restrict__ w2)
{
    // W1: [m=128 f][k=64 c], 8 warps x 4 ksteps
    for (int idx = threadIdx.x; idx < 8192; idx += 256) {
        int w = idx >> 10, s = (idx >> 8) & 3, h = (idx >> 7) & 1;
        int lane = (idx >> 2) & 31, r = idx & 3;
        int m = w * 16 + (r & 1) * 8 + (lane >> 2);
        int k0 = s * 16 + ((r >> 1) & 1) * 8 + (lane & 3) * 2;
        float x0 = w1[m * 64 + k0];
        float x1 = w1[m * 64 + k0 + 1];
        u32 hi, lo; split2(x0, x1, hi, lo);
        g_W1[idx] = h ? lo : hi;
    }
    // W2: [m=32 (30 pad)][k=128 f], 2 mtiles x 8 ksteps
    for (int idx = threadIdx.x; idx < 4096; idx += 256) {
        int mt = idx >> 11, s = (idx >> 8) & 7, h = (idx >> 7) & 1;
        int lane = (idx >> 2) & 31, r = idx & 3;
        int m = mt * 16 + (r & 1) * 8 + (lane >> 2);
        int k0 = s * 16 + ((r >> 1) & 1) * 8 + (lane & 3) * 2;
        float x0 = (m < OO) ? w2[m * 128 + k0] : 0.f;
        float x1 = (m < OO) ? w2[m * 128 + k0 + 1] : 0.f;
        u32 hi, lo; split2(x0, x1, hi, lo);
        g_W2[idx] = h ? lo : hi;
    }
}

// ---------------- K1: global embedding ---------------------------------------
__global__ void __launch_bounds__(256) k_embg(
    const int* __restrict__ gin, const float* __restrict__ emb)
{
    int b = blockIdx.x;
    for (int j = threadIdx.x; j < GEGE; j += 256) {
        int g = j >> 7, e = j & 127;
        int tok = gin[b * GG + g];
        g_embg[b * GEGE + j] = (tok == 0) ? 0.f : emb[tok * EE + e];
    }
}

// ---------------- K2: conditioning vectors (restructured) ---------------------
// Grid (ND, 16 b-groups). Block 256: 128 rows (f||g x 64c) x 2 k-halves,
// 4 batches per block, SMEM reduction across halves.
__global__ void __launch_bounds__(256) k_H(
    const float* __restrict__ wlf, const float* __restrict__ blf,
    const float* __restrict__ wlg, const float* __restrict__ blg)
{
    __shared__ float sE[GEGE * 4];      // [k][b4]  16 KB
    __shared__ float sR[256 * 4];       // reduction buffer
    int i = blockIdx.x;
    int b0 = blockIdx.y * 4;
    int tid = threadIdx.x;

    for (int idx = tid; idx < GEGE * 4; idx += 256) {
        int k = idx >> 2, bj = idx & 3;
        sE[idx] = g_embg[(size_t)(b0 + bj) * GEGE + k];
    }
    __syncthreads();

    int row = tid & 127;          // 0..127: c + 64*isg
    int half = tid >> 7;          // k-half (warp-uniform)
    int c = row & 63;
    bool isf = row < 64;
    const float* w = (isf ? wlf : wlg) + ((size_t)i * CC + c) * GEGE + half * 512;
    const float* ep = sE + half * 512 * 4;

    float a0 = 0.f, a1 = 0.f, a2 = 0.f, a3 = 0.f;
    #pragma unroll 4
    for (int k = 0; k < 512; k += 4) {
        float4 wv = *(const float4*)(w + k);
        float4 e0 = *(const float4*)(ep + k * 4);
        float4 e1 = *(const float4*)(ep + k * 4 + 4);
        float4 e2 = *(const float4*)(ep + k * 4 + 8);
        float4 e3 = *(const float4*)(ep + k * 4 + 12);
        a0 = fmaf(wv.x, e0.x, a0); a1 = fmaf(wv.x, e0.y, a1);
        a2 = fmaf(wv.x, e0.z, a2); a3 = fmaf(wv.x, e0.w, a3);
        a0 = fmaf(wv.y, e1.x, a0); a1 = fmaf(wv.y, e1.y, a1);
        a2 = fmaf(wv.y, e1.z, a2); a3 = fmaf(wv.y, e1.w, a3);
        a0 = fmaf(wv.z, e2.x, a0); a1 = fmaf(wv.z, e2.y, a1);
        a2 = fmaf(wv.z, e2.z, a2); a3 = fmaf(wv.z, e2.w, a3);
        a0 = fmaf(wv.w, e3.x, a0); a1 = fmaf(wv.w, e3.y, a1);
        a2 = fmaf(wv.w, e3.z, a2); a3 = fmaf(wv.w, e3.w, a3);
    }
    *(float4*)&sR[tid * 4] = make_float4(a0, a1, a2, a3);
    __syncthreads();
    if (tid < 128) {
        float4 lo = *(const float4*)&sR[tid * 4];
        float4 hi = *(const float4*)&sR[(tid + 128) * 4];
        float bias = (isf ? blf : blg)[i * CC + c];
        float* dst = (isf ? g_HF : g_HG);
        dst[((size_t)i * BB + b0 + 0) * CC + c] = lo.x + hi.x + bias;
        dst[((size_t)i * BB + b0 + 1) * CC + c] = lo.y + hi.y + bias;
        dst[((size_t)i * BB + b0 + 2) * CC + c] = lo.z + hi.z + bias;
        dst[((size_t)i * BB + b0 + 3) * CC + c] = lo.w + hi.w + bias;
    }
}

// ---------------- K3: initial residual via lookup ----------------------------
__global__ void __launch_bounds__(256) k_init(
    const int* __restrict__ tok, const float* __restrict__ b_causal)
{
    __shared__ float sM0[VV * CC], sM1[VV * CC], sb[CC];
    int tid = threadIdx.x;
    for (int i = tid; i < VV * CC; i += 256) { sM0[i] = g_M0[i]; sM1[i] = g_M1[i]; }
    if (tid < CC) sb[tid] = b_causal[tid];
    __syncthreads();
    int b = blockIdx.y, tt0 = blockIdx.x * 64;
    const int* tb = tok + b * LL;
    float* ro = g_res0 + (size_t)b * LL * CC;
    for (int idx = tid; idx < 64 * 64; idx += 256) {
        int t = tt0 + (idx >> 6);
        int c = idx & 63;
        float r = sM1[tb[t] * CC + c] + sb[c];
        if (t > 0) r += sM0[tb[t - 1] * CC + c];
        ro[(size_t)t * CC + c] = r;
    }
}

// ---------------- K4: dilated residual layer on tensor cores -----------------
__global__ void __launch_bounds__(256, 2) k_layer_tc(
    const float* __restrict__ b_f, const float* __restrict__ b_g,
    const float* __restrict__ b_res,
    int layer, int d, int in_sel, int out_sel)
{
    extern __shared__ u32 smem_u[];
    u32* XH = smem_u;                 // 64 x 68 u32
    u32* XL = smem_u + 4352;
    u32* ZH = smem_u + 8704;          // 64 x 36 u32
    u32* ZL = smem_u + 11008;
    float* sBF = (float*)(smem_u + 13312);
    float* sBG = sBF + 64;
    float* Dsm = (float*)smem_u;      // overlays XH/XL: 128 x 68 f32
    float* SK  = (float*)ZH;          // overlays ZH/ZL: 64 x 68 f32

    int tid = threadIdx.x;
    int lane = tid & 31;
    int w = tid >> 5;
    int b = blockIdx.y;
    int tt0 = blockIdx.x * 64;

    if (tid < 64)
        sBF[tid] = b_f[layer * CC + tid] + g_HF[((size_t)layer * BB + b) * CC + tid];
    else if (tid < 128) {
        int c = tid - 64;
        sBG[c] = b_g[layer * CC + c] + g_HG[((size_t)layer * BB + b) * CC + c];
    }

    const float* rin = buf_c(in_sel) + (size_t)b * LL * CC;
    #pragma unroll
    for (int it = 0; it < 8; it++) {
        int id = it * 256 + tid;
        int t = id >> 5;
        int kq = (id & 31) * 4;
        float4 v = make_float4(0.f, 0.f, 0.f, 0.f);
        if (kq < 64) {
            int gt = tt0 + t - d;
            if (gt >= 0) v = *(const float4*)(rin + (size_t)gt * CC + kq);
        } else {
            v = *(const float4*)(rin + (size_t)(tt0 + t) * CC + (kq - 64));
        }
        u32 h0, l0, h1, l1;
        split2(v.x, v.y, h0, l0);
        split2(v.z, v.w, h1, l1);
        int o = t * 68 + (kq >> 1);
        *(uint2*)&XH[o] = make_uint2(h0, h1);
        *(uint2*)&XL[o] = make_uint2(l0, l1);
    }
    __syncthreads();

    float acc[8][4];
    #pragma unroll
    for (int j = 0; j < 8; j++)
        #pragma unroll
        for (int r = 0; r < 4; r++) acc[j][r] = 0.f;

    const uint4* WFp = (const uint4*)(g_WF + ((size_t)layer * 8 + w) * 2048);
    int tb = lane >> 2;
    #pragma unroll
    for (int s = 0; s < 8; s++) {
        uint4 Ah = WFp[s * 64 + lane];
        uint4 Al = WFp[s * 64 + 32 + lane];
        int kb = s * 8 + (lane & 3);
        #pragma unroll
        for (int j = 0; j < 8; j++) {
            int base = (j * 8 + tb) * 68 + kb;
            u32 bh0 = XH[base], bh1 = XH[base + 4];
            u32 bl0 = XL[base], bl1 = XL[base + 4];
            mma16816(acc[j], Ah.x, Ah.y, Ah.z, Ah.w, bh0, bh1);
            mma16816(acc[j], Ah.x, Ah.y, Ah.z, Ah.w, bl0, bl1);
            mma16816(acc[j], Al.x, Al.y, Al.z, Al.w, bh0, bh1);
        }
    }
    __syncthreads();

    {
        int g = lane >> 2, tq = 2 * (lane & 3);
        int m = w * 16 + g;
        #pragma unroll
        for (int j = 0; j < 8; j++) {
            int t = j * 8 + tq;
            *(float2*)&Dsm[m * 68 + t] = make_float2(acc[j][0], acc[j][1]);
            *(float2*)&Dsm[(m + 8) * 68 + t] = make_float2(acc[j][2], acc[j][3]);
        }
    }
    __syncthreads();

    #pragma unroll
    for (int it = 0; it < 8; it++) {
        int id = it * 256 + tid;
        int cp = id & 31, t = id >> 5;
        float f0 = Dsm[(2 * cp) * 68 + t] + sBF[2 * cp];
        float f1 = Dsm[(2 * cp + 1) * 68 + t] + sBF[2 * cp + 1];
        float g0 = Dsm[(2 * cp + 64) * 68 + t] + sBG[2 * cp];
        float g1 = Dsm[(2 * cp + 65) * 68 + t] + sBG[2 * cp + 1];
        float z0 = fast_tanh(f0) * fast_sigmoid(g0);
        float z1 = fast_tanh(f1) * fast_sigmoid(g1);
        u32 zh, zl; split2(z0, z1, zh, zl);
        ZH[t * 36 + cp] = zh;
        ZL[t * 36 + cp] = zl;
    }
    __syncthreads();

    int mt = w >> 1, nb = (w & 1) * 4;
    float acc2[4][4];
    #pragma unroll
    for (int j = 0; j < 4; j++)
        #pragma unroll
        for (int r = 0; r < 4; r++) acc2[j][r] = 0.f;

    const uint4* WRp = (const uint4*)(g_WR + ((size_t)layer * 4 + mt) * 1024);
    #pragma unroll
    for (int s = 0; s < 4; s++) {
        uint4 Ah = WRp[s * 64 + lane];
        uint4 Al = WRp[s * 64 + 32 + lane];
        int kb = s * 8 + (lane & 3);
        #pragma unroll
        for (int j = 0; j < 4; j++) {
            int base = ((nb + j) * 8 + tb) * 36 + kb;
            u32 bh0 = ZH[base], bh1 = ZH[base + 4];
            u32 bl0 = ZL[base], bl1 = ZL[base + 4];
            mma16816(acc2[j], Ah.x, Ah.y, Ah.z, Ah.w, bh0, bh1);
            mma16816(acc2[j], Ah.x, Ah.y, Ah.z, Ah.w, bl0, bl1);
            mma16816(acc2[j], Al.x, Al.y, Al.z, Al.w, bh0, bh1);
        }
    }
    __syncthreads();

    {
        int m2 = mt * 16 + (lane >> 2);
        #pragma unroll
        for (int j = 0; j < 4; j++) {
            int t = (nb + j) * 8 + 2 * (lane & 3);
            SK[t * 68 + m2] = acc2[j][0];
            SK[(t + 1) * 68 + m2] = acc2[j][1];
            SK[t * 68 + m2 + 8] = acc2[j][2];
            SK[(t + 1) * 68 + m2 + 8] = acc2[j][3];
        }
    }
    __syncthreads();

    const float* brp = b_res + layer * CC;
    float* rout = buf_m(out_sel) + (size_t)b * LL * CC;
    #pragma unroll
    for (int it = 0; it < 4; it++) {
        int id = it * 256 + tid;
        int t = id >> 4, cq = (id & 15) * 4;
        float4 rv = *(const float4*)(rin + (size_t)(tt0 + t) * CC + cq);
        float4 bz = *(const float4*)(brp + cq);
        float4 s4 = *(const float4*)&SK[t * 68 + cq];
        float4 o = make_float4(rv.x + s4.x + bz.x, rv.y + s4.y + bz.y,
                               rv.z + s4.z + bz.z, rv.w + s4.w + bz.w);
        *(float4*)(rout + (size_t)(tt0 + t) * CC + cq) = o;
    }
}

// ---------------- K5: head on tensor cores ------------------------------------
// Tile 64 t x 1 batch, 256 threads. GEMM1: H[128,64t]=W1*relu(resA-res0);
// relu -> split; GEMM2: out[32(30),64t]=W2*H. 2-term bf16 split throughout.
__global__ void __launch_bounds__(256, 2) k_final_tc(
    const float* __restrict__ b1, const float* __restrict__ b2,
    float* __restrict__ out)
{
    extern __shared__ u32 smem_u[];
    u32* XH = smem_u;                 // 64 x 36 u32 (S hi)
    u32* XL = smem_u + 2304;          // 64 x 36 u32
    float* Dsm = (float*)smem_u;      // overlays: 128 x 68 f32 (8704)
    u32* HH = smem_u + 8704;          // 64 x 68 u32
    u32* HL = smem_u + 13056;         // 64 x 68 u32

    int tid = threadIdx.x;
    int lane = tid & 31;
    int w = tid >> 5;
    int b = blockIdx.y;
    int tt0 = blockIdx.x * 64;
    int tb = lane >> 2;

    // ---- S = relu(resA - res0), split, [t][kpair] pitch 36 ----
    const float* rA = g_resA + (size_t)b * LL * CC;
    const float* r0 = g_res0 + (size_t)b * LL * CC;
    #pragma unroll
    for (int it = 0; it < 4; it++) {
        int id = it * 256 + tid;          // 1024 = 64t x 16 c-quads
        int t = id >> 4, cq = (id & 15) * 4;
        size_t off = (size_t)(tt0 + t) * CC + cq;
        float4 a = *(const float4*)(rA + off);
        float4 z = *(const float4*)(r0 + off);
        float s0 = fmaxf(a.x - z.x, 0.f), s1 = fmaxf(a.y - z.y, 0.f);
        float s2 = fmaxf(a.z - z.z, 0.f), s3 = fmaxf(a.w - z.w, 0.f);
        u32 h0, l0, h1, l1;
        split2(s0, s1, h0, l0);
        split2(s2, s3, h1, l1);
        int o = t * 36 + (cq >> 1);
        *(uint2*)&XH[o] = make_uint2(h0, h1);
        *(uint2*)&XL[o] = make_uint2(l0, l1);
    }
    __syncthreads();

    // ---- GEMM1: warp w owns m-rows [w*16, w*16+16), k=64 ----
    float acc[8][4];
    #pragma unroll
    for (int j = 0; j < 8; j++)
        #pragma unroll
        for (int r = 0; r < 4; r++) acc[j][r] = 0.f;

    const uint4* W1p = (const uint4*)(g_W1 + w * 1024);
    #pragma unroll
    for (int s = 0; s < 4; s++) {
        uint4 Ah = W1p[s * 64 + lane];
        uint4 Al = W1p[s * 64 + 32 + lane];
        int kb = s * 8 + (lane & 3);
        #pragma unroll
        for (int j = 0; j < 8; j++) {
            int base = (j * 8 + tb) * 36 + kb;
            u32 bh0 = XH[base], bh1 = XH[base + 4];
            u32 bl0 = XL[base], bl1 = XL[base + 4];
            mma16816(acc[j], Ah.x, Ah.y, Ah.z, Ah.w, bh0, bh1);
            mma16816(acc[j], Ah.x, Ah.y, Ah.z, Ah.w, bl0, bl1);
            mma16816(acc[j], Al.x, Al.y, Al.z, Al.w, bh0, bh1);
        }
    }
    __syncthreads();

    // ---- store D [m][t] pitch 68 ----
    {
        int g = lane >> 2, tq = 2 * (lane & 3);
        int m = w * 16 + g;
        #pragma unroll
        for (int j = 0; j < 8; j++) {
            int t = j * 8 + tq;
            *(float2*)&Dsm[m * 68 + t] = make_float2(acc[j][0], acc[j][1]);
            *(float2*)&Dsm[(m + 8) * 68 + t] = make_float2(acc[j][2], acc[j][3]);
        }
    }
    __syncthreads();

    // ---- H = relu(D + b1), split, [t][mpair] pitch 68 ----
    #pragma unroll
    for (int it = 0; it < 16; it++) {
        int id = it * 256 + tid;          // 4096 = 64t x 64 mpairs
        int mp = id & 63, t = id >> 6;
        float h0 = fmaxf(Dsm[(2 * mp) * 68 + t] + b1[2 * mp], 0.f);
        float h1 = fmaxf(Dsm[(2 * mp + 1) * 68 + t] + b1[2 * mp + 1], 0.f);
        u32 hh, hl; split2(h0, h1, hh, hl);
        HH[t * 68 + mp] = hh;
        HL[t * 68 + mp] = hl;
    }
    __syncthreads();

    // ---- GEMM2: m=32 (2 mtiles), n=64 (8 nblks); warp -> (mt, 2 nblks) ----
    int mt = w & 1;
    float acc2[2][4];
    #pragma unroll
    for (int j = 0; j < 2; j++)
        #pragma unroll
        for (int r = 0; r < 4; r++) acc2[j][r] = 0.f;

    const uint4* W2p = (const uint4*)(g_W2 + mt * 2048);
    #pragma unroll
    for (int s = 0; s < 8; s++) {
        uint4 Ah = W2p[s * 64 + lane];
        uint4 Al = W2p[s * 64 + 32 + lane];
        int kb = s * 8 + (lane & 3);
        #pragma unroll
        for (int j = 0; j < 2; j++) {
            int nblk = (w >> 1) * 2 + j;
            int base = (nblk * 8 + tb) * 68 + kb;
            u32 bh0 = HH[base], bh1 = HH[base + 4];
            u32 bl0 = HL[base], bl1 = HL[base + 4];
            mma16816(acc2[j], Ah.x, Ah.y, Ah.z, Ah.w, bh0, bh1);
            mma16816(acc2[j], Ah.x, Ah.y, Ah.z, Ah.w, bl0, bl1);
            mma16816(acc2[j], Al.x, Al.y, Al.z, Al.w, bh0, bh1);
        }
    }

    // ---- epilogue: out[o][t] = acc2 + b2 ----
    {
        int m = mt * 16 + (lane >> 2);      // 0..23 (mt=0), 16..23 (mt=1)
        #pragma unroll
        for (int j = 0; j < 2; j++) {
            int nblk = (w >> 1) * 2 + j;
            int t = tt0 + nblk * 8 + 2 * (lane & 3);
            int o1 = m, o2 = m + 8;
            *(float2*)(out + ((size_t)b * OO + o1) * LL + t) =
                make_float2(acc2[j][0] + b2[o1], acc2[j][1] + b2[o1]);
            if (o2 < OO)
                *(float2*)(out + ((size_t)b * OO + o2) * LL + t) =
                    make_float2(acc2[j][2] + b2[o2], acc2[j][3] + b2[o2]);
        }
    }
}

// ---------------- launch -----------------------------------------------------
extern "C" void kernel_launch(void* const* d_in, const int* in_sizes, int n_in,
                              void* d_out, int out_size)
{
    const int*   in_tok = (const int*)d_in[0];
    const int*   g_tok  = (const int*)d_in[1];
    const float* emb    = (const float*)d_in[2];
    const float* wc     = (const float*)d_in[3];
    const float* bc     = (const float*)d_in[4];
    const float* wf     = (const float*)d_in[5];
    const float* bf     = (const float*)d_in[6];
    const float* wg     = (const float*)d_in[7];
    const float* bg     = (const float*)d_in[8];
    const float* wlf    = (const float*)d_in[9];
    const float* blf    = (const float*)d_in[10];
    const float* wlg    = (const float*)d_in[11];
    const float* blg    = (const float*)d_in[12];
    const float* wres   = (const float*)d_in[13];
    const float* bres   = (const float*)d_in[14];
    const float* w1     = (const float*)d_in[15];
    const float* b1     = (const float*)d_in[16];
    const float* w2     = (const float*)d_in[17];
    const float* b2     = (const float*)d_in[18];
    float* out = (float*)d_out;

    const int LAYER_SMEM = 13440 * 4;   // 53760 B
    const int FINAL_SMEM = 17408 * 4;   // 69632 B
    cudaFuncSetAttribute(k_layer_tc, cudaFuncAttributeMaxDynamicSharedMemorySize, LAYER_SMEM);
    cudaFuncSetAttribute(k_final_tc, cudaFuncAttributeMaxDynamicSharedMemorySize, FINAL_SMEM);

    k_precompute_M<<<VV, 64>>>(emb, wc);
    k_prep_w<<<NDND, 256>>>(wf, wg, wres);
    k_prep_head<<<1, 256>>>(w1, w2);
    k_embg<<<BB, 256>>>(g_tok, emb);
    k_H<<<dim3(NDND, 16), 256>>>(wlf, blf, wlg, blg);
    k_init<<<dim3(LL / 64, BB), 256>>>(in_tok, bc);
    for (int i = 0; i < NDND; i++) {
        int d = 2 << i;
        int out_sel = (i % 2 == 0) ? 1 : 2;           // layer 8 -> resA
        int in_sel  = (i == 0) ? 0 : ((i % 2 == 0) ? 2 : 1);
        k_layer_tc<<<dim3(LL / 64, BB), 256, LAYER_SMEM>>>(
            bf, bg, bres, i, d, in_sel, out_sel);
    }
    k_final_tc<<<dim3(LL / 64, BB), 256, FINAL_SMEM>>>(b1, b2, out);
}

// round 6
// speedup vs baseline: 4.5182x; 1.0009x over previous
#include <cuda_runtime.h>
#include <cuda_bf16.h>
#include <math.h>

#define BB   64
#define LL   2048
#define VV   30
#define EE   128
#define GG   8
#define GEGE 1024
#define CC   64
#define FF   128
#define OO   30
#define NDND 9

#define XP4  36    // uint4 pitch per t-row, X fragments (32 slots + pad; 144 u32 ≡ 16 mod 32)
#define ZP4  20    // uint4 pitch per t-row, Z fragments (16 slots + pad; 80 u32 ≡ 16 mod 32)

typedef unsigned int u32;

// ---------------- helpers ----------------------------------------------------
__device__ __forceinline__ void mma16816(float* d, u32 a0, u32 a1, u32 a2, u32 a3,
                                         u32 b0, u32 b1) {
    asm volatile(
        "mma.sync.aligned.m16n8k16.row.col.f32.bf16.bf16.f32 "
        "{%0,%1,%2,%3}, {%4,%5,%6,%7}, {%8,%9}, {%0,%1,%2,%3};"
        : "+f"(d[0]), "+f"(d[1]), "+f"(d[2]), "+f"(d[3])
        : "r"(a0), "r"(a1), "r"(a2), "r"(a3), "r"(b0), "r"(b1));
}
__device__ __forceinline__ void split2(float x0, float x1, u32& hi, u32& lo) {
    __nv_bfloat16 h0 = __float2bfloat16_rn(x0);
    __nv_bfloat16 h1 = __float2bfloat16_rn(x1);
    float r0 = x0 - __bfloat162float(h0);
    float r1 = x1 - __bfloat162float(h1);
    __nv_bfloat162 hv; hv.x = h0; hv.y = h1;
    __nv_bfloat162 lv; lv.x = __float2bfloat16_rn(r0); lv.y = __float2bfloat16_rn(r1);
    hi = *(u32*)&hv; lo = *(u32*)&lv;
}
__device__ __forceinline__ float fast_tanh(float x) {
    float e; asm("ex2.approx.f32 %0, %1;" : "=f"(e) : "f"(x * 2.8853900817779268f));
    float r; asm("rcp.approx.f32 %0, %1;" : "=f"(r) : "f"(e + 1.0f));
    return 1.0f - 2.0f * r;
}
__device__ __forceinline__ float fast_sigmoid(float x) {
    float e; asm("ex2.approx.f32 %0, %1;" : "=f"(e) : "f"(-x * 1.4426950408889634f));
    float r; asm("rcp.approx.f32 %0, %1;" : "=f"(r) : "f"(e + 1.0f));
    return r;
}

// ---------------- scratch ----------------------------------------------------
__device__ float g_res0[(size_t)BB * LL * CC];
__device__ float g_resA[(size_t)BB * LL * CC];
__device__ float g_resB[(size_t)BB * LL * CC];
__device__ float g_embg[BB * GEGE];
__device__ float g_HF[NDND * BB * CC];
__device__ float g_HG[NDND * BB * CC];
__device__ float g_M0[VV * CC];
__device__ float g_M1[VV * CC];
__device__ u32 g_WF[NDND * 16384];   // layer GEMM1 A frags: [layer][mtile8][s8][half2][lane32][reg4]
__device__ u32 g_WR[NDND * 4096];    // layer GEMM2 A frags: [layer][mtile4][s4][half2][lane32][reg4]
__device__ u32 g_W1[8192];           // head GEMM1 A frags
__device__ u32 g_W2[4096];           // head GEMM2 A frags

__device__ __forceinline__ const float* buf_c(int sel) {
    return sel == 0 ? g_res0 : (sel == 1 ? g_resA : g_resB);
}
__device__ __forceinline__ float* buf_m(int sel) {
    return sel == 1 ? g_resA : g_resB;
}

// ---------------- K0a: fold embedding + initial conv -------------------------
__global__ void __launch_bounds__(64) k_precompute_M(
    const float* __restrict__ emb, const float* __restrict__ wc)
{
    int v = blockIdx.x, c = threadIdx.x;
    float a0 = 0.f, a1 = 0.f;
    if (v != 0) {
        for (int e = 0; e < EE; e++) {
            float x = emb[v * EE + e];
            a0 = fmaf(x, wc[(c * EE + e) * 2 + 0], a0);
            a1 = fmaf(x, wc[(c * EE + e) * 2 + 1], a1);
        }
    }
    g_M0[v * CC + c] = a0;
    g_M1[v * CC + c] = a1;
}

// ---------------- K0b: layer weights -> fragment layout -----------------------
__global__ void __launch_bounds__(256) k_prep_w(
    const float* __restrict__ wf, const float* __restrict__ wg,
    const float* __restrict__ wres)
{
    int layer = blockIdx.x;
    for (int idx = threadIdx.x; idx < 16384; idx += 256) {
        int w = idx >> 11, s = (idx >> 8) & 7, h = (idx >> 7) & 1;
        int lane = (idx >> 2) & 31, r = idx & 3;
        int m = w * 16 + (r & 1) * 8 + (lane >> 2);
        int k0 = s * 16 + ((r >> 1) & 1) * 8 + (lane & 3) * 2;
        const float* src = (m < 64) ? wf : wg;
        int cout = m & 63;
        int cin0 = k0 & 63, tap0 = k0 >> 6;
        int k1 = k0 + 1;
        int cin1 = k1 & 63, tap1 = k1 >> 6;
        float x0 = src[(((size_t)layer * 64 + cout) * 64 + cin0) * 2 + tap0];
        float x1 = src[(((size_t)layer * 64 + cout) * 64 + cin1) * 2 + tap1];
        u32 hi, lo; split2(x0, x1, hi, lo);
        g_WF[(size_t)layer * 16384 + idx] = h ? lo : hi;
    }
    for (int idx = threadIdx.x; idx < 4096; idx += 256) {
        int mt = idx >> 10, s = (idx >> 8) & 3, h = (idx >> 7) & 1;
        int lane = (idx >> 2) & 31, r = idx & 3;
        int m = mt * 16 + (r & 1) * 8 + (lane >> 2);
        int k0 = s * 16 + ((r >> 1) & 1) * 8 + (lane & 3) * 2;
        float x0 = wres[((size_t)layer * 64 + m) * 64 + k0];
        float x1 = wres[((size_t)layer * 64 + m) * 64 + k0 + 1];
        u32 hi, lo; split2(x0, x1, hi, lo);
        g_WR[(size_t)layer * 4096 + idx] = h ? lo : hi;
    }
}

// ---------------- K0c: head weights -> fragment layout ------------------------
__global__ void __launch_bounds__(256) k_prep_head(
    const float* __restrict__ w1, const float* __restrict__ w2)
{
    for (int idx = threadIdx.x; idx < 8192; idx += 256) {
        int w = idx >> 10, s = (idx >> 8) & 3, h = (idx >> 7) & 1;
        int lane = (idx >> 2) & 31, r = idx & 3;
        int m = w * 16 + (r & 1) * 8 + (lane >> 2);
        int k0 = s * 16 + ((r >> 1) & 1) * 8 + (lane & 3) * 2;
        float x0 = w1[m * 64 + k0];
        float x1 = w1[m * 64 + k0 + 1];
        u32 hi, lo; split2(x0, x1, hi, lo);
        g_W1[idx] = h ? lo : hi;
    }
    for (int idx = threadIdx.x; idx < 4096; idx += 256) {
        int mt = idx >> 11, s = (idx >> 8) & 7, h = (idx >> 7) & 1;
        int lane = (idx >> 2) & 31, r = idx & 3;
        int m = mt * 16 + (r & 1) * 8 + (lane >> 2);
        int k0 = s * 16 + ((r >> 1) & 1) * 8 + (lane & 3) * 2;
        float x0 = (m < OO) ? w2[m * 128 + k0] : 0.f;
        float x1 = (m < OO) ? w2[m * 128 + k0 + 1] : 0.f;
        u32 hi, lo; split2(x0, x1, hi, lo);
        g_W2[idx] = h ? lo : hi;
    }
}

// ---------------- K1: global embedding ---------------------------------------
__global__ void __launch_bounds__(256) k_embg(
    const int* __restrict__ gin, const float* __restrict__ emb)
{
    int b = blockIdx.x;
    for (int j = threadIdx.x; j < GEGE; j += 256) {
        int g = j >> 7, e = j & 127;
        int tok = gin[b * GG + g];
        g_embg[b * GEGE + j] = (tok == 0) ? 0.f : emb[tok * EE + e];
    }
}

// ---------------- K2: conditioning vectors -----------------------------------
__global__ void __launch_bounds__(256) k_H(
    const float* __restrict__ wlf, const float* __restrict__ blf,
    const float* __restrict__ wlg, const float* __restrict__ blg)
{
    __shared__ float sE[GEGE * 4];
    __shared__ float sR[256 * 4];
    int i = blockIdx.x;
    int b0 = blockIdx.y * 4;
    int tid = threadIdx.x;

    for (int idx = tid; idx < GEGE * 4; idx += 256) {
        int k = idx >> 2, bj = idx & 3;
        sE[idx] = g_embg[(size_t)(b0 + bj) * GEGE + k];
    }
    __syncthreads();

    int row = tid & 127;
    int half = tid >> 7;
    int c = row & 63;
    bool isf = row < 64;
    const float* w = (isf ? wlf : wlg) + ((size_t)i * CC + c) * GEGE + half * 512;
    const float* ep = sE + half * 512 * 4;

    float a0 = 0.f, a1 = 0.f, a2 = 0.f, a3 = 0.f;
    #pragma unroll 4
    for (int k = 0; k < 512; k += 4) {
        float4 wv = *(const float4*)(w + k);
        float4 e0 = *(const float4*)(ep + k * 4);
        float4 e1 = *(const float4*)(ep + k * 4 + 4);
        float4 e2 = *(const float4*)(ep + k * 4 + 8);
        float4 e3 = *(const float4*)(ep + k * 4 + 12);
        a0 = fmaf(wv.x, e0.x, a0); a1 = fmaf(wv.x, e0.y, a1);
        a2 = fmaf(wv.x, e0.z, a2); a3 = fmaf(wv.x, e0.w, a3);
        a0 = fmaf(wv.y, e1.x, a0); a1 = fmaf(wv.y, e1.y, a1);
        a2 = fmaf(wv.y, e1.z, a2); a3 = fmaf(wv.y, e1.w, a3);
        a0 = fmaf(wv.z, e2.x, a0); a1 = fmaf(wv.z, e2.y, a1);
        a2 = fmaf(wv.z, e2.z, a2); a3 = fmaf(wv.z, e2.w, a3);
        a0 = fmaf(wv.w, e3.x, a0); a1 = fmaf(wv.w, e3.y, a1);
        a2 = fmaf(wv.w, e3.z, a2); a3 = fmaf(wv.w, e3.w, a3);
    }
    *(float4*)&sR[tid * 4] = make_float4(a0, a1, a2, a3);
    __syncthreads();
    if (tid < 128) {
        float4 lo = *(const float4*)&sR[tid * 4];
        float4 hi = *(const float4*)&sR[(tid + 128) * 4];
        float bias = (isf ? blf : blg)[i * CC + c];
        float* dst = (isf ? g_HF : g_HG);
        dst[((size_t)i * BB + b0 + 0) * CC + c] = lo.x + hi.x + bias;
        dst[((size_t)i * BB + b0 + 1) * CC + c] = lo.y + hi.y + bias;
        dst[((size_t)i * BB + b0 + 2) * CC + c] = lo.z + hi.z + bias;
        dst[((size_t)i * BB + b0 + 3) * CC + c] = lo.w + hi.w + bias;
    }
}

// ---------------- K3: initial residual via lookup ----------------------------
__global__ void __launch_bounds__(256) k_init(
    const int* __restrict__ tok, const float* __restrict__ b_causal)
{
    __shared__ float sM0[VV * CC], sM1[VV * CC], sb[CC];
    int tid = threadIdx.x;
    for (int i = tid; i < VV * CC; i += 256) { sM0[i] = g_M0[i]; sM1[i] = g_M1[i]; }
    if (tid < CC) sb[tid] = b_causal[tid];
    __syncthreads();
    int b = blockIdx.y, tt0 = blockIdx.x * 64;
    const int* tb = tok + b * LL;
    float* ro = g_res0 + (size_t)b * LL * CC;
    for (int idx = tid; idx < 64 * 64; idx += 256) {
        int t = tt0 + (idx >> 6);
        int c = idx & 63;
        float r = sM1[tb[t] * CC + c] + sb[c];
        if (t > 0) r += sM0[tb[t - 1] * CC + c];
        ro[(size_t)t * CC + c] = r;
    }
}

// ---------------- K4: dilated residual layer (fragment-interleaved) ----------
// Tile 64t x 64c. 8 warps = 4 m-groups x 2 n-groups (GEMM1).
// X/Z stored as interleaved uint4 B-fragments: (hi_q, hi_{q+4}, lo_q, lo_{q+4}).
__global__ void __launch_bounds__(256, 2) k_layer_tc(
    const float* __restrict__ b_f, const float* __restrict__ b_g,
    const float* __restrict__ b_res,
    int layer, int d, int in_sel, int out_sel)
{
    extern __shared__ u32 smem_u[];
    uint4* Xf = (uint4*)smem_u;                    // 64 x XP4 uint4 (9216 u32)
    float* Dsm = (float*)smem_u;                   // overlay: 128 x 68 f32 (8704)
    uint4* Zf = (uint4*)(smem_u + 9216);           // 64 x ZP4 uint4 (5120 u32)
    float* SK  = (float*)(smem_u + 9216);          // overlay: 64 x 68 f32 (4352)
    float* sBF = (float*)(smem_u + 14336);         // 64
    float* sBG = sBF + 64;                         // 64

    int tid = threadIdx.x;
    int lane = tid & 31;
    int w = tid >> 5;
    int b = blockIdx.y;
    int tt0 = blockIdx.x * 64;
    int r = lane & 3, tb = lane >> 2;

    if (tid < 64)
        sBF[tid] = b_f[layer * CC + tid] + g_HF[((size_t)layer * BB + b) * CC + tid];
    else if (tid < 128) {
        int c = tid - 64;
        sBG[c] = b_g[layer * CC + c] + g_HG[((size_t)layer * BB + b) * CC + c];
    }

    // ---- build X fragments: slot (t, s*4+r) -> kpairs q=s*8+r and q+4 ----
    const float* rin = buf_c(in_sel) + (size_t)b * LL * CC;
    #pragma unroll
    for (int it = 0; it < 8; it++) {
        int id = it * 256 + tid;          // 2048 slots
        int t = id >> 5;
        int sl = id & 31;
        int q = (sl >> 2) * 8 + (sl & 3);
        int k1 = 2 * q, k2 = 2 * q + 8;   // never straddle the prev/cur boundary
        float2 v1 = make_float2(0.f, 0.f), v2 = make_float2(0.f, 0.f);
        int gtp = tt0 + t - d;
        if (k1 < 64) { if (gtp >= 0) v1 = *(const float2*)(rin + (size_t)gtp * CC + k1); }
        else v1 = *(const float2*)(rin + (size_t)(tt0 + t) * CC + (k1 - 64));
        if (k2 < 64) { if (gtp >= 0) v2 = *(const float2*)(rin + (size_t)gtp * CC + k2); }
        else v2 = *(const float2*)(rin + (size_t)(tt0 + t) * CC + (k2 - 64));
        u32 h1, l1, h2, l2;
        split2(v1.x, v1.y, h1, l1);
        split2(v2.x, v2.y, h2, l2);
        Xf[t * XP4 + sl] = make_uint4(h1, h2, l1, l2);
    }
    __syncthreads();

    // ---- GEMM1: warp = (mg = w&3 -> 32 m-rows, ng = w>>2 -> 32 t) ----
    int mg = w & 3, ng = w >> 2;
    float acc[2][4][4];
    #pragma unroll
    for (int mi = 0; mi < 2; mi++)
        #pragma unroll
        for (int j = 0; j < 4; j++)
            #pragma unroll
            for (int rr = 0; rr < 4; rr++) acc[mi][j][rr] = 0.f;

    const uint4* WFp = (const uint4*)(g_WF + (size_t)layer * 16384) + (mg * 2) * 512;
    #pragma unroll
    for (int s = 0; s < 8; s++) {
        uint4 B0 = Xf[(ng * 32 + 0 + tb) * XP4 + s * 4 + r];
        uint4 B1 = Xf[(ng * 32 + 8 + tb) * XP4 + s * 4 + r];
        uint4 B2 = Xf[(ng * 32 + 16 + tb) * XP4 + s * 4 + r];
        uint4 B3 = Xf[(ng * 32 + 24 + tb) * XP4 + s * 4 + r];
        #pragma unroll
        for (int mi = 0; mi < 2; mi++) {
            uint4 Ah = WFp[mi * 512 + s * 64 + lane];
            uint4 Al = WFp[mi * 512 + s * 64 + 32 + lane];
            mma16816(acc[mi][0], Ah.x, Ah.y, Ah.z, Ah.w, B0.x, B0.y);
            mma16816(acc[mi][0], Ah.x, Ah.y, Ah.z, Ah.w, B0.z, B0.w);
            mma16816(acc[mi][0], Al.x, Al.y, Al.z, Al.w, B0.x, B0.y);
            mma16816(acc[mi][1], Ah.x, Ah.y, Ah.z, Ah.w, B1.x, B1.y);
            mma16816(acc[mi][1], Ah.x, Ah.y, Ah.z, Ah.w, B1.z, B1.w);
            mma16816(acc[mi][1], Al.x, Al.y, Al.z, Al.w, B1.x, B1.y);
            mma16816(acc[mi][2], Ah.x, Ah.y, Ah.z, Ah.w, B2.x, B2.y);
            mma16816(acc[mi][2], Ah.x, Ah.y, Ah.z, Ah.w, B2.z, B2.w);
            mma16816(acc[mi][2], Al.x, Al.y, Al.z, Al.w, B2.x, B2.y);
            mma16816(acc[mi][3], Ah.x, Ah.y, Ah.z, Ah.w, B3.x, B3.y);
            mma16816(acc[mi][3], Ah.x, Ah.y, Ah.z, Ah.w, B3.z, B3.w);
            mma16816(acc[mi][3], Al.x, Al.y, Al.z, Al.w, B3.x, B3.y);
        }
    }
    __syncthreads();   // done reading Xf

    // ---- store D fragments: Dsm[m][t], pitch 68 ----
    {
        int gr = lane >> 2, tq = 2 * (lane & 3);
        #pragma unroll
        for (int mi = 0; mi < 2; mi++)
            #pragma unroll
            for (int j = 0; j < 4; j++) {
                int m = mg * 32 + mi * 16 + gr;
                int t = ng * 32 + j * 8 + tq;
                *(float2*)&Dsm[m * 68 + t] = make_float2(acc[mi][j][0], acc[mi][j][1]);
                *(float2*)&Dsm[(m + 8) * 68 + t] = make_float2(acc[mi][j][2], acc[mi][j][3]);
            }
    }
    __syncthreads();

    // ---- gated activation -> Z fragments ----
    #pragma unroll
    for (int it = 0; it < 4; it++) {
        int id = it * 256 + tid;          // 1024 slots
        int t = id >> 4;
        int sl = id & 15;
        int q = (sl >> 2) * 8 + (sl & 3);
        int c1 = 2 * q, c2 = 2 * q + 8;
        float f0 = Dsm[c1 * 68 + t] + sBF[c1];
        float f1 = Dsm[(c1 + 1) * 68 + t] + sBF[c1 + 1];
        float f2 = Dsm[c2 * 68 + t] + sBF[c2];
        float f3 = Dsm[(c2 + 1) * 68 + t] + sBF[c2 + 1];
        float g0 = Dsm[(c1 + 64) * 68 + t] + sBG[c1];
        float g1 = Dsm[(c1 + 65) * 68 + t] + sBG[c1 + 1];
        float g2 = Dsm[(c2 + 64) * 68 + t] + sBG[c2];
        float g3 = Dsm[(c2 + 65) * 68 + t] + sBG[c2 + 1];
        float z0 = fast_tanh(f0) * fast_sigmoid(g0);
        float z1 = fast_tanh(f1) * fast_sigmoid(g1);
        float z2 = fast_tanh(f2) * fast_sigmoid(g2);
        float z3 = fast_tanh(f3) * fast_sigmoid(g3);
        u32 h1, l1, h2, l2;
        split2(z0, z1, h1, l1);
        split2(z2, z3, h2, l2);
        Zf[t * ZP4 + sl] = make_uint4(h1, h2, l1, l2);
    }
    __syncthreads();

    // ---- GEMM2: warp = (mg2 = w&1 -> 32 m, ng2 = w>>1 -> 16 t) ----
    int mg2 = w & 1, ng2 = w >> 1;
    float acc2[2][2][4];
    #pragma unroll
    for (int mi = 0; mi < 2; mi++)
        #pragma unroll
        for (int j = 0; j < 2; j++)
            #pragma unroll
            for (int rr = 0; rr < 4; rr++) acc2[mi][j][rr] = 0.f;

    const uint4* WRp = (const uint4*)(g_WR + (size_t)layer * 4096) + (mg2 * 2) * 256;
    #pragma unroll
    for (int s = 0; s < 4; s++) {
        uint4 B0 = Zf[(ng2 * 16 + 0 + tb) * ZP4 + s * 4 + r];
        uint4 B1 = Zf[(ng2 * 16 + 8 + tb) * ZP4 + s * 4 + r];
        #pragma unroll
        for (int mi = 0; mi < 2; mi++) {
            uint4 Ah = WRp[mi * 256 + s * 64 + lane];
            uint4 Al = WRp[mi * 256 + s * 64 + 32 + lane];
            mma16816(acc2[mi][0], Ah.x, Ah.y, Ah.z, Ah.w, B0.x, B0.y);
            mma16816(acc2[mi][0], Ah.x, Ah.y, Ah.z, Ah.w, B0.z, B0.w);
            mma16816(acc2[mi][0], Al.x, Al.y, Al.z, Al.w, B0.x, B0.y);
            mma16816(acc2[mi][1], Ah.x, Ah.y, Ah.z, Ah.w, B1.x, B1.y);
            mma16816(acc2[mi][1], Ah.x, Ah.y, Ah.z, Ah.w, B1.z, B1.w);
            mma16816(acc2[mi][1], Al.x, Al.y, Al.z, Al.w, B1.x, B1.y);
        }
    }
    __syncthreads();   // done reading Zf

    // ---- store skip fragments: SK[t][m], pitch 68 ----
    {
        int gr = lane >> 2, tq = 2 * (lane & 3);
        #pragma unroll
        for (int mi = 0; mi < 2; mi++)
            #pragma unroll
            for (int j = 0; j < 2; j++) {
                int m = mg2 * 32 + mi * 16 + gr;
                int t = ng2 * 16 + j * 8 + tq;
                SK[t * 68 + m] = acc2[mi][j][0];
                SK[(t + 1) * 68 + m] = acc2[mi][j][1];
                SK[t * 68 + m + 8] = acc2[mi][j][2];
                SK[(t + 1) * 68 + m + 8] = acc2[mi][j][3];
            }
    }
    __syncthreads();

    // ---- epilogue: res_out = res_in + skip + b_res ----
    const float* brp = b_res + layer * CC;
    float* rout = buf_m(out_sel) + (size_t)b * LL * CC;
    #pragma unroll
    for (int it = 0; it < 4; it++) {
        int id = it * 256 + tid;
        int t = id >> 4, cq = (id & 15) * 4;
        float4 rv = *(const float4*)(rin + (size_t)(tt0 + t) * CC + cq);
        float4 bz = *(const float4*)(brp + cq);
        float4 s4 = *(const float4*)&SK[t * 68 + cq];
        float4 o = make_float4(rv.x + s4.x + bz.x, rv.y + s4.y + bz.y,
                               rv.z + s4.z + bz.z, rv.w + s4.w + bz.w);
        *(float4*)(rout + (size_t)(tt0 + t) * CC + cq) = o;
    }
}

// ---------------- K5: head on tensor cores ------------------------------------
__global__ void __launch_bounds__(256, 2) k_final_tc(
    const float* __restrict__ b1, const float* __restrict__ b2,
    float* __restrict__ out)
{
    extern __shared__ u32 smem_u[];
    u32* XH = smem_u;                 // 64 x 36 u32
    u32* XL = smem_u + 2304;
    float* Dsm = (float*)smem_u;      // overlay: 128 x 68 f32
    u32* HH = smem_u + 8704;          // 64 x 68 u32
    u32* HL = smem_u + 13056;

    int tid = threadIdx.x;
    int lane = tid & 31;
    int w = tid >> 5;
    int b = blockIdx.y;
    int tt0 = blockIdx.x * 64;
    int tb = lane >> 2;

    const float* rA = g_resA + (size_t)b * LL * CC;
    const float* r0 = g_res0 + (size_t)b * LL * CC;
    #pragma unroll
    for (int it = 0; it < 4; it++) {
        int id = it * 256 + tid;
        int t = id >> 4, cq = (id & 15) * 4;
        size_t off = (size_t)(tt0 + t) * CC + cq;
        float4 a = *(const float4*)(rA + off);
        float4 z = *(const float4*)(r0 + off);
        float s0 = fmaxf(a.x - z.x, 0.f), s1 = fmaxf(a.y - z.y, 0.f);
        float s2 = fmaxf(a.z - z.z, 0.f), s3 = fmaxf(a.w - z.w, 0.f);
        u32 h0, l0, h1, l1;
        split2(s0, s1, h0, l0);
        split2(s2, s3, h1, l1);
        int o = t * 36 + (cq >> 1);
        *(uint2*)&XH[o] = make_uint2(h0, h1);
        *(uint2*)&XL[o] = make_uint2(l0, l1);
    }
    __syncthreads();

    float acc[8][4];
    #pragma unroll
    for (int j = 0; j < 8; j++)
        #pragma unroll
        for (int rr = 0; rr < 4; rr++) acc[j][rr] = 0.f;

    const uint4* W1p = (const uint4*)(g_W1 + w * 1024);
    #pragma unroll
    for (int s = 0; s < 4; s++) {
        uint4 Ah = W1p[s * 64 + lane];
        uint4 Al = W1p[s * 64 + 32 + lane];
        int kb = s * 8 + (lane & 3);
        #pragma unroll
        for (int j = 0; j < 8; j++) {
            int base = (j * 8 + tb) * 36 + kb;
            u32 bh0 = XH[base], bh1 = XH[base + 4];
            u32 bl0 = XL[base], bl1 = XL[base + 4];
            mma16816(acc[j], Ah.x, Ah.y, Ah.z, Ah.w, bh0, bh1);
            mma16816(acc[j], Ah.x, Ah.y, Ah.z, Ah.w, bl0, bl1);
            mma16816(acc[j], Al.x, Al.y, Al.z, Al.w, bh0, bh1);
        }
    }
    __syncthreads();

    {
        int g = lane >> 2, tq = 2 * (lane & 3);
        int m = w * 16 + g;
        #pragma unroll
        for (int j = 0; j < 8; j++) {
            int t = j * 8 + tq;
            *(float2*)&Dsm[m * 68 + t] = make_float2(acc[j][0], acc[j][1]);
            *(float2*)&Dsm[(m + 8) * 68 + t] = make_float2(acc[j][2], acc[j][3]);
        }
    }
    __syncthreads();

    #pragma unroll
    for (int it = 0; it < 16; it++) {
        int id = it * 256 + tid;
        int mp = id & 63, t = id >> 6;
        float h0 = fmaxf(Dsm[(2 * mp) * 68 + t] + b1[2 * mp], 0.f);
        float h1 = fmaxf(Dsm[(2 * mp + 1) * 68 + t] + b1[2 * mp + 1], 0.f);
        u32 hh, hl; split2(h0, h1, hh, hl);
        HH[t * 68 + mp] = hh;
        HL[t * 68 + mp] = hl;
    }
    __syncthreads();

    int mt = w & 1;
    float acc2[2][4];
    #pragma unroll
    for (int j = 0; j < 2; j++)
        #pragma unroll
        for (int rr = 0; rr < 4; rr++) acc2[j][rr] = 0.f;

    const uint4* W2p = (const uint4*)(g_W2 + mt * 2048);
    #pragma unroll
    for (int s = 0; s < 8; s++) {
        uint4 Ah = W2p[s * 64 + lane];
        uint4 Al = W2p[s * 64 + 32 + lane];
        int kb = s * 8 + (lane & 3);
        #pragma unroll
        for (int j = 0; j < 2; j++) {
            int nblk = (w >> 1) * 2 + j;
            int base = (nblk * 8 + tb) * 68 + kb;
            u32 bh0 = HH[base], bh1 = HH[base + 4];
            u32 bl0 = HL[base], bl1 = HL[base + 4];
            mma16816(acc2[j], Ah.x, Ah.y, Ah.z, Ah.w, bh0, bh1);
            mma16816(acc2[j], Ah.x, Ah.y, Ah.z, Ah.w, bl0, bl1);
            mma16816(acc2[j], Al.x, Al.y, Al.z, Al.w, bh0, bh1);
        }
    }

    {
        int m = mt * 16 + (lane >> 2);
        #pragma unroll
        for (int j = 0; j < 2; j++) {
            int nblk = (w >> 1) * 2 + j;
            int t = tt0 + nblk * 8 + 2 * (lane & 3);
            int o1 = m, o2 = m + 8;
            *(float2*)(out + ((size_t)b * OO + o1) * LL + t) =
                make_float2(acc2[j][0] + b2[o1], acc2[j][1] + b2[o1]);
            if (o2 < OO)
                *(float2*)(out + ((size_t)b * OO + o2) * LL + t) =
                    make_float2(acc2[j][2] + b2[o2], acc2[j][3] + b2[o2]);
        }
    }
}

// ---------------- launch -----------------------------------------------------
extern "C" void kernel_launch(void* const* d_in, const int* in_sizes, int n_in,
                              void* d_out, int out_size)
{
    const int*   in_tok = (const int*)d_in[0];
    const int*   g_tok  = (const int*)d_in[1];
    const float* emb    = (const float*)d_in[2];
    const float* wc     = (const float*)d_in[3];
    const float* bc     = (const float*)d_in[4];
    const float* wf     = (const float*)d_in[5];
    const float* bf     = (const float*)d_in[6];
    const float* wg     = (const float*)d_in[7];
    const float* bg     = (const float*)d_in[8];
    const float* wlf    = (const float*)d_in[9];
    const float* blf    = (const float*)d_in[10];
    const float* wlg    = (const float*)d_in[11];
    const float* blg    = (const float*)d_in[12];
    const float* wres   = (const float*)d_in[13];
    const float* bres   = (const float*)d_in[14];
    const float* w1     = (const float*)d_in[15];
    const float* b1     = (const float*)d_in[16];
    const float* w2     = (const float*)d_in[17];
    const float* b2     = (const float*)d_in[18];
    float* out = (float*)d_out;

    const int LAYER_SMEM = 14464 * 4;   // 57856 B
    const int FINAL_SMEM = 17408 * 4;   // 69632 B
    cudaFuncSetAttribute(k_layer_tc, cudaFuncAttributeMaxDynamicSharedMemorySize, LAYER_SMEM);
    cudaFuncSetAttribute(k_final_tc, cudaFuncAttributeMaxDynamicSharedMemorySize, FINAL_SMEM);

    k_precompute_M<<<VV, 64>>>(emb, wc);
    k_prep_w<<<NDND, 256>>>(wf, wg, wres);
    k_prep_head<<<1, 256>>>(w1, w2);
    k_embg<<<BB, 256>>>(g_tok, emb);
    k_H<<<dim3(NDND, 16), 256>>>(wlf, blf, wlg, blg);
    k_init<<<dim3(LL / 64, BB), 256>>>(in_tok, bc);
    for (int i = 0; i < NDND; i++) {
        int d = 2 << i;
        int out_sel = (i % 2 == 0) ? 1 : 2;           // layer 8 -> resA
        int in_sel  = (i == 0) ? 0 : ((i % 2 == 0) ? 2 : 1);
        k_layer_tc<<<dim3(LL / 64, BB), 256, LAYER_SMEM>>>(
            bf, bg, bres, i, d, in_sel, out_sel);
    }
    k_final_tc<<<dim3(LL / 64, BB), 256, FINAL_SMEM>>>(b1, b2, out);
}

// round 7
// speedup vs baseline: 4.6177x; 1.0220x over previous
#include <cuda_runtime.h>
#include <cuda_bf16.h>
#include <math.h>

#define BB   64
#define LL   2048
#define VV   30
#define EE   128
#define GG   8
#define GEGE 1024
#define CC   64
#define FF   128
#define OO   30
#define NDND 9

#define XP4  36    // uint4 pitch per t-row, X fragments
#define ZP4  20    // uint4 pitch per t-row, Z fragments

typedef unsigned int u32;

// ---------------- helpers ----------------------------------------------------
__device__ __forceinline__ void mma16816(float* d, u32 a0, u32 a1, u32 a2, u32 a3,
                                         u32 b0, u32 b1) {
    asm volatile(
        "mma.sync.aligned.m16n8k16.row.col.f32.bf16.bf16.f32 "
        "{%0,%1,%2,%3}, {%4,%5,%6,%7}, {%8,%9}, {%0,%1,%2,%3};"
        : "+f"(d[0]), "+f"(d[1]), "+f"(d[2]), "+f"(d[3])
        : "r"(a0), "r"(a1), "r"(a2), "r"(a3), "r"(b0), "r"(b1));
}
__device__ __forceinline__ void split2(float x0, float x1, u32& hi, u32& lo) {
    __nv_bfloat16 h0 = __float2bfloat16_rn(x0);
    __nv_bfloat16 h1 = __float2bfloat16_rn(x1);
    float r0 = x0 - __bfloat162float(h0);
    float r1 = x1 - __bfloat162float(h1);
    __nv_bfloat162 hv; hv.x = h0; hv.y = h1;
    __nv_bfloat162 lv; lv.x = __float2bfloat16_rn(r0); lv.y = __float2bfloat16_rn(r1);
    hi = *(u32*)&hv; lo = *(u32*)&lv;
}
__device__ __forceinline__ float fast_tanh(float x) {
    float e; asm("ex2.approx.f32 %0, %1;" : "=f"(e) : "f"(x * 2.8853900817779268f));
    float r; asm("rcp.approx.f32 %0, %1;" : "=f"(r) : "f"(e + 1.0f));
    return 1.0f - 2.0f * r;
}
__device__ __forceinline__ float fast_sigmoid(float x) {
    float e; asm("ex2.approx.f32 %0, %1;" : "=f"(e) : "f"(-x * 1.4426950408889634f));
    float r; asm("rcp.approx.f32 %0, %1;" : "=f"(r) : "f"(e + 1.0f));
    return r;
}

// ---------------- scratch ----------------------------------------------------
__device__ float g_res0[(size_t)BB * LL * CC];
__device__ float g_resA[(size_t)BB * LL * CC];
__device__ float g_resB[(size_t)BB * LL * CC];
__device__ float g_embg[BB * GEGE];
__device__ float g_HF[NDND * BB * CC];
__device__ float g_HG[NDND * BB * CC];
__device__ float g_M0[VV * CC];
__device__ float g_M1[VV * CC];
__device__ u32 g_WF[NDND * 16384];
__device__ u32 g_WR[NDND * 4096];
__device__ u32 g_W1[8192];
__device__ u32 g_W2[4096];

__device__ __forceinline__ const float* buf_c(int sel) {
    return sel == 0 ? g_res0 : (sel == 1 ? g_resA : g_resB);
}
__device__ __forceinline__ float* buf_m(int sel) {
    return sel == 1 ? g_resA : g_resB;
}

// ---------------- K0a ---------------------------------------------------------
__global__ void __launch_bounds__(64) k_precompute_M(
    const float* __restrict__ emb, const float* __restrict__ wc)
{
    int v = blockIdx.x, c = threadIdx.x;
    float a0 = 0.f, a1 = 0.f;
    if (v != 0) {
        for (int e = 0; e < EE; e++) {
            float x = emb[v * EE + e];
            a0 = fmaf(x, wc[(c * EE + e) * 2 + 0], a0);
            a1 = fmaf(x, wc[(c * EE + e) * 2 + 1], a1);
        }
    }
    g_M0[v * CC + c] = a0;
    g_M1[v * CC + c] = a1;
}

// ---------------- K0b ---------------------------------------------------------
__global__ void __launch_bounds__(256) k_prep_w(
    const float* __restrict__ wf, const float* __restrict__ wg,
    const float* __restrict__ wres)
{
    int layer = blockIdx.x;
    for (int idx = threadIdx.x; idx < 16384; idx += 256) {
        int w = idx >> 11, s = (idx >> 8) & 7, h = (idx >> 7) & 1;
        int lane = (idx >> 2) & 31, r = idx & 3;
        int m = w * 16 + (r & 1) * 8 + (lane >> 2);
        int k0 = s * 16 + ((r >> 1) & 1) * 8 + (lane & 3) * 2;
        const float* src = (m < 64) ? wf : wg;
        int cout = m & 63;
        int cin0 = k0 & 63, tap0 = k0 >> 6;
        int k1 = k0 + 1;
        int cin1 = k1 & 63, tap1 = k1 >> 6;
        float x0 = src[(((size_t)layer * 64 + cout) * 64 + cin0) * 2 + tap0];
        float x1 = src[(((size_t)layer * 64 + cout) * 64 + cin1) * 2 + tap1];
        u32 hi, lo; split2(x0, x1, hi, lo);
        g_WF[(size_t)layer * 16384 + idx] = h ? lo : hi;
    }
    for (int idx = threadIdx.x; idx < 4096; idx += 256) {
        int mt = idx >> 10, s = (idx >> 8) & 3, h = (idx >> 7) & 1;
        int lane = (idx >> 2) & 31, r = idx & 3;
        int m = mt * 16 + (r & 1) * 8 + (lane >> 2);
        int k0 = s * 16 + ((r >> 1) & 1) * 8 + (lane & 3) * 2;
        float x0 = wres[((size_t)layer * 64 + m) * 64 + k0];
        float x1 = wres[((size_t)layer * 64 + m) * 64 + k0 + 1];
        u32 hi, lo; split2(x0, x1, hi, lo);
        g_WR[(size_t)layer * 4096 + idx] = h ? lo : hi;
    }
}

// ---------------- K0c ---------------------------------------------------------
__global__ void __launch_bounds__(256) k_prep_head(
    const float* __restrict__ w1, const float* __restrict__ w2)
{
    for (int idx = threadIdx.x; idx < 8192; idx += 256) {
        int w = idx >> 10, s = (idx >> 8) & 3, h = (idx >> 7) & 1;
        int lane = (idx >> 2) & 31, r = idx & 3;
        int m = w * 16 + (r & 1) * 8 + (lane >> 2);
        int k0 = s * 16 + ((r >> 1) & 1) * 8 + (lane & 3) * 2;
        float x0 = w1[m * 64 + k0];
        float x1 = w1[m * 64 + k0 + 1];
        u32 hi, lo; split2(x0, x1, hi, lo);
        g_W1[idx] = h ? lo : hi;
    }
    for (int idx = threadIdx.x; idx < 4096; idx += 256) {
        int mt = idx >> 11, s = (idx >> 8) & 7, h = (idx >> 7) & 1;
        int lane = (idx >> 2) & 31, r = idx & 3;
        int m = mt * 16 + (r & 1) * 8 + (lane >> 2);
        int k0 = s * 16 + ((r >> 1) & 1) * 8 + (lane & 3) * 2;
        float x0 = (m < OO) ? w2[m * 128 + k0] : 0.f;
        float x1 = (m < OO) ? w2[m * 128 + k0 + 1] : 0.f;
        u32 hi, lo; split2(x0, x1, hi, lo);
        g_W2[idx] = h ? lo : hi;
    }
}

// ---------------- K1 -----------------------------------------------------------
__global__ void __launch_bounds__(256) k_embg(
    const int* __restrict__ gin, const float* __restrict__ emb)
{
    int b = blockIdx.x;
    for (int j = threadIdx.x; j < GEGE; j += 256) {
        int g = j >> 7, e = j & 127;
        int tok = gin[b * GG + g];
        g_embg[b * GEGE + j] = (tok == 0) ? 0.f : emb[tok * EE + e];
    }
}

// ---------------- K2 -----------------------------------------------------------
__global__ void __launch_bounds__(256) k_H(
    const float* __restrict__ wlf, const float* __restrict__ blf,
    const float* __restrict__ wlg, const float* __restrict__ blg)
{
    __shared__ float sE[GEGE * 4];
    __shared__ float sR[256 * 4];
    int i = blockIdx.x;
    int b0 = blockIdx.y * 4;
    int tid = threadIdx.x;

    for (int idx = tid; idx < GEGE * 4; idx += 256) {
        int k = idx >> 2, bj = idx & 3;
        sE[idx] = g_embg[(size_t)(b0 + bj) * GEGE + k];
    }
    __syncthreads();

    int row = tid & 127;
    int half = tid >> 7;
    int c = row & 63;
    bool isf = row < 64;
    const float* w = (isf ? wlf : wlg) + ((size_t)i * CC + c) * GEGE + half * 512;
    const float* ep = sE + half * 512 * 4;

    float a0 = 0.f, a1 = 0.f, a2 = 0.f, a3 = 0.f;
    #pragma unroll 4
    for (int k = 0; k < 512; k += 4) {
        float4 wv = *(const float4*)(w + k);
        float4 e0 = *(const float4*)(ep + k * 4);
        float4 e1 = *(const float4*)(ep + k * 4 + 4);
        float4 e2 = *(const float4*)(ep + k * 4 + 8);
        float4 e3 = *(const float4*)(ep + k * 4 + 12);
        a0 = fmaf(wv.x, e0.x, a0); a1 = fmaf(wv.x, e0.y, a1);
        a2 = fmaf(wv.x, e0.z, a2); a3 = fmaf(wv.x, e0.w, a3);
        a0 = fmaf(wv.y, e1.x, a0); a1 = fmaf(wv.y, e1.y, a1);
        a2 = fmaf(wv.y, e1.z, a2); a3 = fmaf(wv.y, e1.w, a3);
        a0 = fmaf(wv.z, e2.x, a0); a1 = fmaf(wv.z, e2.y, a1);
        a2 = fmaf(wv.z, e2.z, a2); a3 = fmaf(wv.z, e2.w, a3);
        a0 = fmaf(wv.w, e3.x, a0); a1 = fmaf(wv.w, e3.y, a1);
        a2 = fmaf(wv.w, e3.z, a2); a3 = fmaf(wv.w, e3.w, a3);
    }
    *(float4*)&sR[tid * 4] = make_float4(a0, a1, a2, a3);
    __syncthreads();
    if (tid < 128) {
        float4 lo = *(const float4*)&sR[tid * 4];
        float4 hi = *(const float4*)&sR[(tid + 128) * 4];
        float bias = (isf ? blf : blg)[i * CC + c];
        float* dst = (isf ? g_HF : g_HG);
        dst[((size_t)i * BB + b0 + 0) * CC + c] = lo.x + hi.x + bias;
        dst[((size_t)i * BB + b0 + 1) * CC + c] = lo.y + hi.y + bias;
        dst[((size_t)i * BB + b0 + 2) * CC + c] = lo.z + hi.z + bias;
        dst[((size_t)i * BB + b0 + 3) * CC + c] = lo.w + hi.w + bias;
    }
}

// ---------------- K3: initial residual (vectorized) ---------------------------
__global__ void __launch_bounds__(256) k_init(
    const int* __restrict__ tok, const float* __restrict__ b_causal)
{
    __shared__ float sM0[VV * CC], sM1[VV * CC], sb[CC];
    int tid = threadIdx.x;
    for (int i = tid; i < VV * CC; i += 256) { sM0[i] = g_M0[i]; sM1[i] = g_M1[i]; }
    if (tid < CC) sb[tid] = b_causal[tid];
    __syncthreads();
    int b = blockIdx.y, tt0 = blockIdx.x * 64;
    const int* tb = tok + b * LL;
    float* ro = g_res0 + (size_t)b * LL * CC;
    for (int idx = tid; idx < 64 * 16; idx += 256) {
        int t = tt0 + (idx >> 4);
        int c4 = (idx & 15) * 4;
        float4 r = *(const float4*)&sM1[tb[t] * CC + c4];
        float4 bz = *(const float4*)&sb[c4];
        r.x += bz.x; r.y += bz.y; r.z += bz.z; r.w += bz.w;
        if (t > 0) {
            float4 p = *(const float4*)&sM0[tb[t - 1] * CC + c4];
            r.x += p.x; r.y += p.y; r.z += p.z; r.w += p.w;
        }
        *(float4*)(ro + (size_t)t * CC + c4) = r;
    }
}

// ---------------- K4: dilated residual layer (prefetch + fewer barriers) -----
__global__ void __launch_bounds__(256, 2) k_layer_tc(
    const float* __restrict__ b_f, const float* __restrict__ b_g,
    const float* __restrict__ b_res,
    int layer, int d, int in_sel, int out_sel)
{
    extern __shared__ u32 smem_u[];
    uint4* Xf  = (uint4*)smem_u;                   // 2304 uint4 = 9216 u32
    float* Dsm = (float*)(smem_u + 9216);          // 128 x 68 = 8704 u32 (separate)
    uint4* Zf  = (uint4*)(smem_u + 17920);         // 1280 uint4 = 5120 u32
    float* SK  = (float*)(smem_u + 23040);         // 64 x 68 = 4352 u32 (separate)
    float* sBF = (float*)(smem_u + 27392);         // 64
    float* sBG = sBF + 64;                         // 64

    int tid = threadIdx.x;
    int lane = tid & 31;
    int w = tid >> 5;
    int b = blockIdx.y;
    int tt0 = blockIdx.x * 64;
    int r = lane & 3, tb = lane >> 2;

    if (tid < 64)
        sBF[tid] = b_f[layer * CC + tid] + g_HF[((size_t)layer * BB + b) * CC + tid];
    else if (tid < 128) {
        int c = tid - 64;
        sBG[c] = b_g[layer * CC + c] + g_HG[((size_t)layer * BB + b) * CC + c];
    }

    // ---- build X fragments ----
    const float* rin = buf_c(in_sel) + (size_t)b * LL * CC;
    #pragma unroll
    for (int it = 0; it < 8; it++) {
        int id = it * 256 + tid;
        int t = id >> 5;
        int sl = id & 31;
        int q = (sl >> 2) * 8 + (sl & 3);
        int k1 = 2 * q, k2 = 2 * q + 8;
        float2 v1 = make_float2(0.f, 0.f), v2 = make_float2(0.f, 0.f);
        int gtp = tt0 + t - d;
        if (k1 < 64) { if (gtp >= 0) v1 = *(const float2*)(rin + (size_t)gtp * CC + k1); }
        else v1 = *(const float2*)(rin + (size_t)(tt0 + t) * CC + (k1 - 64));
        if (k2 < 64) { if (gtp >= 0) v2 = *(const float2*)(rin + (size_t)gtp * CC + k2); }
        else v2 = *(const float2*)(rin + (size_t)(tt0 + t) * CC + (k2 - 64));
        u32 h1, l1, h2, l2;
        split2(v1.x, v1.y, h1, l1);
        split2(v2.x, v2.y, h2, l2);
        Xf[t * XP4 + sl] = make_uint4(h1, h2, l1, l2);
    }
    __syncthreads();                       // (1) X + biases ready

    // ---- GEMM1 with register double-buffered A prefetch ----
    int mg = w & 3, ng = w >> 2;
    float acc[2][4][4];
    #pragma unroll
    for (int mi = 0; mi < 2; mi++)
        #pragma unroll
        for (int j = 0; j < 4; j++)
            #pragma unroll
            for (int rr = 0; rr < 4; rr++) acc[mi][j][rr] = 0.f;

    const uint4* WFp = (const uint4*)(g_WF + (size_t)layer * 16384) + (mg * 2) * 512;
    uint4 AhR[2][2], AlR[2][2];
    #pragma unroll
    for (int mi = 0; mi < 2; mi++) {
        AhR[0][mi] = WFp[mi * 512 + lane];
        AlR[0][mi] = WFp[mi * 512 + 32 + lane];
    }
    #pragma unroll
    for (int s = 0; s < 8; s++) {
        int cur = s & 1, nxt = cur ^ 1;
        if (s < 7) {
            #pragma unroll
            for (int mi = 0; mi < 2; mi++) {
                AhR[nxt][mi] = WFp[mi * 512 + (s + 1) * 64 + lane];
                AlR[nxt][mi] = WFp[mi * 512 + (s + 1) * 64 + 32 + lane];
            }
        }
        uint4 B0 = Xf[(ng * 32 + 0 + tb) * XP4 + s * 4 + r];
        uint4 B1 = Xf[(ng * 32 + 8 + tb) * XP4 + s * 4 + r];
        uint4 B2 = Xf[(ng * 32 + 16 + tb) * XP4 + s * 4 + r];
        uint4 B3 = Xf[(ng * 32 + 24 + tb) * XP4 + s * 4 + r];
        #pragma unroll
        for (int mi = 0; mi < 2; mi++) {
            uint4 Ah = AhR[cur][mi];
            uint4 Al = AlR[cur][mi];
            mma16816(acc[mi][0], Ah.x, Ah.y, Ah.z, Ah.w, B0.x, B0.y);
            mma16816(acc[mi][0], Ah.x, Ah.y, Ah.z, Ah.w, B0.z, B0.w);
            mma16816(acc[mi][0], Al.x, Al.y, Al.z, Al.w, B0.x, B0.y);
            mma16816(acc[mi][1], Ah.x, Ah.y, Ah.z, Ah.w, B1.x, B1.y);
            mma16816(acc[mi][1], Ah.x, Ah.y, Ah.z, Ah.w, B1.z, B1.w);
            mma16816(acc[mi][1], Al.x, Al.y, Al.z, Al.w, B1.x, B1.y);
            mma16816(acc[mi][2], Ah.x, Ah.y, Ah.z, Ah.w, B2.x, B2.y);
            mma16816(acc[mi][2], Ah.x, Ah.y, Ah.z, Ah.w, B2.z, B2.w);
            mma16816(acc[mi][2], Al.x, Al.y, Al.z, Al.w, B2.x, B2.y);
            mma16816(acc[mi][3], Ah.x, Ah.y, Ah.z, Ah.w, B3.x, B3.y);
            mma16816(acc[mi][3], Ah.x, Ah.y, Ah.z, Ah.w, B3.z, B3.w);
            mma16816(acc[mi][3], Al.x, Al.y, Al.z, Al.w, B3.x, B3.y);
        }
    }

    // ---- store D to separate buffer (no barrier needed before store) ----
    {
        int gr = lane >> 2, tq = 2 * (lane & 3);
        #pragma unroll
        for (int mi = 0; mi < 2; mi++)
            #pragma unroll
            for (int j = 0; j < 4; j++) {
                int m = mg * 32 + mi * 16 + gr;
                int t = ng * 32 + j * 8 + tq;
                *(float2*)&Dsm[m * 68 + t] = make_float2(acc[mi][j][0], acc[mi][j][1]);
                *(float2*)&Dsm[(m + 8) * 68 + t] = make_float2(acc[mi][j][2], acc[mi][j][3]);
            }
    }
    __syncthreads();                       // (2) D complete

    // ---- gated activation -> Z fragments ----
    #pragma unroll
    for (int it = 0; it < 4; it++) {
        int id = it * 256 + tid;
        int t = id >> 4;
        int sl = id & 15;
        int q = (sl >> 2) * 8 + (sl & 3);
        int c1 = 2 * q, c2 = 2 * q + 8;
        float f0 = Dsm[c1 * 68 + t] + sBF[c1];
        float f1 = Dsm[(c1 + 1) * 68 + t] + sBF[c1 + 1];
        float f2 = Dsm[c2 * 68 + t] + sBF[c2];
        float f3 = Dsm[(c2 + 1) * 68 + t] + sBF[c2 + 1];
        float g0 = Dsm[(c1 + 64) * 68 + t] + sBG[c1];
        float g1 = Dsm[(c1 + 65) * 68 + t] + sBG[c1 + 1];
        float g2 = Dsm[(c2 + 64) * 68 + t] + sBG[c2];
        float g3 = Dsm[(c2 + 65) * 68 + t] + sBG[c2 + 1];
        float z0 = fast_tanh(f0) * fast_sigmoid(g0);
        float z1 = fast_tanh(f1) * fast_sigmoid(g1);
        float z2 = fast_tanh(f2) * fast_sigmoid(g2);
        float z3 = fast_tanh(f3) * fast_sigmoid(g3);
        u32 h1, l1, h2, l2;
        split2(z0, z1, h1, l1);
        split2(z2, z3, h2, l2);
        Zf[t * ZP4 + sl] = make_uint4(h1, h2, l1, l2);
    }
    __syncthreads();                       // (3) Z ready

    // ---- GEMM2 with prefetch ----
    int mg2 = w & 1, ng2 = w >> 1;
    float acc2[2][2][4];
    #pragma unroll
    for (int mi = 0; mi < 2; mi++)
        #pragma unroll
        for (int j = 0; j < 2; j++)
            #pragma unroll
            for (int rr = 0; rr < 4; rr++) acc2[mi][j][rr] = 0.f;

    const uint4* WRp = (const uint4*)(g_WR + (size_t)layer * 4096) + (mg2 * 2) * 256;
    uint4 Ah2R[2][2], Al2R[2][2];
    #pragma unroll
    for (int mi = 0; mi < 2; mi++) {
        Ah2R[0][mi] = WRp[mi * 256 + lane];
        Al2R[0][mi] = WRp[mi * 256 + 32 + lane];
    }
    #pragma unroll
    for (int s = 0; s < 4; s++) {
        int cur = s & 1, nxt = cur ^ 1;
        if (s < 3) {
            #pragma unroll
            for (int mi = 0; mi < 2; mi++) {
                Ah2R[nxt][mi] = WRp[mi * 256 + (s + 1) * 64 + lane];
                Al2R[nxt][mi] = WRp[mi * 256 + (s + 1) * 64 + 32 + lane];
            }
        }
        uint4 B0 = Zf[(ng2 * 16 + 0 + tb) * ZP4 + s * 4 + r];
        uint4 B1 = Zf[(ng2 * 16 + 8 + tb) * ZP4 + s * 4 + r];
        #pragma unroll
        for (int mi = 0; mi < 2; mi++) {
            uint4 Ah = Ah2R[cur][mi];
            uint4 Al = Al2R[cur][mi];
            mma16816(acc2[mi][0], Ah.x, Ah.y, Ah.z, Ah.w, B0.x, B0.y);
            mma16816(acc2[mi][0], Ah.x, Ah.y, Ah.z, Ah.w, B0.z, B0.w);
            mma16816(acc2[mi][0], Al.x, Al.y, Al.z, Al.w, B0.x, B0.y);
            mma16816(acc2[mi][1], Ah.x, Ah.y, Ah.z, Ah.w, B1.x, B1.y);
            mma16816(acc2[mi][1], Ah.x, Ah.y, Ah.z, Ah.w, B1.z, B1.w);
            mma16816(acc2[mi][1], Al.x, Al.y, Al.z, Al.w, B1.x, B1.y);
        }
    }

    // ---- store skip to separate buffer ----
    {
        int gr = lane >> 2, tq = 2 * (lane & 3);
        #pragma unroll
        for (int mi = 0; mi < 2; mi++)
            #pragma unroll
            for (int j = 0; j < 2; j++) {
                int m = mg2 * 32 + mi * 16 + gr;
                int t = ng2 * 16 + j * 8 + tq;
                SK[t * 68 + m] = acc2[mi][j][0];
                SK[(t + 1) * 68 + m] = acc2[mi][j][1];
                SK[t * 68 + m + 8] = acc2[mi][j][2];
                SK[(t + 1) * 68 + m + 8] = acc2[mi][j][3];
            }
    }
    __syncthreads();                       // (4) SK complete

    // ---- epilogue ----
    const float* brp = b_res + layer * CC;
    float* rout = buf_m(out_sel) + (size_t)b * LL * CC;
    #pragma unroll
    for (int it = 0; it < 4; it++) {
        int id = it * 256 + tid;
        int t = id >> 4, cq = (id & 15) * 4;
        float4 rv = *(const float4*)(rin + (size_t)(tt0 + t) * CC + cq);
        float4 bz = *(const float4*)(brp + cq);
        float4 s4 = *(const float4*)&SK[t * 68 + cq];
        float4 o = make_float4(rv.x + s4.x + bz.x, rv.y + s4.y + bz.y,
                               rv.z + s4.z + bz.z, rv.w + s4.w + bz.w);
        *(float4*)(rout + (size_t)(tt0 + t) * CC + cq) = o;
    }
}

// ---------------- K5: head on tensor cores ------------------------------------
__global__ void __launch_bounds__(256, 2) k_final_tc(
    const float* __restrict__ b1, const float* __restrict__ b2,
    float* __restrict__ out)
{
    extern __shared__ u32 smem_u[];
    u32* XH = smem_u;                 // 64 x 36 u32
    u32* XL = smem_u + 2304;
    float* Dsm = (float*)smem_u;      // overlay: 128 x 68 f32
    u32* HH = smem_u + 8704;          // 64 x 68 u32
    u32* HL = smem_u + 13056;

    int tid = threadIdx.x;
    int lane = tid & 31;
    int w = tid >> 5;
    int b = blockIdx.y;
    int tt0 = blockIdx.x * 64;
    int tb = lane >> 2;

    const float* rA = g_resA + (size_t)b * LL * CC;
    const float* r0 = g_res0 + (size_t)b * LL * CC;
    #pragma unroll
    for (int it = 0; it < 4; it++) {
        int id = it * 256 + tid;
        int t = id >> 4, cq = (id & 15) * 4;
        size_t off = (size_t)(tt0 + t) * CC + cq;
        float4 a = *(const float4*)(rA + off);
        float4 z = *(const float4*)(r0 + off);
        float s0 = fmaxf(a.x - z.x, 0.f), s1 = fmaxf(a.y - z.y, 0.f);
        float s2 = fmaxf(a.z - z.z, 0.f), s3 = fmaxf(a.w - z.w, 0.f);
        u32 h0, l0, h1, l1;
        split2(s0, s1, h0, l0);
        split2(s2, s3, h1, l1);
        int o = t * 36 + (cq >> 1);
        *(uint2*)&XH[o] = make_uint2(h0, h1);
        *(uint2*)&XL[o] = make_uint2(l0, l1);
    }
    __syncthreads();

    float acc[8][4];
    #pragma unroll
    for (int j = 0; j < 8; j++)
        #pragma unroll
        for (int rr = 0; rr < 4; rr++) acc[j][rr] = 0.f;

    const uint4* W1p = (const uint4*)(g_W1 + w * 1024);
    #pragma unroll
    for (int s = 0; s < 4; s++) {
        uint4 Ah = W1p[s * 64 + lane];
        uint4 Al = W1p[s * 64 + 32 + lane];
        int kb = s * 8 + (lane & 3);
        #pragma unroll
        for (int j = 0; j < 8; j++) {
            int base = (j * 8 + tb) * 36 + kb;
            u32 bh0 = XH[base], bh1 = XH[base + 4];
            u32 bl0 = XL[base], bl1 = XL[base + 4];
            mma16816(acc[j], Ah.x, Ah.y, Ah.z, Ah.w, bh0, bh1);
            mma16816(acc[j], Ah.x, Ah.y, Ah.z, Ah.w, bl0, bl1);
            mma16816(acc[j], Al.x, Al.y, Al.z, Al.w, bh0, bh1);
        }
    }
    __syncthreads();

    {
        int g = lane >> 2, tq = 2 * (lane & 3);
        int m = w * 16 + g;
        #pragma unroll
        for (int j = 0; j < 8; j++) {
            int t = j * 8 + tq;
            *(float2*)&Dsm[m * 68 + t] = make_float2(acc[j][0], acc[j][1]);
            *(float2*)&Dsm[(m + 8) * 68 + t] = make_float2(acc[j][2], acc[j][3]);
        }
    }
    __syncthreads();

    #pragma unroll
    for (int it = 0; it < 16; it++) {
        int id = it * 256 + tid;
        int mp = id & 63, t = id >> 6;
        float h0 = fmaxf(Dsm[(2 * mp) * 68 + t] + b1[2 * mp], 0.f);
        float h1 = fmaxf(Dsm[(2 * mp + 1) * 68 + t] + b1[2 * mp + 1], 0.f);
        u32 hh, hl; split2(h0, h1, hh, hl);
        HH[t * 68 + mp] = hh;
        HL[t * 68 + mp] = hl;
    }
    __syncthreads();

    int mt = w & 1;
    float acc2[2][4];
    #pragma unroll
    for (int j = 0; j < 2; j++)
        #pragma unroll
        for (int rr = 0; rr < 4; rr++) acc2[j][rr] = 0.f;

    const uint4* W2p = (const uint4*)(g_W2 + mt * 2048);
    #pragma unroll
    for (int s = 0; s < 8; s++) {
        uint4 Ah = W2p[s * 64 + lane];
        uint4 Al = W2p[s * 64 + 32 + lane];
        int kb = s * 8 + (lane & 3);
        #pragma unroll
        for (int j = 0; j < 2; j++) {
            int nblk = (w >> 1) * 2 + j;
            int base = (nblk * 8 + tb) * 68 + kb;
            u32 bh0 = HH[base], bh1 = HH[base + 4];
            u32 bl0 = HL[base], bl1 = HL[base + 4];
            mma16816(acc2[j], Ah.x, Ah.y, Ah.z, Ah.w, bh0, bh1);
            mma16816(acc2[j], Ah.x, Ah.y, Ah.z, Ah.w, bl0, bl1);
            mma16816(acc2[j], Al.x, Al.y, Al.z, Al.w, bh0, bh1);
        }
    }

    {
        int m = mt * 16 + (lane >> 2);
        #pragma unroll
        for (int j = 0; j < 2; j++) {
            int nblk = (w >> 1) * 2 + j;
            int t = tt0 + nblk * 8 + 2 * (lane & 3);
            int o1 = m, o2 = m + 8;
            *(float2*)(out + ((size_t)b * OO + o1) * LL + t) =
                make_float2(acc2[j][0] + b2[o1], acc2[j][1] + b2[o1]);
            if (o2 < OO)
                *(float2*)(out + ((size_t)b * OO + o2) * LL + t) =
                    make_float2(acc2[j][2] + b2[o2], acc2[j][3] + b2[o2]);
        }
    }
}

// ---------------- launch -----------------------------------------------------
extern "C" void kernel_launch(void* const* d_in, const int* in_sizes, int n_in,
                              void* d_out, int out_size)
{
    const int*   in_tok = (const int*)d_in[0];
    const int*   g_tok  = (const int*)d_in[1];
    const float* emb    = (const float*)d_in[2];
    const float* wc     = (const float*)d_in[3];
    const float* bc     = (const float*)d_in[4];
    const float* wf     = (const float*)d_in[5];
    const float* bf     = (const float*)d_in[6];
    const float* wg     = (const float*)d_in[7];
    const float* bg     = (const float*)d_in[8];
    const float* wlf    = (const float*)d_in[9];
    const float* blf    = (const float*)d_in[10];
    const float* wlg    = (const float*)d_in[11];
    const float* blg    = (const float*)d_in[12];
    const float* wres   = (const float*)d_in[13];
    const float* bres   = (const float*)d_in[14];
    const float* w1     = (const float*)d_in[15];
    const float* b1     = (const float*)d_in[16];
    const float* w2     = (const float*)d_in[17];
    const float* b2     = (const float*)d_in[18];
    float* out = (float*)d_out;

    const int LAYER_SMEM = 27520 * 4;   // 110080 B (2 blocks/SM: 215 KB of 228)
    const int FINAL_SMEM = 17408 * 4;   // 69632 B
    cudaFuncSetAttribute(k_layer_tc, cudaFuncAttributeMaxDynamicSharedMemorySize, LAYER_SMEM);
    cudaFuncSetAttribute(k_final_tc, cudaFuncAttributeMaxDynamicSharedMemorySize, FINAL_SMEM);

    k_precompute_M<<<VV, 64>>>(emb, wc);
    k_prep_w<<<NDND, 256>>>(wf, wg, wres);
    k_prep_head<<<1, 256>>>(w1, w2);
    k_embg<<<BB, 256>>>(g_tok, emb);
    k_H<<<dim3(NDND, 16), 256>>>(wlf, blf, wlg, blg);
    k_init<<<dim3(LL / 64, BB), 256>>>(in_tok, bc);
    for (int i = 0; i < NDND; i++) {
        int d = 2 << i;
        int out_sel = (i % 2 == 0) ? 1 : 2;           // layer 8 -> resA
        int in_sel  = (i == 0) ? 0 : ((i % 2 == 0) ? 2 : 1);
        k_layer_tc<<<dim3(LL / 64, BB), 256, LAYER_SMEM>>>(
            bf, bg, bres, i, d, in_sel, out_sel);
    }
    k_final_tc<<<dim3(LL / 64, BB), 256, FINAL_SMEM>>>(b1, b2, out);
}

// round 9
// speedup vs baseline: 5.3044x; 1.1487x over previous
#include <cuda_runtime.h>
#include <cuda_fp16.h>
#include <math.h>

#define BB   64
#define LL   2048
#define VV   30
#define EE   128
#define GG   8
#define GEGE 1024
#define CC   64
#define FF   128
#define OO   30
#define NDND 9

#define XP4  36    // uint4 pitch per t-row, X fragments
#define ZP4  20    // uint4 pitch per t-row, Z fragments
#define RSCALE 2048.0f
#define RSCALE_INV 4.8828125e-4f

typedef unsigned int u32;

// ---------------- helpers ----------------------------------------------------
__device__ __forceinline__ void mma16816h(float* d, u32 a0, u32 a1, u32 a2, u32 a3,
                                          u32 b0, u32 b1) {
    asm volatile(
        "mma.sync.aligned.m16n8k16.row.col.f32.f16.f16.f32 "
        "{%0,%1,%2,%3}, {%4,%5,%6,%7}, {%8,%9}, {%0,%1,%2,%3};"
        : "+f"(d[0]), "+f"(d[1]), "+f"(d[2]), "+f"(d[3])
        : "r"(a0), "r"(a1), "r"(a2), "r"(a3), "r"(b0), "r"(b1));
}
// split two floats: hi = packed fp16 pair; lo = packed fp16 pair of residual*2048
__device__ __forceinline__ void split2h(float x0, float x1, u32& hi, u32& lo) {
    __half h0 = __float2half_rn(x0);
    __half h1 = __float2half_rn(x1);
    float r0 = (x0 - __half2float(h0)) * RSCALE;
    float r1 = (x1 - __half2float(h1)) * RSCALE;
    __half2 hv = __halves2half2(h0, h1);
    __half2 lv = __halves2half2(__float2half_rn(r0), __float2half_rn(r1));
    hi = *(u32*)&hv; lo = *(u32*)&lv;
}
// hi-only fp16 pair (for weights)
__device__ __forceinline__ u32 pack2h(float x0, float x1) {
    __half2 hv = __halves2half2(__float2half_rn(x0), __float2half_rn(x1));
    return *(u32*)&hv;
}
__device__ __forceinline__ float fast_tanh(float x) {
    float e; asm("ex2.approx.f32 %0, %1;" : "=f"(e) : "f"(x * 2.8853900817779268f));
    float r; asm("rcp.approx.f32 %0, %1;" : "=f"(r) : "f"(e + 1.0f));
    return 1.0f - 2.0f * r;
}
__device__ __forceinline__ float fast_sigmoid(float x) {
    float e; asm("ex2.approx.f32 %0, %1;" : "=f"(e) : "f"(-x * 1.4426950408889634f));
    float r; asm("rcp.approx.f32 %0, %1;" : "=f"(r) : "f"(e + 1.0f));
    return r;
}

// ---------------- scratch ----------------------------------------------------
__device__ float g_res0[(size_t)BB * LL * CC];
__device__ float g_resA[(size_t)BB * LL * CC];
__device__ float g_resB[(size_t)BB * LL * CC];
__device__ float g_embg[BB * GEGE];
__device__ float g_HF[NDND * BB * CC];
__device__ float g_HG[NDND * BB * CC];
__device__ float g_M0[VV * CC];
__device__ float g_M1[VV * CC];
__device__ u32 g_WF[NDND * 8192];   // GEMM1 A frags (fp16, hi only): [layer][mt8][s8][lane32][r4]
__device__ u32 g_WR[NDND * 2048];   // GEMM2 A frags: [layer][mt4][s4][lane32][r4]
__device__ u32 g_W1[4096];          // head GEMM1 A frags: [warp8][s4][lane32][r4]
__device__ u32 g_W2[2048];          // head GEMM2 A frags: [mt2][s8][lane32][r4]

__device__ __forceinline__ const float* buf_c(int sel) {
    return sel == 0 ? g_res0 : (sel == 1 ? g_resA : g_resB);
}
__device__ __forceinline__ float* buf_m(int sel) {
    return sel == 1 ? g_resA : g_resB;
}

// ---------------- K0a: fold embedding + initial conv --------------------------
__global__ void __launch_bounds__(64) k_precompute_M(
    const float* __restrict__ emb, const float* __restrict__ wc)
{
    int v = blockIdx.x, c = threadIdx.x;
    float a0 = 0.f, a1 = 0.f;
    if (v != 0) {
        for (int e = 0; e < EE; e++) {
            float x = emb[v * EE + e];
            a0 = fmaf(x, wc[(c * EE + e) * 2 + 0], a0);
            a1 = fmaf(x, wc[(c * EE + e) * 2 + 1], a1);
        }
    }
    g_M0[v * CC + c] = a0;
    g_M1[v * CC + c] = a1;
}

// ---------------- K0b: layer weights -> fp16 fragment layout -------------------
__global__ void __launch_bounds__(256) k_prep_w(
    const float* __restrict__ wf, const float* __restrict__ wg,
    const float* __restrict__ wres)
{
    int layer = blockIdx.x;
    // GEMM1 A: [m=128 (f||g)][k=128 (prev||cur)]
    for (int idx = threadIdx.x; idx < 8192; idx += 256) {
        int w = idx >> 10, s = (idx >> 7) & 7;
        int lane = (idx >> 2) & 31, r = idx & 3;
        int m = w * 16 + (r & 1) * 8 + (lane >> 2);
        int k0 = s * 16 + ((r >> 1) & 1) * 8 + (lane & 3) * 2;
        const float* src = (m < 64) ? wf : wg;
        int cout = m & 63;
        int cin0 = k0 & 63, tap0 = k0 >> 6;
        int k1 = k0 + 1;
        int cin1 = k1 & 63, tap1 = k1 >> 6;
        float x0 = src[(((size_t)layer * 64 + cout) * 64 + cin0) * 2 + tap0];
        float x1 = src[(((size_t)layer * 64 + cout) * 64 + cin1) * 2 + tap1];
        g_WF[(size_t)layer * 8192 + idx] = pack2h(x0, x1);
    }
    // GEMM2 A: W_res [m=64][k=64]
    for (int idx = threadIdx.x; idx < 2048; idx += 256) {
        int mt = idx >> 9, s = (idx >> 7) & 3;
        int lane = (idx >> 2) & 31, r = idx & 3;
        int m = mt * 16 + (r & 1) * 8 + (lane >> 2);
        int k0 = s * 16 + ((r >> 1) & 1) * 8 + (lane & 3) * 2;
        float x0 = wres[((size_t)layer * 64 + m) * 64 + k0];
        float x1 = wres[((size_t)layer * 64 + m) * 64 + k0 + 1];
        g_WR[(size_t)layer * 2048 + idx] = pack2h(x0, x1);
    }
}

// ---------------- K0c: head weights -> fp16 fragment layout --------------------
__global__ void __launch_bounds__(256) k_prep_head(
    const float* __restrict__ w1, const float* __restrict__ w2)
{
    for (int idx = threadIdx.x; idx < 4096; idx += 256) {
        int w = idx >> 9, s = (idx >> 7) & 3;
        int lane = (idx >> 2) & 31, r = idx & 3;
        int m = w * 16 + (r & 1) * 8 + (lane >> 2);
        int k0 = s * 16 + ((r >> 1) & 1) * 8 + (lane & 3) * 2;
        g_W1[idx] = pack2h(w1[m * 64 + k0], w1[m * 64 + k0 + 1]);
    }
    for (int idx = threadIdx.x; idx < 2048; idx += 256) {
        int mt = idx >> 10, s = (idx >> 7) & 7;
        int lane = (idx >> 2) & 31, r = idx & 3;
        int m = mt * 16 + (r & 1) * 8 + (lane >> 2);
        int k0 = s * 16 + ((r >> 1) & 1) * 8 + (lane & 3) * 2;
        float x0 = (m < OO) ? w2[m * 128 + k0] : 0.f;
        float x1 = (m < OO) ? w2[m * 128 + k0 + 1] : 0.f;
        g_W2[idx] = pack2h(x0, x1);
    }
}

// ---------------- K1: global embedding -----------------------------------------
__global__ void __launch_bounds__(256) k_embg(
    const int* __restrict__ gin, const float* __restrict__ emb)
{
    int b = blockIdx.x;
    for (int j = threadIdx.x; j < GEGE; j += 256) {
        int g = j >> 7, e = j & 127;
        int tok = gin[b * GG + g];
        g_embg[b * GEGE + j] = (tok == 0) ? 0.f : emb[tok * EE + e];
    }
}

// ---------------- K2: conditioning vectors --------------------------------------
__global__ void __launch_bounds__(256) k_H(
    const float* __restrict__ wlf, const float* __restrict__ blf,
    const float* __restrict__ wlg, const float* __restrict__ blg)
{
    __shared__ float sE[GEGE * 4];
    __shared__ float sR[256 * 4];
    int i = blockIdx.x;
    int b0 = blockIdx.y * 4;
    int tid = threadIdx.x;

    for (int idx = tid; idx < GEGE * 4; idx += 256) {
        int k = idx >> 2, bj = idx & 3;
        sE[idx] = g_embg[(size_t)(b0 + bj) * GEGE + k];
    }
    __syncthreads();

    int row = tid & 127;
    int half = tid >> 7;
    int c = row & 63;
    bool isf = row < 64;
    const float* w = (isf ? wlf : wlg) + ((size_t)i * CC + c) * GEGE + half * 512;
    const float* ep = sE + half * 512 * 4;

    float a0 = 0.f, a1 = 0.f, a2 = 0.f, a3 = 0.f;
    #pragma unroll 4
    for (int k = 0; k < 512; k += 4) {
        float4 wv = *(const float4*)(w + k);
        float4 e0 = *(const float4*)(ep + k * 4);
        float4 e1 = *(const float4*)(ep + k * 4 + 4);
        float4 e2 = *(const float4*)(ep + k * 4 + 8);
        float4 e3 = *(const float4*)(ep + k * 4 + 12);
        a0 = fmaf(wv.x, e0.x, a0); a1 = fmaf(wv.x, e0.y, a1);
        a2 = fmaf(wv.x, e0.z, a2); a3 = fmaf(wv.x, e0.w, a3);
        a0 = fmaf(wv.y, e1.x, a0); a1 = fmaf(wv.y, e1.y, a1);
        a2 = fmaf(wv.y, e1.z, a2); a3 = fmaf(wv.y, e1.w, a3);
        a0 = fmaf(wv.z, e2.x, a0); a1 = fmaf(wv.z, e2.y, a1);
        a2 = fmaf(wv.z, e2.z, a2); a3 = fmaf(wv.z, e2.w, a3);
        a0 = fmaf(wv.w, e3.x, a0); a1 = fmaf(wv.w, e3.y, a1);
        a2 = fmaf(wv.w, e3.z, a2); a3 = fmaf(wv.w, e3.w, a3);
    }
    *(float4*)&sR[tid * 4] = make_float4(a0, a1, a2, a3);
    __syncthreads();
    if (tid < 128) {
        float4 lo = *(const float4*)&sR[tid * 4];
        float4 hi = *(const float4*)&sR[(tid + 128) * 4];
        float bias = (isf ? blf : blg)[i * CC + c];
        float* dst = (isf ? g_HF : g_HG);
        dst[((size_t)i * BB + b0 + 0) * CC + c] = lo.x + hi.x + bias;
        dst[((size_t)i * BB + b0 + 1) * CC + c] = lo.y + hi.y + bias;
        dst[((size_t)i * BB + b0 + 2) * CC + c] = lo.z + hi.z + bias;
        dst[((size_t)i * BB + b0 + 3) * CC + c] = lo.w + hi.w + bias;
    }
}

// ---------------- K3: initial residual ------------------------------------------
__global__ void __launch_bounds__(256) k_init(
    const int* __restrict__ tok, const float* __restrict__ b_causal)
{
    __shared__ float sM0[VV * CC], sM1[VV * CC], sb[CC];
    int tid = threadIdx.x;
    for (int i = tid; i < VV * CC; i += 256) { sM0[i] = g_M0[i]; sM1[i] = g_M1[i]; }
    if (tid < CC) sb[tid] = b_causal[tid];
    __syncthreads();
    int b = blockIdx.y, tt0 = blockIdx.x * 64;
    const int* tb = tok + b * LL;
    float* ro = g_res0 + (size_t)b * LL * CC;
    for (int idx = tid; idx < 64 * 16; idx += 256) {
        int t = tt0 + (idx >> 4);
        int c4 = (idx & 15) * 4;
        float4 r = *(const float4*)&sM1[tb[t] * CC + c4];
        float4 bz = *(const float4*)&sb[c4];
        r.x += bz.x; r.y += bz.y; r.z += bz.z; r.w += bz.w;
        if (t > 0) {
            float4 p = *(const float4*)&sM0[tb[t - 1] * CC + c4];
            r.x += p.x; r.y += p.y; r.z += p.z; r.w += p.w;
        }
        *(float4*)(ro + (size_t)t * CC + c4) = r;
    }
}

// ---------------- K4: dilated residual layer (fp16 2-MMA split) ----------------
__global__ void __launch_bounds__(256, 2) k_layer_tc(
    const float* __restrict__ b_f, const float* __restrict__ b_g,
    const float* __restrict__ b_res,
    int layer, int d, int in_sel, int out_sel)
{
    extern __shared__ u32 smem_u[];
    uint4* Xf  = (uint4*)smem_u;                   // 2304 uint4 = 9216 u32
    float* Dsm = (float*)(smem_u + 9216);          // 128 x 68 = 8704 u32
    uint4* Zf  = (uint4*)(smem_u + 17920);         // 1280 uint4 = 5120 u32
    float* SK  = (float*)(smem_u + 23040);         // 64 x 68 = 4352 u32
    float* sBF = (float*)(smem_u + 27392);         // 64
    float* sBG = sBF + 64;                         // 64

    int tid = threadIdx.x;
    int lane = tid & 31;
    int w = tid >> 5;
    int b = blockIdx.y;
    int tt0 = blockIdx.x * 64;
    int r = lane & 3, tb = lane >> 2;

    if (tid < 64)
        sBF[tid] = b_f[layer * CC + tid] + g_HF[((size_t)layer * BB + b) * CC + tid];
    else if (tid < 128) {
        int c = tid - 64;
        sBG[c] = b_g[layer * CC + c] + g_HG[((size_t)layer * BB + b) * CC + c];
    }

    // ---- build X fragments: slot = (hi_q, hi_{q+4}, loS_q, loS_{q+4}) ----
    const float* rin = buf_c(in_sel) + (size_t)b * LL * CC;
    #pragma unroll
    for (int it = 0; it < 8; it++) {
        int id = it * 256 + tid;
        int t = id >> 5;
        int sl = id & 31;
        int q = (sl >> 2) * 8 + (sl & 3);
        int k1 = 2 * q, k2 = 2 * q + 8;
        float2 v1 = make_float2(0.f, 0.f), v2 = make_float2(0.f, 0.f);
        int gtp = tt0 + t - d;
        if (k1 < 64) { if (gtp >= 0) v1 = *(const float2*)(rin + (size_t)gtp * CC + k1); }
        else v1 = *(const float2*)(rin + (size_t)(tt0 + t) * CC + (k1 - 64));
        if (k2 < 64) { if (gtp >= 0) v2 = *(const float2*)(rin + (size_t)gtp * CC + k2); }
        else v2 = *(const float2*)(rin + (size_t)(tt0 + t) * CC + (k2 - 64));
        u32 h1, l1, h2, l2;
        split2h(v1.x, v1.y, h1, l1);
        split2h(v2.x, v2.y, h2, l2);
        Xf[t * XP4 + sl] = make_uint4(h1, h2, l1, l2);
    }
    __syncthreads();

    // ---- GEMM1: main + scaled-correction accumulators ----
    int mg = w & 3, ng = w >> 2;
    float acc[2][4][4], accc[2][4][4];
    #pragma unroll
    for (int mi = 0; mi < 2; mi++)
        #pragma unroll
        for (int j = 0; j < 4; j++)
            #pragma unroll
            for (int rr = 0; rr < 4; rr++) { acc[mi][j][rr] = 0.f; accc[mi][j][rr] = 0.f; }

    const uint4* WFp = (const uint4*)(g_WF + (size_t)layer * 8192) + (mg * 2) * 256;
    uint4 AhR[2][2];
    #pragma unroll
    for (int mi = 0; mi < 2; mi++) AhR[0][mi] = WFp[mi * 256 + lane];
    #pragma unroll
    for (int s = 0; s < 8; s++) {
        int cur = s & 1, nxt = cur ^ 1;
        if (s < 7) {
            #pragma unroll
            for (int mi = 0; mi < 2; mi++)
                AhR[nxt][mi] = WFp[mi * 256 + (s + 1) * 32 + lane];
        }
        uint4 B0 = Xf[(ng * 32 + 0 + tb) * XP4 + s * 4 + r];
        uint4 B1 = Xf[(ng * 32 + 8 + tb) * XP4 + s * 4 + r];
        uint4 B2 = Xf[(ng * 32 + 16 + tb) * XP4 + s * 4 + r];
        uint4 B3 = Xf[(ng * 32 + 24 + tb) * XP4 + s * 4 + r];
        #pragma unroll
        for (int mi = 0; mi < 2; mi++) {
            uint4 Ah = AhR[cur][mi];
            mma16816h(acc[mi][0], Ah.x, Ah.y, Ah.z, Ah.w, B0.x, B0.y);
            mma16816h(accc[mi][0], Ah.x, Ah.y, Ah.z, Ah.w, B0.z, B0.w);
            mma16816h(acc[mi][1], Ah.x, Ah.y, Ah.z, Ah.w, B1.x, B1.y);
            mma16816h(accc[mi][1], Ah.x, Ah.y, Ah.z, Ah.w, B1.z, B1.w);
            mma16816h(acc[mi][2], Ah.x, Ah.y, Ah.z, Ah.w, B2.x, B2.y);
            mma16816h(accc[mi][2], Ah.x, Ah.y, Ah.z, Ah.w, B2.z, B2.w);
            mma16816h(acc[mi][3], Ah.x, Ah.y, Ah.z, Ah.w, B3.x, B3.y);
            mma16816h(accc[mi][3], Ah.x, Ah.y, Ah.z, Ah.w, B3.z, B3.w);
        }
    }

    // ---- store D = acc + accc/2048 ----
    {
        int gr = lane >> 2, tq = 2 * (lane & 3);
        #pragma unroll
        for (int mi = 0; mi < 2; mi++)
            #pragma unroll
            for (int j = 0; j < 4; j++) {
                int m = mg * 32 + mi * 16 + gr;
                int t = ng * 32 + j * 8 + tq;
                float d0 = fmaf(accc[mi][j][0], RSCALE_INV, acc[mi][j][0]);
                float d1 = fmaf(accc[mi][j][1], RSCALE_INV, acc[mi][j][1]);
                float d2 = fmaf(accc[mi][j][2], RSCALE_INV, acc[mi][j][2]);
                float d3 = fmaf(accc[mi][j][3], RSCALE_INV, acc[mi][j][3]);
                *(float2*)&Dsm[m * 68 + t] = make_float2(d0, d1);
                *(float2*)&Dsm[(m + 8) * 68 + t] = make_float2(d2, d3);
            }
    }
    __syncthreads();

    // ---- gated activation -> Z fragments ----
    #pragma unroll
    for (int it = 0; it < 4; it++) {
        int id = it * 256 + tid;
        int t = id >> 4;
        int sl = id & 15;
        int q = (sl >> 2) * 8 + (sl & 3);
        int c1 = 2 * q, c2 = 2 * q + 8;
        float f0 = Dsm[c1 * 68 + t] + sBF[c1];
        float f1 = Dsm[(c1 + 1) * 68 + t] + sBF[c1 + 1];
        float f2 = Dsm[c2 * 68 + t] + sBF[c2];
        float f3 = Dsm[(c2 + 1) * 68 + t] + sBF[c2 + 1];
        float g0 = Dsm[(c1 + 64) * 68 + t] + sBG[c1];
        float g1 = Dsm[(c1 + 65) * 68 + t] + sBG[c1 + 1];
        float g2 = Dsm[(c2 + 64) * 68 + t] + sBG[c2];
        float g3 = Dsm[(c2 + 65) * 68 + t] + sBG[c2 + 1];
        float z0 = fast_tanh(f0) * fast_sigmoid(g0);
        float z1 = fast_tanh(f1) * fast_sigmoid(g1);
        float z2 = fast_tanh(f2) * fast_sigmoid(g2);
        float z3 = fast_tanh(f3) * fast_sigmoid(g3);
        u32 h1, l1, h2, l2;
        split2h(z0, z1, h1, l1);
        split2h(z2, z3, h2, l2);
        Zf[t * ZP4 + sl] = make_uint4(h1, h2, l1, l2);
    }
    __syncthreads();

    // ---- GEMM2: main + correction ----
    int mg2 = w & 1, ng2 = w >> 1;
    float acc2[2][2][4], acc2c[2][2][4];
    #pragma unroll
    for (int mi = 0; mi < 2; mi++)
        #pragma unroll
        for (int j = 0; j < 2; j++)
            #pragma unroll
            for (int rr = 0; rr < 4; rr++) { acc2[mi][j][rr] = 0.f; acc2c[mi][j][rr] = 0.f; }

    const uint4* WRp = (const uint4*)(g_WR + (size_t)layer * 2048) + (mg2 * 2) * 128;
    uint4 Ah2R[2][2];
    #pragma unroll
    for (int mi = 0; mi < 2; mi++) Ah2R[0][mi] = WRp[mi * 128 + lane];
    #pragma unroll
    for (int s = 0; s < 4; s++) {
        int cur = s & 1, nxt = cur ^ 1;
        if (s < 3) {
            #pragma unroll
            for (int mi = 0; mi < 2; mi++)
                Ah2R[nxt][mi] = WRp[mi * 128 + (s + 1) * 32 + lane];
        }
        uint4 B0 = Zf[(ng2 * 16 + 0 + tb) * ZP4 + s * 4 + r];
        uint4 B1 = Zf[(ng2 * 16 + 8 + tb) * ZP4 + s * 4 + r];
        #pragma unroll
        for (int mi = 0; mi < 2; mi++) {
            uint4 Ah = Ah2R[cur][mi];
            mma16816h(acc2[mi][0], Ah.x, Ah.y, Ah.z, Ah.w, B0.x, B0.y);
            mma16816h(acc2c[mi][0], Ah.x, Ah.y, Ah.z, Ah.w, B0.z, B0.w);
            mma16816h(acc2[mi][1], Ah.x, Ah.y, Ah.z, Ah.w, B1.x, B1.y);
            mma16816h(acc2c[mi][1], Ah.x, Ah.y, Ah.z, Ah.w, B1.z, B1.w);
        }
    }

    // ---- store skip = acc2 + acc2c/2048 ----
    {
        int gr = lane >> 2, tq = 2 * (lane & 3);
        #pragma unroll
        for (int mi = 0; mi < 2; mi++)
            #pragma unroll
            for (int j = 0; j < 2; j++) {
                int m = mg2 * 32 + mi * 16 + gr;
                int t = ng2 * 16 + j * 8 + tq;
                SK[t * 68 + m]       = fmaf(acc2c[mi][j][0], RSCALE_INV, acc2[mi][j][0]);
                SK[(t + 1) * 68 + m] = fmaf(acc2c[mi][j][1], RSCALE_INV, acc2[mi][j][1]);
                SK[t * 68 + m + 8]       = fmaf(acc2c[mi][j][2], RSCALE_INV, acc2[mi][j][2]);
                SK[(t + 1) * 68 + m + 8] = fmaf(acc2c[mi][j][3], RSCALE_INV, acc2[mi][j][3]);
            }
    }
    __syncthreads();

    // ---- epilogue ----
    const float* brp = b_res + layer * CC;
    float* rout = buf_m(out_sel) + (size_t)b * LL * CC;
    #pragma unroll
    for (int it = 0; it < 4; it++) {
        int id = it * 256 + tid;
        int t = id >> 4, cq = (id & 15) * 4;
        float4 rv = *(const float4*)(rin + (size_t)(tt0 + t) * CC + cq);
        float4 bz = *(const float4*)(brp + cq);
        float4 s4 = *(const float4*)&SK[t * 68 + cq];
        float4 o = make_float4(rv.x + s4.x + bz.x, rv.y + s4.y + bz.y,
                               rv.z + s4.z + bz.z, rv.w + s4.w + bz.w);
        *(float4*)(rout + (size_t)(tt0 + t) * CC + cq) = o;
    }
}

// ---------------- K5: head (fp16 2-MMA split) -----------------------------------
__global__ void __launch_bounds__(256, 2) k_final_tc(
    const float* __restrict__ b1, const float* __restrict__ b2,
    float* __restrict__ out)
{
    extern __shared__ u32 smem_u[];
    u32* XH = smem_u;                 // 64 x 36 u32
    u32* XL = smem_u + 2304;
    float* Dsm = (float*)smem_u;      // overlay: 128 x 68 f32
    u32* HH = smem_u + 8704;          // 64 x 68 u32
    u32* HL = smem_u + 13056;

    int tid = threadIdx.x;
    int lane = tid & 31;
    int w = tid >> 5;
    int b = blockIdx.y;
    int tt0 = blockIdx.x * 64;
    int tb = lane >> 2;

    const float* rA = g_resA + (size_t)b * LL * CC;
    const float* r0 = g_res0 + (size_t)b * LL * CC;
    #pragma unroll
    for (int it = 0; it < 4; it++) {
        int id = it * 256 + tid;
        int t = id >> 4, cq = (id & 15) * 4;
        size_t off = (size_t)(tt0 + t) * CC + cq;
        float4 a = *(const float4*)(rA + off);
        float4 z = *(const float4*)(r0 + off);
        float s0 = fmaxf(a.x - z.x, 0.f), s1 = fmaxf(a.y - z.y, 0.f);
        float s2 = fmaxf(a.z - z.z, 0.f), s3 = fmaxf(a.w - z.w, 0.f);
        u32 h0, l0, h1, l1;
        split2h(s0, s1, h0, l0);
        split2h(s2, s3, h1, l1);
        int o = t * 36 + (cq >> 1);
        *(uint2*)&XH[o] = make_uint2(h0, h1);
        *(uint2*)&XL[o] = make_uint2(l0, l1);
    }
    __syncthreads();

    float acc[8][4], accc[8][4];
    #pragma unroll
    for (int j = 0; j < 8; j++)
        #pragma unroll
        for (int rr = 0; rr < 4; rr++) { acc[j][rr] = 0.f; accc[j][rr] = 0.f; }

    const uint4* W1p = (const uint4*)(g_W1 + w * 512);
    #pragma unroll
    for (int s = 0; s < 4; s++) {
        uint4 Ah = W1p[s * 32 + lane];
        int kb = s * 8 + (lane & 3);
        #pragma unroll
        for (int j = 0; j < 8; j++) {
            int base = (j * 8 + tb) * 36 + kb;
            u32 bh0 = XH[base], bh1 = XH[base + 4];
            u32 bl0 = XL[base], bl1 = XL[base + 4];
            mma16816h(acc[j], Ah.x, Ah.y, Ah.z, Ah.w, bh0, bh1);
            mma16816h(accc[j], Ah.x, Ah.y, Ah.z, Ah.w, bl0, bl1);
        }
    }
    __syncthreads();

    {
        int g = lane >> 2, tq = 2 * (lane & 3);
        int m = w * 16 + g;
        #pragma unroll
        for (int j = 0; j < 8; j++) {
            int t = j * 8 + tq;
            float d0 = fmaf(accc[j][0], RSCALE_INV, acc[j][0]);
            float d1 = fmaf(accc[j][1], RSCALE_INV, acc[j][1]);
            float d2 = fmaf(accc[j][2], RSCALE_INV, acc[j][2]);
            float d3 = fmaf(accc[j][3], RSCALE_INV, acc[j][3]);
            *(float2*)&Dsm[m * 68 + t] = make_float2(d0, d1);
            *(float2*)&Dsm[(m + 8) * 68 + t] = make_float2(d2, d3);
        }
    }
    __syncthreads();

    #pragma unroll
    for (int it = 0; it < 16; it++) {
        int id = it * 256 + tid;
        int mp = id & 63, t = id >> 6;
        float h0 = fmaxf(Dsm[(2 * mp) * 68 + t] + b1[2 * mp], 0.f);
        float h1 = fmaxf(Dsm[(2 * mp + 1) * 68 + t] + b1[2 * mp + 1], 0.f);
        u32 hh, hl; split2h(h0, h1, hh, hl);
        HH[t * 68 + mp] = hh;
        HL[t * 68 + mp] = hl;
    }
    __syncthreads();

    int mt = w & 1;
    float acc2[2][4], acc2c[2][4];
    #pragma unroll
    for (int j = 0; j < 2; j++)
        #pragma unroll
        for (int rr = 0; rr < 4; rr++) { acc2[j][rr] = 0.f; acc2c[j][rr] = 0.f; }

    const uint4* W2p = (const uint4*)(g_W2 + mt * 1024);
    #pragma unroll
    for (int s = 0; s < 8; s++) {
        uint4 Ah = W2p[s * 32 + lane];
        int kb = s * 8 + (lane & 3);
        #pragma unroll
        for (int j = 0; j < 2; j++) {
            int nblk = (w >> 1) * 2 + j;
            int base = (nblk * 8 + tb) * 68 + kb;
            u32 bh0 = HH[base], bh1 = HH[base + 4];
            u32 bl0 = HL[base], bl1 = HL[base + 4];
            mma16816h(acc2[j], Ah.x, Ah.y, Ah.z, Ah.w, bh0, bh1);
            mma16816h(acc2c[j], Ah.x, Ah.y, Ah.z, Ah.w, bl0, bl1);
        }
    }

    {
        int m = mt * 16 + (lane >> 2);
        #pragma unroll
        for (int j = 0; j < 2; j++) {
            int nblk = (w >> 1) * 2 + j;
            int t = tt0 + nblk * 8 + 2 * (lane & 3);
            int o1 = m, o2 = m + 8;
            float v0 = fmaf(acc2c[j][0], RSCALE_INV, acc2[j][0]) + b2[o1];
            float v1 = fmaf(acc2c[j][1], RSCALE_INV, acc2[j][1]) + b2[o1];
            *(float2*)(out + ((size_t)b * OO + o1) * LL + t) = make_float2(v0, v1);
            if (o2 < OO) {
                float v2 = fmaf(acc2c[j][2], RSCALE_INV, acc2[j][2]) + b2[o2];
                float v3 = fmaf(acc2c[j][3], RSCALE_INV, acc2[j][3]) + b2[o2];
                *(float2*)(out + ((size_t)b * OO + o2) * LL + t) = make_float2(v2, v3);
            }
        }
    }
}

// ---------------- launch --------------------------------------------------------
extern "C" void kernel_launch(void* const* d_in, const int* in_sizes, int n_in,
                              void* d_out, int out_size)
{
    const int*   in_tok = (const int*)d_in[0];
    const int*   g_tok  = (const int*)d_in[1];
    const float* emb    = (const float*)d_in[2];
    const float* wc     = (const float*)d_in[3];
    const float* bc     = (const float*)d_in[4];
    const float* wf     = (const float*)d_in[5];
    const float* bf     = (const float*)d_in[6];
    const float* wg     = (const float*)d_in[7];
    const float* bg     = (const float*)d_in[8];
    const float* wlf    = (const float*)d_in[9];
    const float* blf    = (const float*)d_in[10];
    const float* wlg    = (const float*)d_in[11];
    const float* blg    = (const float*)d_in[12];
    const float* wres   = (const float*)d_in[13];
    const float* bres   = (const float*)d_in[14];
    const float* w1     = (const float*)d_in[15];
    const float* b1     = (const float*)d_in[16];
    const float* w2     = (const float*)d_in[17];
    const float* b2     = (const float*)d_in[18];
    float* out = (float*)d_out;

    const int LAYER_SMEM = 27520 * 4;   // 110080 B (2 blocks/SM)
    const int FINAL_SMEM = 17408 * 4;   // 69632 B
    cudaFuncSetAttribute(k_layer_tc, cudaFuncAttributeMaxDynamicSharedMemorySize, LAYER_SMEM);
    cudaFuncSetAttribute(k_final_tc, cudaFuncAttributeMaxDynamicSharedMemorySize, FINAL_SMEM);

    k_precompute_M<<<VV, 64>>>(emb, wc);
    k_prep_w<<<NDND, 256>>>(wf, wg, wres);
    k_prep_head<<<1, 256>>>(w1, w2);
    k_embg<<<BB, 256>>>(g_tok, emb);
    k_H<<<dim3(NDND, 16), 256>>>(wlf, blf, wlg, blg);
    k_init<<<dim3(LL / 64, BB), 256>>>(in_tok, bc);
    for (int i = 0; i < NDND; i++) {
        int d = 2 << i;
        int out_sel = (i % 2 == 0) ? 1 : 2;           // layer 8 -> resA
        int in_sel  = (i == 0) ? 0 : ((i % 2 == 0) ? 2 : 1);
        k_layer_tc<<<dim3(LL / 64, BB), 256, LAYER_SMEM>>>(
            bf, bg, bres, i, d, in_sel, out_sel);
    }
    k_final_tc<<<dim3(LL / 64, BB), 256, FINAL_SMEM>>>(b1, b2, out);
}

// round 10
// speedup vs baseline: 6.5282x; 1.2307x over previous
#include <cuda_runtime.h>
#include <cuda_fp16.h>
#include <math.h>

#define BB   64
#define LL   2048
#define VV   30
#define EE   128
#define GG   8
#define GEGE 1024
#define CC   64
#define FF   128
#define OO   30
#define NDND 9

#define XP4  36
#define ZP4  20
#define RSCALE 2048.0f
#define RSCALE_INV 4.8828125e-4f

typedef unsigned int u32;

// ---------------- helpers ----------------------------------------------------
__device__ __forceinline__ void mma16816h(float* d, u32 a0, u32 a1, u32 a2, u32 a3,
                                          u32 b0, u32 b1) {
    asm volatile(
        "mma.sync.aligned.m16n8k16.row.col.f32.f16.f16.f32 "
        "{%0,%1,%2,%3}, {%4,%5,%6,%7}, {%8,%9}, {%0,%1,%2,%3};"
        : "+f"(d[0]), "+f"(d[1]), "+f"(d[2]), "+f"(d[3])
        : "r"(a0), "r"(a1), "r"(a2), "r"(a3), "r"(b0), "r"(b1));
}
__device__ __forceinline__ void split2h(float x0, float x1, u32& hi, u32& lo) {
    __half h0 = __float2half_rn(x0);
    __half h1 = __float2half_rn(x1);
    float r0 = (x0 - __half2float(h0)) * RSCALE;
    float r1 = (x1 - __half2float(h1)) * RSCALE;
    __half2 hv = __halves2half2(h0, h1);
    __half2 lv = __halves2half2(__float2half_rn(r0), __float2half_rn(r1));
    hi = *(u32*)&hv; lo = *(u32*)&lv;
}
__device__ __forceinline__ u32 pack2h(float x0, float x1) {
    __half2 hv = __halves2half2(__float2half_rn(x0), __float2half_rn(x1));
    return *(u32*)&hv;
}
__device__ __forceinline__ float2 recon2(u32 h, u32 l) {
    float2 a = __half22float2(*(__half2*)&h);
    float2 b = __half22float2(*(__half2*)&l);
    return make_float2(fmaf(b.x, RSCALE_INV, a.x), fmaf(b.y, RSCALE_INV, a.y));
}
__device__ __forceinline__ float fast_tanh(float x) {
    float e; asm("ex2.approx.f32 %0, %1;" : "=f"(e) : "f"(x * 2.8853900817779268f));
    float r; asm("rcp.approx.f32 %0, %1;" : "=f"(r) : "f"(e + 1.0f));
    return 1.0f - 2.0f * r;
}
__device__ __forceinline__ float fast_sigmoid(float x) {
    float e; asm("ex2.approx.f32 %0, %1;" : "=f"(e) : "f"(-x * 1.4426950408889634f));
    float r; asm("rcp.approx.f32 %0, %1;" : "=f"(r) : "f"(e + 1.0f));
    return r;
}

// ---------------- scratch -----------------------------------------------------
// residual in split-fp16 slot format: [sel][b][t][16 slots], slot s holds
// channel pairs (qc, qc+4) with qc = (s>>2)*8 + (s&3); H = fp16 hi, L = fp16 res*2048
__device__ uint2 g_rH[(size_t)3 * BB * LL * 16];
__device__ uint2 g_rL[(size_t)3 * BB * LL * 16];
__device__ float g_embg[BB * GEGE];
__device__ float g_HF[NDND * BB * CC];
__device__ float g_HG[NDND * BB * CC];
__device__ float g_M0[VV * CC];
__device__ float g_M1[VV * CC];
__device__ u32 g_WF[NDND * 8192];
__device__ u32 g_WR[NDND * 2048];
__device__ u32 g_W1[4096];
__device__ u32 g_W2[2048];

__device__ __forceinline__ uint2* rowsH(int sel, int b) {
    return g_rH + ((size_t)sel * BB + b) * LL * 16;
}
__device__ __forceinline__ uint2* rowsL(int sel, int b) {
    return g_rL + ((size_t)sel * BB + b) * LL * 16;
}

// ---------------- K0a: fold embedding + initial conv ---------------------------
__global__ void __launch_bounds__(64) k_precompute_M(
    const float* __restrict__ emb, const float* __restrict__ wc)
{
    int v = blockIdx.x, c = threadIdx.x;
    float a0 = 0.f, a1 = 0.f;
    if (v != 0) {
        for (int e = 0; e < EE; e++) {
            float x = emb[v * EE + e];
            a0 = fmaf(x, wc[(c * EE + e) * 2 + 0], a0);
            a1 = fmaf(x, wc[(c * EE + e) * 2 + 1], a1);
        }
    }
    g_M0[v * CC + c] = a0;
    g_M1[v * CC + c] = a1;
}

// ---------------- K0b: layer weights -> fp16 fragment layout --------------------
__global__ void __launch_bounds__(256) k_prep_w(
    const float* __restrict__ wf, const float* __restrict__ wg,
    const float* __restrict__ wres)
{
    int layer = blockIdx.x;
    for (int idx = threadIdx.x; idx < 8192; idx += 256) {
        int w = idx >> 10, s = (idx >> 7) & 7;
        int lane = (idx >> 2) & 31, r = idx & 3;
        int m = w * 16 + (r & 1) * 8 + (lane >> 2);
        int k0 = s * 16 + ((r >> 1) & 1) * 8 + (lane & 3) * 2;
        const float* src = (m < 64) ? wf : wg;
        int cout = m & 63;
        int cin0 = k0 & 63, tap0 = k0 >> 6;
        int k1 = k0 + 1;
        int cin1 = k1 & 63, tap1 = k1 >> 6;
        float x0 = src[(((size_t)layer * 64 + cout) * 64 + cin0) * 2 + tap0];
        float x1 = src[(((size_t)layer * 64 + cout) * 64 + cin1) * 2 + tap1];
        g_WF[(size_t)layer * 8192 + idx] = pack2h(x0, x1);
    }
    for (int idx = threadIdx.x; idx < 2048; idx += 256) {
        int mt = idx >> 9, s = (idx >> 7) & 3;
        int lane = (idx >> 2) & 31, r = idx & 3;
        int m = mt * 16 + (r & 1) * 8 + (lane >> 2);
        int k0 = s * 16 + ((r >> 1) & 1) * 8 + (lane & 3) * 2;
        float x0 = wres[((size_t)layer * 64 + m) * 64 + k0];
        float x1 = wres[((size_t)layer * 64 + m) * 64 + k0 + 1];
        g_WR[(size_t)layer * 2048 + idx] = pack2h(x0, x1);
    }
}

// ---------------- K0c: head weights -> fp16 fragment layout ---------------------
__global__ void __launch_bounds__(256) k_prep_head(
    const float* __restrict__ w1, const float* __restrict__ w2)
{
    for (int idx = threadIdx.x; idx < 4096; idx += 256) {
        int w = idx >> 9, s = (idx >> 7) & 3;
        int lane = (idx >> 2) & 31, r = idx & 3;
        int m = w * 16 + (r & 1) * 8 + (lane >> 2);
        int k0 = s * 16 + ((r >> 1) & 1) * 8 + (lane & 3) * 2;
        g_W1[idx] = pack2h(w1[m * 64 + k0], w1[m * 64 + k0 + 1]);
    }
    for (int idx = threadIdx.x; idx < 2048; idx += 256) {
        int mt = idx >> 10, s = (idx >> 7) & 7;
        int lane = (idx >> 2) & 31, r = idx & 3;
        int m = mt * 16 + (r & 1) * 8 + (lane >> 2);
        int k0 = s * 16 + ((r >> 1) & 1) * 8 + (lane & 3) * 2;
        float x0 = (m < OO) ? w2[m * 128 + k0] : 0.f;
        float x1 = (m < OO) ? w2[m * 128 + k0 + 1] : 0.f;
        g_W2[idx] = pack2h(x0, x1);
    }
}

// ---------------- K1: global embedding ------------------------------------------
__global__ void __launch_bounds__(256) k_embg(
    const int* __restrict__ gin, const float* __restrict__ emb)
{
    int b = blockIdx.x;
    for (int j = threadIdx.x; j < GEGE; j += 256) {
        int g = j >> 7, e = j & 127;
        int tok = gin[b * GG + g];
        g_embg[b * GEGE + j] = (tok == 0) ? 0.f : emb[tok * EE + e];
    }
}

// ---------------- K2: conditioning vectors ---------------------------------------
__global__ void __launch_bounds__(256) k_H(
    const float* __restrict__ wlf, const float* __restrict__ blf,
    const float* __restrict__ wlg, const float* __restrict__ blg)
{
    __shared__ float sE[GEGE * 4];
    __shared__ float sR[256 * 4];
    int i = blockIdx.x;
    int b0 = blockIdx.y * 4;
    int tid = threadIdx.x;

    for (int idx = tid; idx < GEGE * 4; idx += 256) {
        int k = idx >> 2, bj = idx & 3;
        sE[idx] = g_embg[(size_t)(b0 + bj) * GEGE + k];
    }
    __syncthreads();

    int row = tid & 127;
    int half = tid >> 7;
    int c = row & 63;
    bool isf = row < 64;
    const float* w = (isf ? wlf : wlg) + ((size_t)i * CC + c) * GEGE + half * 512;
    const float* ep = sE + half * 512 * 4;

    float a0 = 0.f, a1 = 0.f, a2 = 0.f, a3 = 0.f;
    #pragma unroll 4
    for (int k = 0; k < 512; k += 4) {
        float4 wv = *(const float4*)(w + k);
        float4 e0 = *(const float4*)(ep + k * 4);
        float4 e1 = *(const float4*)(ep + k * 4 + 4);
        float4 e2 = *(const float4*)(ep + k * 4 + 8);
        float4 e3 = *(const float4*)(ep + k * 4 + 12);
        a0 = fmaf(wv.x, e0.x, a0); a1 = fmaf(wv.x, e0.y, a1);
        a2 = fmaf(wv.x, e0.z, a2); a3 = fmaf(wv.x, e0.w, a3);
        a0 = fmaf(wv.y, e1.x, a0); a1 = fmaf(wv.y, e1.y, a1);
        a2 = fmaf(wv.y, e1.z, a2); a3 = fmaf(wv.y, e1.w, a3);
        a0 = fmaf(wv.z, e2.x, a0); a1 = fmaf(wv.z, e2.y, a1);
        a2 = fmaf(wv.z, e2.z, a2); a3 = fmaf(wv.z, e2.w, a3);
        a0 = fmaf(wv.w, e3.x, a0); a1 = fmaf(wv.w, e3.y, a1);
        a2 = fmaf(wv.w, e3.z, a2); a3 = fmaf(wv.w, e3.w, a3);
    }
    *(float4*)&sR[tid * 4] = make_float4(a0, a1, a2, a3);
    __syncthreads();
    if (tid < 128) {
        float4 lo = *(const float4*)&sR[tid * 4];
        float4 hi = *(const float4*)&sR[(tid + 128) * 4];
        float bias = (isf ? blf : blg)[i * CC + c];
        float* dst = (isf ? g_HF : g_HG);
        dst[((size_t)i * BB + b0 + 0) * CC + c] = lo.x + hi.x + bias;
        dst[((size_t)i * BB + b0 + 1) * CC + c] = lo.y + hi.y + bias;
        dst[((size_t)i * BB + b0 + 2) * CC + c] = lo.z + hi.z + bias;
        dst[((size_t)i * BB + b0 + 3) * CC + c] = lo.w + hi.w + bias;
    }
}

// ---------------- K3: initial residual -> split slot format ----------------------
__global__ void __launch_bounds__(256) k_init(
    const int* __restrict__ tok, const float* __restrict__ b_causal)
{
    __shared__ float sM0[VV * CC], sM1[VV * CC], sb[CC];
    int tid = threadIdx.x;
    for (int i = tid; i < VV * CC; i += 256) { sM0[i] = g_M0[i]; sM1[i] = g_M1[i]; }
    if (tid < CC) sb[tid] = b_causal[tid];
    __syncthreads();
    int b = blockIdx.y, tt0 = blockIdx.x * 64;
    const int* tb = tok + b * LL;
    uint2* oH = rowsH(0, b);
    uint2* oL = rowsL(0, b);
    for (int idx = tid; idx < 1024; idx += 256) {
        int tl = idx >> 4, s = idx & 15;
        int qc = ((s >> 2) << 3) + (s & 3);
        int c0 = 2 * qc;
        int t = tt0 + tl;
        int v1 = tb[t] * CC;
        float r[4];
        r[0] = sM1[v1 + c0] + sb[c0];
        r[1] = sM1[v1 + c0 + 1] + sb[c0 + 1];
        r[2] = sM1[v1 + c0 + 8] + sb[c0 + 8];
        r[3] = sM1[v1 + c0 + 9] + sb[c0 + 9];
        if (t > 0) {
            int v0 = tb[t - 1] * CC;
            r[0] += sM0[v0 + c0];
            r[1] += sM0[v0 + c0 + 1];
            r[2] += sM0[v0 + c0 + 8];
            r[3] += sM0[v0 + c0 + 9];
        }
        u32 h1, l1, h2, l2;
        split2h(r[0], r[1], h1, l1);
        split2h(r[2], r[3], h2, l2);
        oH[t * 16 + s] = make_uint2(h1, h2);
        oL[t * 16 + s] = make_uint2(l1, l2);
    }
}

// ---------------- K4: dilated residual layer (split-format residual) -------------
__global__ void __launch_bounds__(256, 2) k_layer_tc(
    const float* __restrict__ b_f, const float* __restrict__ b_g,
    const float* __restrict__ b_res,
    int layer, int d, int in_sel, int out_sel)
{
    extern __shared__ u32 smem_u[];
    uint4* Xf  = (uint4*)smem_u;                   // 2304 uint4 = 9216 u32
    float* Dsm = (float*)(smem_u + 9216);          // 128 x 68 = 8704 u32
    uint4* Zf  = (uint4*)(smem_u + 17920);         // 1280 uint4 = 5120 u32
    float* SK  = (float*)(smem_u + 23040);         // 64 x 68 = 4352 u32
    float* sBF = (float*)(smem_u + 27392);         // 64
    float* sBG = sBF + 64;                         // 64
    float* sBR = sBG + 64;                         // 64

    int tid = threadIdx.x;
    int lane = tid & 31;
    int w = tid >> 5;
    int b = blockIdx.y;
    int tt0 = blockIdx.x * 64;
    int r = lane & 3, tb = lane >> 2;

    if (tid < 64)
        sBF[tid] = b_f[layer * CC + tid] + g_HF[((size_t)layer * BB + b) * CC + tid];
    else if (tid < 128) {
        int c = tid - 64;
        sBG[c] = b_g[layer * CC + c] + g_HG[((size_t)layer * BB + b) * CC + c];
    } else if (tid < 192) {
        int c = tid - 128;
        sBR[c] = b_res[layer * CC + c];
    }

    // ---- X fragments: straight gather from split-format residual ----
    const uint2* iH = rowsH(in_sel, b);
    const uint2* iL = rowsL(in_sel, b);
    #pragma unroll
    for (int it = 0; it < 8; it++) {
        int id = it * 256 + tid;          // 2048 slots
        int t = id >> 5;
        int sl = id & 31;
        int s = sl & 15;
        int gt = (sl < 16) ? (tt0 + t - d) : (tt0 + t);
        uint2 H = make_uint2(0u, 0u), L = make_uint2(0u, 0u);
        if (gt >= 0) { H = iH[gt * 16 + s]; L = iL[gt * 16 + s]; }
        Xf[t * XP4 + sl] = make_uint4(H.x, H.y, L.x, L.y);
    }
    __syncthreads();

    // ---- GEMM1: main + scaled-correction accumulators ----
    int mg = w & 3, ng = w >> 2;
    float acc[2][4][4], accc[2][4][4];
    #pragma unroll
    for (int mi = 0; mi < 2; mi++)
        #pragma unroll
        for (int j = 0; j < 4; j++)
            #pragma unroll
            for (int rr = 0; rr < 4; rr++) { acc[mi][j][rr] = 0.f; accc[mi][j][rr] = 0.f; }

    const uint4* WFp = (const uint4*)(g_WF + (size_t)layer * 8192) + (mg * 2) * 256;
    uint4 AhR[2][2];
    #pragma unroll
    for (int mi = 0; mi < 2; mi++) AhR[0][mi] = WFp[mi * 256 + lane];
    #pragma unroll
    for (int s = 0; s < 8; s++) {
        int cur = s & 1, nxt = cur ^ 1;
        if (s < 7) {
            #pragma unroll
            for (int mi = 0; mi < 2; mi++)
                AhR[nxt][mi] = WFp[mi * 256 + (s + 1) * 32 + lane];
        }
        uint4 B0 = Xf[(ng * 32 + 0 + tb) * XP4 + s * 4 + r];
        uint4 B1 = Xf[(ng * 32 + 8 + tb) * XP4 + s * 4 + r];
        uint4 B2 = Xf[(ng * 32 + 16 + tb) * XP4 + s * 4 + r];
        uint4 B3 = Xf[(ng * 32 + 24 + tb) * XP4 + s * 4 + r];
        #pragma unroll
        for (int mi = 0; mi < 2; mi++) {
            uint4 Ah = AhR[cur][mi];
            mma16816h(acc[mi][0], Ah.x, Ah.y, Ah.z, Ah.w, B0.x, B0.y);
            mma16816h(accc[mi][0], Ah.x, Ah.y, Ah.z, Ah.w, B0.z, B0.w);
            mma16816h(acc[mi][1], Ah.x, Ah.y, Ah.z, Ah.w, B1.x, B1.y);
            mma16816h(accc[mi][1], Ah.x, Ah.y, Ah.z, Ah.w, B1.z, B1.w);
            mma16816h(acc[mi][2], Ah.x, Ah.y, Ah.z, Ah.w, B2.x, B2.y);
            mma16816h(accc[mi][2], Ah.x, Ah.y, Ah.z, Ah.w, B2.z, B2.w);
            mma16816h(acc[mi][3], Ah.x, Ah.y, Ah.z, Ah.w, B3.x, B3.y);
            mma16816h(accc[mi][3], Ah.x, Ah.y, Ah.z, Ah.w, B3.z, B3.w);
        }
    }

    // ---- store D = acc + accc/2048 ----
    {
        int gr = lane >> 2, tq = 2 * (lane & 3);
        #pragma unroll
        for (int mi = 0; mi < 2; mi++)
            #pragma unroll
            for (int j = 0; j < 4; j++) {
                int m = mg * 32 + mi * 16 + gr;
                int t = ng * 32 + j * 8 + tq;
                float d0 = fmaf(accc[mi][j][0], RSCALE_INV, acc[mi][j][0]);
                float d1 = fmaf(accc[mi][j][1], RSCALE_INV, acc[mi][j][1]);
                float d2 = fmaf(accc[mi][j][2], RSCALE_INV, acc[mi][j][2]);
                float d3 = fmaf(accc[mi][j][3], RSCALE_INV, acc[mi][j][3]);
                *(float2*)&Dsm[m * 68 + t] = make_float2(d0, d1);
                *(float2*)&Dsm[(m + 8) * 68 + t] = make_float2(d2, d3);
            }
    }
    __syncthreads();

    // ---- gated activation -> Z fragments ----
    #pragma unroll
    for (int it = 0; it < 4; it++) {
        int id = it * 256 + tid;
        int t = id >> 4;
        int sl = id & 15;
        int q = (sl >> 2) * 8 + (sl & 3);
        int c1 = 2 * q, c2 = 2 * q + 8;
        float f0 = Dsm[c1 * 68 + t] + sBF[c1];
        float f1 = Dsm[(c1 + 1) * 68 + t] + sBF[c1 + 1];
        float f2 = Dsm[c2 * 68 + t] + sBF[c2];
        float f3 = Dsm[(c2 + 1) * 68 + t] + sBF[c2 + 1];
        float g0 = Dsm[(c1 + 64) * 68 + t] + sBG[c1];
        float g1 = Dsm[(c1 + 65) * 68 + t] + sBG[c1 + 1];
        float g2 = Dsm[(c2 + 64) * 68 + t] + sBG[c2];
        float g3 = Dsm[(c2 + 65) * 68 + t] + sBG[c2 + 1];
        float z0 = fast_tanh(f0) * fast_sigmoid(g0);
        float z1 = fast_tanh(f1) * fast_sigmoid(g1);
        float z2 = fast_tanh(f2) * fast_sigmoid(g2);
        float z3 = fast_tanh(f3) * fast_sigmoid(g3);
        u32 h1, l1, h2, l2;
        split2h(z0, z1, h1, l1);
        split2h(z2, z3, h2, l2);
        Zf[t * ZP4 + sl] = make_uint4(h1, h2, l1, l2);
    }
    __syncthreads();

    // ---- GEMM2: main + correction ----
    int mg2 = w & 1, ng2 = w >> 1;
    float acc2[2][2][4], acc2c[2][2][4];
    #pragma unroll
    for (int mi = 0; mi < 2; mi++)
        #pragma unroll
        for (int j = 0; j < 2; j++)
            #pragma unroll
            for (int rr = 0; rr < 4; rr++) { acc2[mi][j][rr] = 0.f; acc2c[mi][j][rr] = 0.f; }

    const uint4* WRp = (const uint4*)(g_WR + (size_t)layer * 2048) + (mg2 * 2) * 128;
    uint4 Ah2R[2][2];
    #pragma unroll
    for (int mi = 0; mi < 2; mi++) Ah2R[0][mi] = WRp[mi * 128 + lane];
    #pragma unroll
    for (int s = 0; s < 4; s++) {
        int cur = s & 1, nxt = cur ^ 1;
        if (s < 3) {
            #pragma unroll
            for (int mi = 0; mi < 2; mi++)
                Ah2R[nxt][mi] = WRp[mi * 128 + (s + 1) * 32 + lane];
        }
        uint4 B0 = Zf[(ng2 * 16 + 0 + tb) * ZP4 + s * 4 + r];
        uint4 B1 = Zf[(ng2 * 16 + 8 + tb) * ZP4 + s * 4 + r];
        #pragma unroll
        for (int mi = 0; mi < 2; mi++) {
            uint4 Ah = Ah2R[cur][mi];
            mma16816h(acc2[mi][0], Ah.x, Ah.y, Ah.z, Ah.w, B0.x, B0.y);
            mma16816h(acc2c[mi][0], Ah.x, Ah.y, Ah.z, Ah.w, B0.z, B0.w);
            mma16816h(acc2[mi][1], Ah.x, Ah.y, Ah.z, Ah.w, B1.x, B1.y);
            mma16816h(acc2c[mi][1], Ah.x, Ah.y, Ah.z, Ah.w, B1.z, B1.w);
        }
    }

    // ---- store skip = acc2 + acc2c/2048 ----
    {
        int gr = lane >> 2, tq = 2 * (lane & 3);
        #pragma unroll
        for (int mi = 0; mi < 2; mi++)
            #pragma unroll
            for (int j = 0; j < 2; j++) {
                int m = mg2 * 32 + mi * 16 + gr;
                int t = ng2 * 16 + j * 8 + tq;
                SK[t * 68 + m]       = fmaf(acc2c[mi][j][0], RSCALE_INV, acc2[mi][j][0]);
                SK[(t + 1) * 68 + m] = fmaf(acc2c[mi][j][1], RSCALE_INV, acc2[mi][j][1]);
                SK[t * 68 + m + 8]       = fmaf(acc2c[mi][j][2], RSCALE_INV, acc2[mi][j][2]);
                SK[(t + 1) * 68 + m + 8] = fmaf(acc2c[mi][j][3], RSCALE_INV, acc2[mi][j][3]);
            }
    }
    __syncthreads();

    // ---- epilogue: res_out = res_in(from Xf) + skip + b_res, re-split ----
    uint2* oH = rowsH(out_sel, b);
    uint2* oL = rowsL(out_sel, b);
    #pragma unroll
    for (int it = 0; it < 4; it++) {
        int id = it * 256 + tid;          // 1024 = 64t x 16 slots
        int t = id >> 4, s = id & 15;
        int qc = ((s >> 2) << 3) + (s & 3);
        int c0 = 2 * qc;
        uint4 v = Xf[t * XP4 + 16 + s];   // cur-row slot
        float2 ra = recon2(v.x, v.z);     // channels c0, c0+1
        float2 rb = recon2(v.y, v.w);     // channels c0+8, c0+9
        float2 sk1 = *(const float2*)&SK[t * 68 + c0];
        float2 sk2 = *(const float2*)&SK[t * 68 + c0 + 8];
        float o0 = ra.x + sk1.x + sBR[c0];
        float o1 = ra.y + sk1.y + sBR[c0 + 1];
        float o2 = rb.x + sk2.x + sBR[c0 + 8];
        float o3 = rb.y + sk2.y + sBR[c0 + 9];
        u32 h1, l1, h2, l2;
        split2h(o0, o1, h1, l1);
        split2h(o2, o3, h2, l2);
        int gt = tt0 + t;
        oH[gt * 16 + s] = make_uint2(h1, h2);
        oL[gt * 16 + s] = make_uint2(l1, l2);
    }
}

// ---------------- K5: head (fp16 2-MMA split, split-format input) ---------------
__global__ void __launch_bounds__(256, 2) k_final_tc(
    const float* __restrict__ b1, const float* __restrict__ b2,
    float* __restrict__ out)
{
    extern __shared__ u32 smem_u[];
    u32* XH = smem_u;                 // 64 x 36 u32
    u32* XL = smem_u + 2304;
    float* Dsm = (float*)smem_u;      // overlay: 128 x 68 f32
    u32* HH = smem_u + 8704;          // 64 x 68 u32
    u32* HL = smem_u + 13056;

    int tid = threadIdx.x;
    int lane = tid & 31;
    int w = tid >> 5;
    int b = blockIdx.y;
    int tt0 = blockIdx.x * 64;
    int tb = lane >> 2;

    // ---- S = relu(resA - res0), both in split slot format ----
    const uint2* aH = rowsH(1, b);
    const uint2* aL = rowsL(1, b);
    const uint2* zH = rowsH(0, b);
    const uint2* zL = rowsL(0, b);
    #pragma unroll
    for (int it = 0; it < 4; it++) {
        int id = it * 256 + tid;          // 1024 = 64t x 16 slots
        int t = id >> 4, s = id & 15;
        int gt = tt0 + t;
        uint2 AH = aH[gt * 16 + s], AL = aL[gt * 16 + s];
        uint2 ZH0 = zH[gt * 16 + s], ZL0 = zL[gt * 16 + s];
        float2 a1 = recon2(AH.x, AL.x), a2 = recon2(AH.y, AL.y);
        float2 z1 = recon2(ZH0.x, ZL0.x), z2 = recon2(ZH0.y, ZL0.y);
        float s0 = fmaxf(a1.x - z1.x, 0.f), s1 = fmaxf(a1.y - z1.y, 0.f);
        float s2 = fmaxf(a2.x - z2.x, 0.f), s3 = fmaxf(a2.y - z2.y, 0.f);
        u32 h1, l1, h2, l2;
        split2h(s0, s1, h1, l1);
        split2h(s2, s3, h2, l2);
        int q = ((s >> 2) << 3) + (s & 3);
        int o = t * 36 + q;
        XH[o] = h1; XH[o + 4] = h2;
        XL[o] = l1; XL[o + 4] = l2;
    }
    __syncthreads();

    float acc[8][4], accc[8][4];
    #pragma unroll
    for (int j = 0; j < 8; j++)
        #pragma unroll
        for (int rr = 0; rr < 4; rr++) { acc[j][rr] = 0.f; accc[j][rr] = 0.f; }

    const uint4* W1p = (const uint4*)(g_W1 + w * 512);
    #pragma unroll
    for (int s = 0; s < 4; s++) {
        uint4 Ah = W1p[s * 32 + lane];
        int kb = s * 8 + (lane & 3);
        #pragma unroll
        for (int j = 0; j < 8; j++) {
            int base = (j * 8 + tb) * 36 + kb;
            u32 bh0 = XH[base], bh1 = XH[base + 4];
            u32 bl0 = XL[base], bl1 = XL[base + 4];
            mma16816h(acc[j], Ah.x, Ah.y, Ah.z, Ah.w, bh0, bh1);
            mma16816h(accc[j], Ah.x, Ah.y, Ah.z, Ah.w, bl0, bl1);
        }
    }
    __syncthreads();

    {
        int g = lane >> 2, tq = 2 * (lane & 3);
        int m = w * 16 + g;
        #pragma unroll
        for (int j = 0; j < 8; j++) {
            int t = j * 8 + tq;
            float d0 = fmaf(accc[j][0], RSCALE_INV, acc[j][0]);
            float d1 = fmaf(accc[j][1], RSCALE_INV, acc[j][1]);
            float d2 = fmaf(accc[j][2], RSCALE_INV, acc[j][2]);
            float d3 = fmaf(accc[j][3], RSCALE_INV, acc[j][3]);
            *(float2*)&Dsm[m * 68 + t] = make_float2(d0, d1);
            *(float2*)&Dsm[(m + 8) * 68 + t] = make_float2(d2, d3);
        }
    }
    __syncthreads();

    #pragma unroll
    for (int it = 0; it < 16; it++) {
        int id = it * 256 + tid;
        int mp = id & 63, t = id >> 6;
        float h0 = fmaxf(Dsm[(2 * mp) * 68 + t] + b1[2 * mp], 0.f);
        float h1 = fmaxf(Dsm[(2 * mp + 1) * 68 + t] + b1[2 * mp + 1], 0.f);
        u32 hh, hl; split2h(h0, h1, hh, hl);
        HH[t * 68 + mp] = hh;
        HL[t * 68 + mp] = hl;
    }
    __syncthreads();

    int mt = w & 1;
    float acc2[2][4], acc2c[2][4];
    #pragma unroll
    for (int j = 0; j < 2; j++)
        #pragma unroll
        for (int rr = 0; rr < 4; rr++) { acc2[j][rr] = 0.f; acc2c[j][rr] = 0.f; }

    const uint4* W2p = (const uint4*)(g_W2 + mt * 1024);
    #pragma unroll
    for (int s = 0; s < 8; s++) {
        uint4 Ah = W2p[s * 32 + lane];
        int kb = s * 8 + (lane & 3);
        #pragma unroll
        for (int j = 0; j < 2; j++) {
            int nblk = (w >> 1) * 2 + j;
            int base = (nblk * 8 + tb) * 68 + kb;
            u32 bh0 = HH[base], bh1 = HH[base + 4];
            u32 bl0 = HL[base], bl1 = HL[base + 4];
            mma16816h(acc2[j], Ah.x, Ah.y, Ah.z, Ah.w, bh0, bh1);
            mma16816h(acc2c[j], Ah.x, Ah.y, Ah.z, Ah.w, bl0, bl1);
        }
    }

    {
        int m = mt * 16 + (lane >> 2);
        #pragma unroll
        for (int j = 0; j < 2; j++) {
            int nblk = (w >> 1) * 2 + j;
            int t = tt0 + nblk * 8 + 2 * (lane & 3);
            int o1 = m, o2 = m + 8;
            float v0 = fmaf(acc2c[j][0], RSCALE_INV, acc2[j][0]) + b2[o1];
            float v1 = fmaf(acc2c[j][1], RSCALE_INV, acc2[j][1]) + b2[o1];
            *(float2*)(out + ((size_t)b * OO + o1) * LL + t) = make_float2(v0, v1);
            if (o2 < OO) {
                float v2 = fmaf(acc2c[j][2], RSCALE_INV, acc2[j][2]) + b2[o2];
                float v3 = fmaf(acc2c[j][3], RSCALE_INV, acc2[j][3]) + b2[o2];
                *(float2*)(out + ((size_t)b * OO + o2) * LL + t) = make_float2(v2, v3);
            }
        }
    }
}

// ---------------- launch ----------------------------------------------------------
extern "C" void kernel_launch(void* const* d_in, const int* in_sizes, int n_in,
                              void* d_out, int out_size)
{
    const int*   in_tok = (const int*)d_in[0];
    const int*   g_tok  = (const int*)d_in[1];
    const float* emb    = (const float*)d_in[2];
    const float* wc     = (const float*)d_in[3];
    const float* bc     = (const float*)d_in[4];
    const float* wf     = (const float*)d_in[5];
    const float* bf     = (const float*)d_in[6];
    const float* wg     = (const float*)d_in[7];
    const float* bg     = (const float*)d_in[8];
    const float* wlf    = (const float*)d_in[9];
    const float* blf    = (const float*)d_in[10];
    const float* wlg    = (const float*)d_in[11];
    const float* blg    = (const float*)d_in[12];
    const float* wres   = (const float*)d_in[13];
    const float* bres   = (const float*)d_in[14];
    const float* w1     = (const float*)d_in[15];
    const float* b1     = (const float*)d_in[16];
    const float* w2     = (const float*)d_in[17];
    const float* b2     = (const float*)d_in[18];
    float* out = (float*)d_out;

    const int LAYER_SMEM = 27584 * 4;   // 110336 B (2 blocks/SM)
    const int FINAL_SMEM = 17408 * 4;   // 69632 B
    cudaFuncSetAttribute(k_layer_tc, cudaFuncAttributeMaxDynamicSharedMemorySize, LAYER_SMEM);
    cudaFuncSetAttribute(k_final_tc, cudaFuncAttributeMaxDynamicSharedMemorySize, FINAL_SMEM);

    k_precompute_M<<<VV, 64>>>(emb, wc);
    k_prep_w<<<NDND, 256>>>(wf, wg, wres);
    k_prep_head<<<1, 256>>>(w1, w2);
    k_embg<<<BB, 256>>>(g_tok, emb);
    k_H<<<dim3(NDND, 16), 256>>>(wlf, blf, wlg, blg);
    k_init<<<dim3(LL / 64, BB), 256>>>(in_tok, bc);
    for (int i = 0; i < NDND; i++) {
        int d = 2 << i;
        int out_sel = (i % 2 == 0) ? 1 : 2;           // layer 8 -> sel 1
        int in_sel  = (i == 0) ? 0 : ((i % 2 == 0) ? 2 : 1);
        k_layer_tc<<<dim3(LL / 64, BB), 256, LAYER_SMEM>>>(
            bf, bg, bres, i, d, in_sel, out_sel);
    }
    k_final_tc<<<dim3(LL / 64, BB), 256, FINAL_SMEM>>>(b1, b2, out);
}